// round 1
// baseline (speedup 1.0000x reference)
#include <cuda_runtime.h>

#define NPIX 65536
#define IMG_H 256
#define IMG_W 256
#define NB 8

// ---- device scratch (allowed: __device__ globals, no cudaMalloc) ----
__device__ float g_cat[NB * 128 * NPIX];   // concat of branch outputs [b][128][N] (268MB)
__device__ float g_mat[2 * NB * 64 * 64];  // matrix = K V^T  [br][b][m][c]
__device__ float g_ksum[2 * NB * 64];
__device__ float g_vsum[2 * NB * 64];
__device__ float g_RMt[2 * NB * 64 * 64];  // RM transposed: [m][o], RM[o][m]=sum_c rw[o][c]*mat[m][c]
__device__ float g_rv[2 * NB * 64];        // rw @ vsum
__device__ float g_ksumE[2 * NB * 64];     // ksum + eps
__device__ float g_wqT[2 * 64 * 64];       // q weights transposed [c][o]
__device__ float g_wkT[2 * 64 * 64];
__device__ float g_wvT[2 * 64 * 64];
__device__ float g_cwT[128 * 9 * 64];      // conv weights [ci][k][o]

// -------------------- tiny prep kernels --------------------

__global__ void __launch_bounds__(256) zero_stats_kernel() {
    int idx = blockIdx.x * 256 + threadIdx.x;     // grid = 256 blocks -> idx < 65536 exactly
    g_mat[idx] = 0.f;
    if (idx < 2 * NB * 64) { g_ksum[idx] = 0.f; g_vsum[idx] = 0.f; }
}

__global__ void __launch_bounds__(256) transpose64_kernel(const float* __restrict__ src,
                                                          int which, int br) {
    int idx = blockIdx.x * 256 + threadIdx.x;
    if (idx < 4096) {
        float* dst = (which == 0 ? g_wqT : which == 1 ? g_wkT : g_wvT) + br * 4096;
        int o = idx >> 6, c = idx & 63;
        dst[c * 64 + o] = src[idx];
    }
}

__global__ void __launch_bounds__(256) transpose_conv_kernel(const float* __restrict__ w) {
    int idx = blockIdx.x * 256 + threadIdx.x;
    if (idx < 64 * 128 * 9) {
        int o = idx / (128 * 9);
        int rem = idx % (128 * 9);
        int ci = rem / 9, k = rem % 9;
        g_cwT[(ci * 9 + k) * 64 + o] = w[idx];
    }
}

// -------------------- pass 1: K,V projections + global stats --------------------
// grid (64, 8), 256 threads. Each block: 1024 pixels = 16 tiles of 64.
__global__ void __launch_bounds__(256) pass1_kernel(
    const float* __restrict__ x,
    const float* __restrict__ kb, const float* __restrict__ vb,
    int br)
{
    __shared__ float sA[64 * 65];   // phase A: x tile [c*64+p]; phase B: K tile [m*65+p]
    __shared__ float sV[64 * 65];   // V tile [m*65+p]
    __shared__ float sInv[64];      // 1/||K_col||

    const int tid = threadIdx.x;
    const int ty = tid >> 4, tx = tid & 15;
    const int b = blockIdx.y;
    const float* xb = x + (size_t)b * 64 * NPIX;
    const int pbase = blockIdx.x * 1024;

    const float4* wkT = (const float4*)(g_wkT + br * 4096);
    const float4* wvT = (const float4*)(g_wvT + br * 4096);

    float macc[4][4];
    float ks[4] = {0.f, 0.f, 0.f, 0.f}, vs[4] = {0.f, 0.f, 0.f, 0.f};
#pragma unroll
    for (int i = 0; i < 4; i++)
#pragma unroll
        for (int j = 0; j < 4; j++) macc[i][j] = 0.f;

    float kbv[4], vbv[4];
#pragma unroll
    for (int i = 0; i < 4; i++) {
        kbv[i] = __ldg(&kb[ty * 4 + i]);
        vbv[i] = __ldg(&vb[ty * 4 + i]);
    }

    for (int t = 0; t < 16; t++) {
        const int p0 = pbase + t * 64;
        // load x tile (coalesced rows)
#pragma unroll
        for (int r = 0; r < 16; r++) {
            int i = tid + r * 256;
            int c = i >> 6, p = i & 63;
            sA[c * 64 + p] = xb[(size_t)c * NPIX + p0 + p];
        }
        __syncthreads();

        float ka[4][4], va[4][4];
#pragma unroll
        for (int i = 0; i < 4; i++)
#pragma unroll
            for (int j = 0; j < 4; j++) { ka[i][j] = 0.f; va[i][j] = 0.f; }

#pragma unroll 4
        for (int c = 0; c < 64; c++) {
            float4 wk = __ldg(&wkT[c * 16 + ty]);
            float4 wv = __ldg(&wvT[c * 16 + ty]);
            float4 xv = *(const float4*)&sA[c * 64 + tx * 4];
            float xa[4] = {xv.x, xv.y, xv.z, xv.w};
            float wka[4] = {wk.x, wk.y, wk.z, wk.w};
            float wva[4] = {wv.x, wv.y, wv.z, wv.w};
#pragma unroll
            for (int i = 0; i < 4; i++)
#pragma unroll
                for (int j = 0; j < 4; j++) {
                    ka[i][j] += wka[i] * xa[j];
                    va[i][j] += wva[i] * xa[j];
                }
        }
        __syncthreads();   // done reading x tile; sA now becomes K tile

#pragma unroll
        for (int i = 0; i < 4; i++)
#pragma unroll
            for (int j = 0; j < 4; j++) {
                sA[(ty * 4 + i) * 65 + tx * 4 + j] = ka[i][j] + kbv[i];
                sV[(ty * 4 + i) * 65 + tx * 4 + j] = va[i][j] + vbv[i];
            }
        __syncthreads();

        if (tid < 64) {
            float s = 0.f;
#pragma unroll 8
            for (int m = 0; m < 64; m++) { float v = sA[m * 65 + tid]; s += v * v; }
            sInv[tid] = rsqrtf(s);
        }
        __syncthreads();

        // matrix += Kn V^T ; ksum += Kn row sums ; vsum += V row sums
#pragma unroll 4
        for (int p = 0; p < 64; p++) {
            float inv = sInv[p];
            float a[4], bv[4];
#pragma unroll
            for (int i = 0; i < 4; i++) a[i] = sA[(ty * 4 + i) * 65 + p] * inv;
#pragma unroll
            for (int j = 0; j < 4; j++) bv[j] = sV[(tx * 4 + j) * 65 + p];
#pragma unroll
            for (int i = 0; i < 4; i++)
#pragma unroll
                for (int j = 0; j < 4; j++) macc[i][j] += a[i] * bv[j];
            if (tx == 0) {
#pragma unroll
                for (int i = 0; i < 4; i++) ks[i] += a[i];
            }
            if (ty == 0) {
#pragma unroll
                for (int j = 0; j < 4; j++) vs[j] += bv[j];
            }
        }
        __syncthreads();
    }

    float* mat = g_mat + ((size_t)br * NB + b) * 4096;
#pragma unroll
    for (int i = 0; i < 4; i++)
#pragma unroll
        for (int j = 0; j < 4; j++)
            atomicAdd(&mat[(ty * 4 + i) * 64 + tx * 4 + j], macc[i][j]);
    if (tx == 0) {
        float* kp = g_ksum + ((size_t)br * NB + b) * 64;
#pragma unroll
        for (int i = 0; i < 4; i++) atomicAdd(&kp[ty * 4 + i], ks[i]);
    }
    if (ty == 0) {
        float* vp = g_vsum + ((size_t)br * NB + b) * 64;
#pragma unroll
        for (int j = 0; j < 4; j++) atomicAdd(&vp[tx * 4 + j], vs[j]);
    }
}

// -------------------- mid: RM = rw @ mat^T, rv = rw @ vsum, ksum+eps ------------
__global__ void __launch_bounds__(256) mid_kernel(const float* __restrict__ rw, int br)
{
    __shared__ float sMat[4096];
    __shared__ float sRw[4096];
    const int tid = threadIdx.x;
    const int b = blockIdx.x;
    const float* mat = g_mat + ((size_t)br * NB + b) * 4096;
#pragma unroll
    for (int r = 0; r < 16; r++) {
        int i = tid + r * 256;
        sMat[i] = mat[i];
        sRw[i] = rw[i];
    }
    __syncthreads();
    const int ty = tid >> 4, tx = tid & 15;
    float acc[4][4];
#pragma unroll
    for (int i = 0; i < 4; i++)
#pragma unroll
        for (int j = 0; j < 4; j++) acc[i][j] = 0.f;
#pragma unroll 4
    for (int c = 0; c < 64; c++) {
        float a[4], w[4];
#pragma unroll
        for (int i = 0; i < 4; i++) a[i] = sMat[(ty * 4 + i) * 64 + c];
#pragma unroll
        for (int j = 0; j < 4; j++) w[j] = sRw[(tx * 4 + j) * 64 + c];
#pragma unroll
        for (int i = 0; i < 4; i++)
#pragma unroll
            for (int j = 0; j < 4; j++) acc[i][j] += a[i] * w[j];
    }
    float* RMt = g_RMt + ((size_t)br * NB + b) * 4096;
#pragma unroll
    for (int i = 0; i < 4; i++)
#pragma unroll
        for (int j = 0; j < 4; j++)
            RMt[(ty * 4 + i) * 64 + tx * 4 + j] = acc[i][j];   // [m][o]
    if (tid < 64) {
        const float* vsump = g_vsum + ((size_t)br * NB + b) * 64;
        float s = 0.f;
        for (int c = 0; c < 64; c++) s += sRw[tid * 64 + c] * vsump[c];
        g_rv[((size_t)br * NB + b) * 64 + tid] = s;
        g_ksumE[((size_t)br * NB + b) * 64 + tid] =
            g_ksum[((size_t)br * NB + b) * 64 + tid] + 1e-6f;
    }
}

// -------------------- pass 2: Q proj + per-pixel output --------------------
__global__ void __launch_bounds__(256) pass2_kernel(
    const float* __restrict__ x,
    const float* __restrict__ qb,
    const float* __restrict__ rb,
    int br)
{
    __shared__ float sA[64 * 65];  // x tile then Q tile
    __shared__ float sInv[64];
    __shared__ float sDen[64];

    const int tid = threadIdx.x;
    const int ty = tid >> 4, tx = tid & 15;
    const int b = blockIdx.y;
    const float* xb = x + (size_t)b * 64 * NPIX;
    const int pbase = blockIdx.x * 1024;

    const float4* wqT = (const float4*)(g_wqT + br * 4096);
    const float4* RMt4 = (const float4*)(g_RMt + ((size_t)br * NB + b) * 4096);
    const float* ksE = g_ksumE + ((size_t)br * NB + b) * 64;
    const float* rvp = g_rv + ((size_t)br * NB + b) * 64;

    float qbv[4], rvv[4], rbv[4];
#pragma unroll
    for (int i = 0; i < 4; i++) {
        qbv[i] = __ldg(&qb[ty * 4 + i]);
        rvv[i] = __ldg(&rvp[ty * 4 + i]);
        rbv[i] = __ldg(&rb[ty * 4 + i]);
    }

    float* outp = g_cat + ((size_t)b * 128 + br * 64) * NPIX;

    for (int t = 0; t < 16; t++) {
        const int p0 = pbase + t * 64;
#pragma unroll
        for (int r = 0; r < 16; r++) {
            int i = tid + r * 256;
            int c = i >> 6, p = i & 63;
            sA[c * 64 + p] = xb[(size_t)c * NPIX + p0 + p];
        }
        __syncthreads();
        float qa[4][4];
#pragma unroll
        for (int i = 0; i < 4; i++)
#pragma unroll
            for (int j = 0; j < 4; j++) qa[i][j] = 0.f;
#pragma unroll 4
        for (int c = 0; c < 64; c++) {
            float4 wq = __ldg(&wqT[c * 16 + ty]);
            float4 xv = *(const float4*)&sA[c * 64 + tx * 4];
            float xa[4] = {xv.x, xv.y, xv.z, xv.w};
            float wa[4] = {wq.x, wq.y, wq.z, wq.w};
#pragma unroll
            for (int i = 0; i < 4; i++)
#pragma unroll
                for (int j = 0; j < 4; j++) qa[i][j] += wa[i] * xa[j];
        }
        __syncthreads();
#pragma unroll
        for (int i = 0; i < 4; i++)
#pragma unroll
            for (int j = 0; j < 4; j++)
                sA[(ty * 4 + i) * 65 + tx * 4 + j] = qa[i][j] + qbv[i];
        __syncthreads();
        if (tid < 64) {
            float s = 0.f, d = 0.f;
#pragma unroll 8
            for (int m = 0; m < 64; m++) {
                float v = sA[m * 65 + tid];
                s += v * v;
                d += v * __ldg(&ksE[m]);
            }
            float inv = rsqrtf(s);
            sInv[tid] = inv;
            sDen[tid] = 1.f / (65536.f + inv * d);
        }
        __syncthreads();
        float sacc[4][4];
#pragma unroll
        for (int i = 0; i < 4; i++)
#pragma unroll
            for (int j = 0; j < 4; j++) sacc[i][j] = 0.f;
#pragma unroll 4
        for (int m = 0; m < 64; m++) {
            float4 a4 = __ldg(&RMt4[m * 16 + ty]);
            float aa[4] = {a4.x, a4.y, a4.z, a4.w};
            float bq[4];
#pragma unroll
            for (int j = 0; j < 4; j++) bq[j] = sA[m * 65 + tx * 4 + j];
#pragma unroll
            for (int i = 0; i < 4; i++)
#pragma unroll
                for (int j = 0; j < 4; j++) sacc[i][j] += aa[i] * bq[j];
        }
        float dn[4], iv[4];
#pragma unroll
        for (int j = 0; j < 4; j++) { dn[j] = sDen[tx * 4 + j]; iv[j] = sInv[tx * 4 + j]; }
#pragma unroll
        for (int i = 0; i < 4; i++) {
            int o = ty * 4 + i;
            float4 ov;
            ov.x = dn[0] * (rvv[i] + iv[0] * sacc[i][0]) + rbv[i];
            ov.y = dn[1] * (rvv[i] + iv[1] * sacc[i][1]) + rbv[i];
            ov.z = dn[2] * (rvv[i] + iv[2] * sacc[i][2]) + rbv[i];
            ov.w = dn[3] * (rvv[i] + iv[3] * sacc[i][3]) + rbv[i];
            *(float4*)&outp[(size_t)o * NPIX + p0 + tx * 4] = ov;
        }
        __syncthreads();
    }
}

// -------------------- conv 3x3, 128 -> 64 ch, SAME --------------------
// grid (8, 64, 8): 32x4 pixel tile, all 64 oc. 256 threads = 16 oc-groups x 16 pix.
__global__ void __launch_bounds__(256) conv_kernel(const float* __restrict__ cbias,
                                                   float* __restrict__ out)
{
    __shared__ float sx[8 * 6 * 36];   // [ci][y 0..5][x 0..33 pad 36]
    __shared__ float sw[8 * 9 * 64];   // [ci][k][o]
    __shared__ float sb[64];
    const int tid = threadIdx.x;
    const int ty = tid >> 4, tx = tid & 15;
    const int x0 = blockIdx.x * 32, y0 = blockIdx.y * 4, b = blockIdx.z;
    if (tid < 64) sb[tid] = cbias[tid];
    const float* catb = g_cat + (size_t)b * 128 * NPIX;

    float acc[4][8];
#pragma unroll
    for (int i = 0; i < 4; i++)
#pragma unroll
        for (int p = 0; p < 8; p++) acc[i][p] = 0.f;

    for (int c0 = 0; c0 < 128; c0 += 8) {
        __syncthreads();
        for (int i = tid; i < 8 * 6 * 34; i += 256) {
            int ci = i / 204, r = i % 204, yy = r / 34, xx = r % 34;
            int gy = y0 + yy - 1, gx = x0 + xx - 1;
            float v = 0.f;
            if (gy >= 0 && gy < IMG_H && gx >= 0 && gx < IMG_W)
                v = catb[(size_t)(c0 + ci) * NPIX + gy * IMG_W + gx];
            sx[ci * 216 + yy * 36 + xx] = v;
        }
        for (int i = tid; i < 8 * 9 * 64; i += 256) {
            int o = i & 63, kk = (i >> 6) % 9, ci = i / 576;
            sw[ci * 576 + kk * 64 + o] = g_cwT[((size_t)(c0 + ci) * 9 + kk) * 64 + o];
        }
        __syncthreads();
#pragma unroll 2
        for (int ci = 0; ci < 8; ci++) {
            const float* sxc = sx + ci * 216;
            const float* swc = sw + ci * 576;
#pragma unroll
            for (int ky = 0; ky < 3; ky++) {
#pragma unroll
                for (int kx = 0; kx < 3; kx++) {
                    float4 w4 = *(const float4*)(swc + (ky * 3 + kx) * 64 + ty * 4);
#pragma unroll
                    for (int py = 0; py < 4; py++) {
#pragma unroll
                        for (int pxi = 0; pxi < 2; pxi++) {
                            float xv = sxc[(py + ky) * 36 + tx * 2 + pxi + kx];
                            int pi = py * 2 + pxi;
                            acc[0][pi] += w4.x * xv;
                            acc[1][pi] += w4.y * xv;
                            acc[2][pi] += w4.z * xv;
                            acc[3][pi] += w4.w * xv;
                        }
                    }
                }
            }
        }
    }
#pragma unroll
    for (int i = 0; i < 4; i++) {
        int o = ty * 4 + i;
        float bias = sb[o];
#pragma unroll
        for (int py = 0; py < 4; py++) {
            float2 v2;
            v2.x = acc[i][py * 2] + bias;
            v2.y = acc[i][py * 2 + 1] + bias;
            *(float2*)&out[((size_t)(b * 64 + o)) * NPIX + (size_t)(y0 + py) * IMG_W + x0 + tx * 2] = v2;
        }
    }
}

// -------------------- launch --------------------
extern "C" void kernel_launch(void* const* d_in, const int* in_sizes, int n_in,
                              void* d_out, int out_size)
{
    (void)in_sizes; (void)n_in; (void)out_size;
    const float* t1  = (const float*)d_in[0];
    const float* t2  = (const float*)d_in[1];
    const float* q1w = (const float*)d_in[2];  const float* q1b = (const float*)d_in[3];
    const float* k1w = (const float*)d_in[4];  const float* k1b = (const float*)d_in[5];
    const float* v1w = (const float*)d_in[6];  const float* v1b = (const float*)d_in[7];
    const float* r1w = (const float*)d_in[8];  const float* r1b = (const float*)d_in[9];
    const float* q2w = (const float*)d_in[10]; const float* q2b = (const float*)d_in[11];
    const float* k2w = (const float*)d_in[12]; const float* k2b = (const float*)d_in[13];
    const float* v2w = (const float*)d_in[14]; const float* v2b = (const float*)d_in[15];
    const float* r2w = (const float*)d_in[16]; const float* r2b = (const float*)d_in[17];
    const float* cw  = (const float*)d_in[18]; const float* cb  = (const float*)d_in[19];

    zero_stats_kernel<<<256, 256>>>();
    transpose64_kernel<<<16, 256>>>(q1w, 0, 0);
    transpose64_kernel<<<16, 256>>>(k1w, 1, 0);
    transpose64_kernel<<<16, 256>>>(v1w, 2, 0);
    transpose64_kernel<<<16, 256>>>(q2w, 0, 1);
    transpose64_kernel<<<16, 256>>>(k2w, 1, 1);
    transpose64_kernel<<<16, 256>>>(v2w, 2, 1);
    transpose_conv_kernel<<<(64 * 128 * 9 + 255) / 256, 256>>>(cw);

    dim3 g1(64, 8);
    pass1_kernel<<<g1, 256>>>(t1, k1b, v1b, 0);
    pass1_kernel<<<g1, 256>>>(t2, k2b, v2b, 1);
    mid_kernel<<<8, 256>>>(r1w, 0);
    mid_kernel<<<8, 256>>>(r2w, 1);
    pass2_kernel<<<g1, 256>>>(t1, q1b, r1b, 0);
    pass2_kernel<<<g1, 256>>>(t2, q2b, r2b, 1);

    dim3 gc(8, 64, 8);
    conv_kernel<<<gc, 256>>>(cb, (float*)d_out);
}

// round 2
// speedup vs baseline: 1.1194x; 1.1194x over previous
#include <cuda_runtime.h>

#define NPIX 65536
#define IMG_H 256
#define IMG_W 256
#define NB 8

// ---- device scratch ----
__device__ float g_cat[NB * 128 * NPIX];    // [b][128][N]
__device__ float g_mat[2 * NB * 64 * 64];   // K V^T  [br][b][m][c]
__device__ float g_ksum[2 * NB * 64];
__device__ float g_vsum[2 * NB * 64];
__device__ float g_RMt2[2 * NB * 64 * 128]; // dup'd: [m][2o],[m][2o+1]
__device__ float g_rv[2 * NB * 64];
__device__ float g_ksumE[2 * NB * 64];
__device__ float g_wqT2[2 * 64 * 128];      // dup'd transposed q weights [c][2o]
__device__ float g_wkT[2 * 64 * 64];        // [c][o]
__device__ float g_wvT[2 * 64 * 64];
__device__ float g_cwT[128 * 9 * 64];       // [ci][k][o]

// ---- packed f32x2 helpers ----
__device__ __forceinline__ float2 ffma2(float2 a, float2 b, float2 c) {
    float2 d;
    asm("fma.rn.f32x2 %0, %1, %2, %3;"
        : "=l"(*(unsigned long long*)&d)
        : "l"(*(unsigned long long*)&a), "l"(*(unsigned long long*)&b),
          "l"(*(unsigned long long*)&c));
    return d;
}
__device__ __forceinline__ float2 mul2(float2 a, float2 b) {
    float2 d;
    asm("mul.rn.f32x2 %0, %1, %2;"
        : "=l"(*(unsigned long long*)&d)
        : "l"(*(unsigned long long*)&a), "l"(*(unsigned long long*)&b));
    return d;
}
__device__ __forceinline__ float2 add2(float2 a, float2 b) {
    float2 d;
    asm("add.rn.f32x2 %0, %1, %2;"
        : "=l"(*(unsigned long long*)&d)
        : "l"(*(unsigned long long*)&a), "l"(*(unsigned long long*)&b));
    return d;
}

// -------------------- prep kernels --------------------
__global__ void __launch_bounds__(256) zero_stats_kernel() {
    int idx = blockIdx.x * 256 + threadIdx.x;    // 256 blocks -> 65536
    g_mat[idx] = 0.f;
    if (idx < 2 * NB * 64) { g_ksum[idx] = 0.f; g_vsum[idx] = 0.f; }
}

__global__ void __launch_bounds__(256) transpose64_kernel(const float* __restrict__ src,
                                                          int which, int br) {
    int idx = blockIdx.x * 256 + threadIdx.x;
    if (idx < 4096) {
        float* dst = (which == 0 ? g_wkT : g_wvT) + br * 4096;
        int o = idx >> 6, c = idx & 63;
        dst[c * 64 + o] = src[idx];
    }
}

__global__ void __launch_bounds__(256) transpose_dup_kernel(const float* __restrict__ src,
                                                            int br) {
    int idx = blockIdx.x * 256 + threadIdx.x;
    if (idx < 4096) {
        int o = idx >> 6, c = idx & 63;
        float v = src[idx];
        float2* dst = (float2*)(g_wqT2 + br * 8192);
        dst[c * 64 + o] = make_float2(v, v);
    }
}

__global__ void __launch_bounds__(256) transpose_conv_kernel(const float* __restrict__ w) {
    int idx = blockIdx.x * 256 + threadIdx.x;
    if (idx < 64 * 128 * 9) {
        int o = idx / (128 * 9);
        int rem = idx % (128 * 9);
        int ci = rem / 9, k = rem % 9;
        g_cwT[(ci * 9 + k) * 64 + o] = w[idx];
    }
}

// -------------------- pass 1: K,V proj + stats --------------------
// grid (128, 8, 2), 256 thr. 512 px per block (8 tiles of 64).
__global__ void __launch_bounds__(256) pass1_kernel(
    const float* __restrict__ x1, const float* __restrict__ x2,
    const float* __restrict__ kb1, const float* __restrict__ vb1,
    const float* __restrict__ kb2, const float* __restrict__ vb2)
{
    __shared__ float sKt[64 * 68];   // phase A: x tile [c*64+p] (4096<4352); phase B: Kt [p][m] st68
    __shared__ float sVt[64 * 68];
    __shared__ float sNp[4 * 64];
    __shared__ float sInv[64];

    const int tid = threadIdx.x;
    const int ty = tid >> 4, tx = tid & 15;
    const int b = blockIdx.y, br = blockIdx.z;
    const float* xb = (br ? x2 : x1) + (size_t)b * 64 * NPIX;
    const float* kb = br ? kb2 : kb1;
    const float* vb = br ? vb2 : vb1;
    const int pbase = blockIdx.x * 512;

    const float4* wk4 = (const float4*)(g_wkT + br * 4096);
    const float4* wv4 = (const float4*)(g_wvT + br * 4096);

    float2 kbv[2], vbv[2];
#pragma unroll
    for (int ip = 0; ip < 2; ip++) {
        kbv[ip] = __ldg(&((const float2*)kb)[ty * 2 + ip]);
        vbv[ip] = __ldg(&((const float2*)vb)[ty * 2 + ip]);
    }

    float2 macc[2][4];
    float2 ks2[2] = {{0.f, 0.f}, {0.f, 0.f}};
    float2 vs2[2] = {{0.f, 0.f}, {0.f, 0.f}};
#pragma unroll
    for (int ip = 0; ip < 2; ip++)
#pragma unroll
        for (int j = 0; j < 4; j++) macc[ip][j] = make_float2(0.f, 0.f);

    for (int t = 0; t < 8; t++) {
        const int p0 = pbase + t * 64;
#pragma unroll
        for (int r = 0; r < 16; r++) {
            int i = tid + r * 256;
            sKt[i] = xb[(size_t)(i >> 6) * NPIX + p0 + (i & 63)];
        }
        __syncthreads();

        float2 ka[2][4], va[2][4];
#pragma unroll
        for (int ip = 0; ip < 2; ip++)
#pragma unroll
            for (int j = 0; j < 4; j++) { ka[ip][j] = kbv[ip]; va[ip][j] = vbv[ip]; }

#pragma unroll 8
        for (int c = 0; c < 64; c++) {
            float4 xv = *(const float4*)&sKt[c * 64 + tx * 4];
            float2 xd[4] = {{xv.x, xv.x}, {xv.y, xv.y}, {xv.z, xv.z}, {xv.w, xv.w}};
            float4 wk = __ldg(&wk4[c * 16 + ty]);
            float4 wv = __ldg(&wv4[c * 16 + ty]);
            float2 wkp[2] = {{wk.x, wk.y}, {wk.z, wk.w}};
            float2 wvp[2] = {{wv.x, wv.y}, {wv.z, wv.w}};
#pragma unroll
            for (int ip = 0; ip < 2; ip++)
#pragma unroll
                for (int j = 0; j < 4; j++) {
                    ka[ip][j] = ffma2(wkp[ip], xd[j], ka[ip][j]);
                    va[ip][j] = ffma2(wvp[ip], xd[j], va[ip][j]);
                }
        }
        __syncthreads();

        // write transposed [p][m], st 68
#pragma unroll
        for (int j = 0; j < 4; j++)
#pragma unroll
            for (int ip = 0; ip < 2; ip++) {
                *(float2*)&sKt[(tx * 4 + j) * 68 + ty * 4 + ip * 2] = ka[ip][j];
                *(float2*)&sVt[(tx * 4 + j) * 68 + ty * 4 + ip * 2] = va[ip][j];
            }
        __syncthreads();

        // distributed norm: thread (p = tid&63, q = tid>>6) sums 16 m's
        {
            int p = tid & 63, q = tid >> 6;
            const float2* row = (const float2*)(sKt + p * 68 + q * 16);
            float2 s2 = make_float2(0.f, 0.f);
#pragma unroll
            for (int mm = 0; mm < 8; mm++) s2 = ffma2(row[mm], row[mm], s2);
            sNp[q * 64 + p] = s2.x + s2.y;
        }
        __syncthreads();
        if (tid < 64)
            sInv[tid] = rsqrtf(sNp[tid] + sNp[64 + tid] + sNp[128 + tid] + sNp[192 + tid]);
        __syncthreads();

        // stats: matrix += Kn V^T, ksum, vsum
#pragma unroll 4
        for (int p = 0; p < 64; p++) {
            float inv = sInv[p];
            float2 invd = {inv, inv};
            float4 a4 = *(const float4*)&sKt[p * 68 + ty * 4];
            float2 a2[2] = {mul2(make_float2(a4.x, a4.y), invd),
                            mul2(make_float2(a4.z, a4.w), invd)};
            float4 b4 = *(const float4*)&sVt[p * 68 + tx * 4];
            float2 bd[4] = {{b4.x, b4.x}, {b4.y, b4.y}, {b4.z, b4.z}, {b4.w, b4.w}};
#pragma unroll
            for (int ip = 0; ip < 2; ip++)
#pragma unroll
                for (int j = 0; j < 4; j++) macc[ip][j] = ffma2(a2[ip], bd[j], macc[ip][j]);
            if (tx == 0) {
                ks2[0] = add2(ks2[0], a2[0]);
                ks2[1] = add2(ks2[1], a2[1]);
            }
            if (ty == 0) {
                vs2[0] = add2(vs2[0], make_float2(b4.x, b4.y));
                vs2[1] = add2(vs2[1], make_float2(b4.z, b4.w));
            }
        }
        __syncthreads();
    }

    float* mat = g_mat + ((size_t)br * NB + b) * 4096;
#pragma unroll
    for (int ip = 0; ip < 2; ip++)
#pragma unroll
        for (int j = 0; j < 4; j++) {
            atomicAdd(&mat[(ty * 4 + ip * 2) * 64 + tx * 4 + j], macc[ip][j].x);
            atomicAdd(&mat[(ty * 4 + ip * 2 + 1) * 64 + tx * 4 + j], macc[ip][j].y);
        }
    if (tx == 0) {
        float* kp = g_ksum + ((size_t)br * NB + b) * 64;
#pragma unroll
        for (int ip = 0; ip < 2; ip++) {
            atomicAdd(&kp[ty * 4 + ip * 2], ks2[ip].x);
            atomicAdd(&kp[ty * 4 + ip * 2 + 1], ks2[ip].y);
        }
    }
    if (ty == 0) {
        float* vp = g_vsum + ((size_t)br * NB + b) * 64;
        atomicAdd(&vp[tx * 4 + 0], vs2[0].x);
        atomicAdd(&vp[tx * 4 + 1], vs2[0].y);
        atomicAdd(&vp[tx * 4 + 2], vs2[1].x);
        atomicAdd(&vp[tx * 4 + 3], vs2[1].y);
    }
}

// -------------------- mid: RM (dup'd), rv, ksum+eps --------------------
__global__ void __launch_bounds__(256) mid_kernel(const float* __restrict__ rw1,
                                                  const float* __restrict__ rw2)
{
    __shared__ float sMat[4096];
    __shared__ float sRw[4096];
    const int tid = threadIdx.x;
    const int b = blockIdx.x, br = blockIdx.y;
    const float* rw = br ? rw2 : rw1;
    const float* mat = g_mat + ((size_t)br * NB + b) * 4096;
#pragma unroll
    for (int r = 0; r < 16; r++) {
        int i = tid + r * 256;
        sMat[i] = mat[i];
        sRw[i] = rw[i];
    }
    __syncthreads();
    const int ty = tid >> 4, tx = tid & 15;
    float acc[4][4];
#pragma unroll
    for (int i = 0; i < 4; i++)
#pragma unroll
        for (int j = 0; j < 4; j++) acc[i][j] = 0.f;
#pragma unroll 4
    for (int c = 0; c < 64; c++) {
        float a[4], w[4];
#pragma unroll
        for (int i = 0; i < 4; i++) a[i] = sMat[(ty * 4 + i) * 64 + c];
#pragma unroll
        for (int j = 0; j < 4; j++) w[j] = sRw[(tx * 4 + j) * 64 + c];
#pragma unroll
        for (int i = 0; i < 4; i++)
#pragma unroll
            for (int j = 0; j < 4; j++) acc[i][j] += a[i] * w[j];
    }
    float2* RMt = (float2*)(g_RMt2 + ((size_t)br * NB + b) * 8192);
#pragma unroll
    for (int i = 0; i < 4; i++)
#pragma unroll
        for (int j = 0; j < 4; j++)
            RMt[(ty * 4 + i) * 64 + tx * 4 + j] = make_float2(acc[i][j], acc[i][j]);
    if (tid < 64) {
        const float* vsump = g_vsum + ((size_t)br * NB + b) * 64;
        float s = 0.f;
        for (int c = 0; c < 64; c++) s += sRw[tid * 64 + c] * vsump[c];
        g_rv[((size_t)br * NB + b) * 64 + tid] = s;
        g_ksumE[((size_t)br * NB + b) * 64 + tid] =
            g_ksum[((size_t)br * NB + b) * 64 + tid] + 1e-6f;
    }
}

// -------------------- pass 2: Q proj + output --------------------
// grid (128, 8, 2), 256 thr, 512 px/block
__global__ void __launch_bounds__(256) pass2_kernel(
    const float* __restrict__ x1, const float* __restrict__ x2,
    const float* __restrict__ qb1, const float* __restrict__ rb1,
    const float* __restrict__ qb2, const float* __restrict__ rb2)
{
    __shared__ float sQ[64 * 64];    // x tile then Q tile [m][p]
    __shared__ float sNp[256], sDp[256];
    __shared__ float sInv[64], sDen[64];

    const int tid = threadIdx.x;
    const int ty = tid >> 4, tx = tid & 15;
    const int b = blockIdx.y, br = blockIdx.z;
    const float* xb = (br ? x2 : x1) + (size_t)b * 64 * NPIX;
    const float* qb = br ? qb2 : qb1;
    const float* rb = br ? rb2 : rb1;
    const int pbase = blockIdx.x * 512;

    const float4* wq4 = (const float4*)(g_wqT2 + br * 8192);
    const float4* rm4 = (const float4*)(g_RMt2 + ((size_t)br * NB + b) * 8192);
    const float* ksE = g_ksumE + ((size_t)br * NB + b) * 64;
    const float* rvp = g_rv + ((size_t)br * NB + b) * 64;

    float2 qbv[4], rv2[4], rb2v[4];
#pragma unroll
    for (int i = 0; i < 4; i++) {
        float q = __ldg(&qb[ty * 4 + i]);
        float rv = __ldg(&rvp[ty * 4 + i]);
        float rbv = __ldg(&rb[ty * 4 + i]);
        qbv[i] = make_float2(q, q);
        rv2[i] = make_float2(rv, rv);
        rb2v[i] = make_float2(rbv, rbv);
    }

    float* outp = g_cat + ((size_t)b * 128 + br * 64) * NPIX;

    for (int t = 0; t < 8; t++) {
        const int p0 = pbase + t * 64;
#pragma unroll
        for (int r = 0; r < 16; r++) {
            int i = tid + r * 256;
            sQ[i] = xb[(size_t)(i >> 6) * NPIX + p0 + (i & 63)];
        }
        __syncthreads();

        float2 qa[4][2];
#pragma unroll
        for (int i = 0; i < 4; i++) { qa[i][0] = qbv[i]; qa[i][1] = qbv[i]; }

#pragma unroll 8
        for (int c = 0; c < 64; c++) {
            float4 xv = *(const float4*)&sQ[c * 64 + tx * 4];
            float2 xp[2] = {{xv.x, xv.y}, {xv.z, xv.w}};
            float4 w0 = __ldg(&wq4[c * 32 + ty * 2]);
            float4 w1 = __ldg(&wq4[c * 32 + ty * 2 + 1]);
            float2 wd[4] = {{w0.x, w0.y}, {w0.z, w0.w}, {w1.x, w1.y}, {w1.z, w1.w}};
#pragma unroll
            for (int i = 0; i < 4; i++)
#pragma unroll
                for (int jp = 0; jp < 2; jp++) qa[i][jp] = ffma2(wd[i], xp[jp], qa[i][jp]);
        }
        __syncthreads();

#pragma unroll
        for (int i = 0; i < 4; i++)
#pragma unroll
            for (int jp = 0; jp < 2; jp++)
                *(float2*)&sQ[(ty * 4 + i) * 64 + tx * 4 + jp * 2] = qa[i][jp];
        __syncthreads();

        // distributed norm + denom
        {
            int p = tid & 63, q = tid >> 6;
            float s = 0.f, d = 0.f;
#pragma unroll
            for (int mm = 0; mm < 16; mm++) {
                int m = q * 16 + mm;
                float v = sQ[m * 64 + p];
                s = fmaf(v, v, s);
                d = fmaf(v, __ldg(&ksE[m]), d);
            }
            sNp[q * 64 + p] = s;
            sDp[q * 64 + p] = d;
        }
        __syncthreads();
        if (tid < 64) {
            float s = sNp[tid] + sNp[64 + tid] + sNp[128 + tid] + sNp[192 + tid];
            float d = sDp[tid] + sDp[64 + tid] + sDp[128 + tid] + sDp[192 + tid];
            float inv = rsqrtf(s);
            sInv[tid] = inv;
            sDen[tid] = 1.f / (65536.f + inv * d);
        }
        __syncthreads();

        float2 acc[4][2];
#pragma unroll
        for (int i = 0; i < 4; i++) { acc[i][0] = make_float2(0.f, 0.f); acc[i][1] = make_float2(0.f, 0.f); }

#pragma unroll 8
        for (int m = 0; m < 64; m++) {
            float4 bq = *(const float4*)&sQ[m * 64 + tx * 4];
            float2 bp[2] = {{bq.x, bq.y}, {bq.z, bq.w}};
            float4 w0 = __ldg(&rm4[m * 32 + ty * 2]);
            float4 w1 = __ldg(&rm4[m * 32 + ty * 2 + 1]);
            float2 wd[4] = {{w0.x, w0.y}, {w0.z, w0.w}, {w1.x, w1.y}, {w1.z, w1.w}};
#pragma unroll
            for (int i = 0; i < 4; i++)
#pragma unroll
                for (int jp = 0; jp < 2; jp++) acc[i][jp] = ffma2(wd[i], bp[jp], acc[i][jp]);
        }

        float2 iv[2] = {*(const float2*)&sInv[tx * 4], *(const float2*)&sInv[tx * 4 + 2]};
        float2 dn[2] = {*(const float2*)&sDen[tx * 4], *(const float2*)&sDen[tx * 4 + 2]};
#pragma unroll
        for (int i = 0; i < 4; i++) {
            float2 t0 = ffma2(iv[0], acc[i][0], rv2[i]);
            float2 t1 = ffma2(iv[1], acc[i][1], rv2[i]);
            t0 = ffma2(dn[0], t0, rb2v[i]);
            t1 = ffma2(dn[1], t1, rb2v[i]);
            float4 ov = make_float4(t0.x, t0.y, t1.x, t1.y);
            *(float4*)&outp[(size_t)(ty * 4 + i) * NPIX + p0 + tx * 4] = ov;
        }
        __syncthreads();
    }
}

// -------------------- conv 3x3, 128 -> 64, SAME --------------------
// grid (8, 64, 8), 256 thr. Tile: 32x4 px, 64 oc. oc-packed f32x2.
__global__ void __launch_bounds__(256) conv_kernel(const float* __restrict__ cbias,
                                                   float* __restrict__ out)
{
    __shared__ float sx[8 * 6 * 36];
    __shared__ float sw[8 * 9 * 64];
    __shared__ float sb[64];
    const int tid = threadIdx.x;
    const int ty = tid >> 4, tx = tid & 15;
    const int x0 = blockIdx.x * 32, y0 = blockIdx.y * 4, b = blockIdx.z;
    if (tid < 64) sb[tid] = cbias[tid];
    const float* catb = g_cat + (size_t)b * 128 * NPIX;

    float2 acc[2][8];   // [oc pair][py*2+px]
#pragma unroll
    for (int ip = 0; ip < 2; ip++)
#pragma unroll
        for (int p = 0; p < 8; p++) acc[ip][p] = make_float2(0.f, 0.f);

    for (int c0 = 0; c0 < 128; c0 += 8) {
        __syncthreads();
        for (int i = tid; i < 8 * 6 * 34; i += 256) {
            int ci = i / 204, r = i % 204, yy = r / 34, xx = r % 34;
            int gy = y0 + yy - 1, gx = x0 + xx - 1;
            float v = 0.f;
            if (gy >= 0 && gy < IMG_H && gx >= 0 && gx < IMG_W)
                v = catb[(size_t)(c0 + ci) * NPIX + gy * IMG_W + gx];
            sx[ci * 216 + yy * 36 + xx] = v;
        }
        for (int i = tid; i < 8 * 9 * 64; i += 256) {
            int o = i & 63, kk = (i >> 6) % 9, ci = i / 576;
            sw[ci * 576 + kk * 64 + o] = g_cwT[((size_t)(c0 + ci) * 9 + kk) * 64 + o];
        }
        __syncthreads();
#pragma unroll 2
        for (int ci = 0; ci < 8; ci++) {
            const float* sxc = sx + ci * 216;
            const float* swc = sw + ci * 576;
            // per-row x values tx*2 .. tx*2+3, duplicated
            float2 d[6][4];
#pragma unroll
            for (int r = 0; r < 6; r++) {
                float2 e0 = *(const float2*)&sxc[r * 36 + tx * 2];
                float2 e1 = *(const float2*)&sxc[r * 36 + tx * 2 + 2];
                d[r][0] = make_float2(e0.x, e0.x);
                d[r][1] = make_float2(e0.y, e0.y);
                d[r][2] = make_float2(e1.x, e1.x);
                d[r][3] = make_float2(e1.y, e1.y);
            }
#pragma unroll
            for (int ky = 0; ky < 3; ky++)
#pragma unroll
                for (int kx = 0; kx < 3; kx++) {
                    float4 w4 = *(const float4*)&swc[(ky * 3 + kx) * 64 + ty * 4];
                    float2 w0 = make_float2(w4.x, w4.y);
                    float2 w1 = make_float2(w4.z, w4.w);
#pragma unroll
                    for (int py = 0; py < 4; py++) {
                        int r = py + ky;
                        acc[0][py * 2 + 0] = ffma2(w0, d[r][kx], acc[0][py * 2 + 0]);
                        acc[1][py * 2 + 0] = ffma2(w1, d[r][kx], acc[1][py * 2 + 0]);
                        acc[0][py * 2 + 1] = ffma2(w0, d[r][kx + 1], acc[0][py * 2 + 1]);
                        acc[1][py * 2 + 1] = ffma2(w1, d[r][kx + 1], acc[1][py * 2 + 1]);
                    }
                }
        }
    }
#pragma unroll
    for (int ip = 0; ip < 2; ip++) {
#pragma unroll
        for (int h = 0; h < 2; h++) {
            int o = ty * 4 + ip * 2 + h;
            float bias = sb[o];
#pragma unroll
            for (int py = 0; py < 4; py++) {
                float2 v2;
                if (h == 0) {
                    v2.x = acc[ip][py * 2 + 0].x + bias;
                    v2.y = acc[ip][py * 2 + 1].x + bias;
                } else {
                    v2.x = acc[ip][py * 2 + 0].y + bias;
                    v2.y = acc[ip][py * 2 + 1].y + bias;
                }
                *(float2*)&out[((size_t)(b * 64 + o)) * NPIX +
                               (size_t)(y0 + py) * IMG_W + x0 + tx * 2] = v2;
            }
        }
    }
}

// -------------------- launch --------------------
extern "C" void kernel_launch(void* const* d_in, const int* in_sizes, int n_in,
                              void* d_out, int out_size)
{
    (void)in_sizes; (void)n_in; (void)out_size;
    const float* t1  = (const float*)d_in[0];
    const float* t2  = (const float*)d_in[1];
    const float* q1w = (const float*)d_in[2];  const float* q1b = (const float*)d_in[3];
    const float* k1w = (const float*)d_in[4];  const float* k1b = (const float*)d_in[5];
    const float* v1w = (const float*)d_in[6];  const float* v1b = (const float*)d_in[7];
    const float* r1w = (const float*)d_in[8];  const float* r1b = (const float*)d_in[9];
    const float* q2w = (const float*)d_in[10]; const float* q2b = (const float*)d_in[11];
    const float* k2w = (const float*)d_in[12]; const float* k2b = (const float*)d_in[13];
    const float* v2w = (const float*)d_in[14]; const float* v2b = (const float*)d_in[15];
    const float* r2w = (const float*)d_in[16]; const float* r2b = (const float*)d_in[17];
    const float* cw  = (const float*)d_in[18]; const float* cb  = (const float*)d_in[19];

    zero_stats_kernel<<<256, 256>>>();
    transpose64_kernel<<<16, 256>>>(k1w, 0, 0);
    transpose64_kernel<<<16, 256>>>(v1w, 1, 0);
    transpose64_kernel<<<16, 256>>>(k2w, 0, 1);
    transpose64_kernel<<<16, 256>>>(v2w, 1, 1);
    transpose_dup_kernel<<<16, 256>>>(q1w, 0);
    transpose_dup_kernel<<<16, 256>>>(q2w, 1);
    transpose_conv_kernel<<<(64 * 128 * 9 + 255) / 256, 256>>>(cw);

    dim3 g1(128, 8, 2);
    pass1_kernel<<<g1, 256>>>(t1, t2, k1b, v1b, k2b, v2b);
    dim3 gm(8, 2);
    mid_kernel<<<gm, 256>>>(r1w, r2w);
    pass2_kernel<<<g1, 256>>>(t1, t2, q1b, r1b, q2b, r2b);

    dim3 gc(8, 64, 8);
    conv_kernel<<<gc, 256>>>(cb, (float*)d_out);
}

// round 5
// speedup vs baseline: 1.2383x; 1.1061x over previous
#include <cuda_runtime.h>
#include <cuda_bf16.h>
#include <cstdint>

#define NPIX 65536
#define IMG_H 256
#define IMG_W 256
#define NB 8

// ---- device scratch ----
__device__ __nv_bfloat16 g_hi[NB * NPIX * 128];   // NHWC [b][y][x][ci], hi plane
__device__ __nv_bfloat16 g_lo[NB * NPIX * 128];   // lo plane
__device__ uint32_t g_Bfrag[3 * 24 * 2 * 32 * 16]; // [ky][kc][half][lane][nt*2+j] mma B frags
__device__ float g_mat[2 * NB * 64 * 64];
__device__ float g_ksum[2 * NB * 64];
__device__ float g_vsum[2 * NB * 64];
__device__ float g_RMt2[2 * NB * 64 * 128];
__device__ float g_rv[2 * NB * 64];
__device__ float g_ksumE[2 * NB * 64];
__device__ float g_wqT2[2 * 64 * 128];
__device__ float g_wkT[2 * 64 * 64];
__device__ float g_wvT[2 * 64 * 64];

// ---- packed f32x2 helpers ----
__device__ __forceinline__ float2 ffma2(float2 a, float2 b, float2 c) {
    float2 d;
    asm("fma.rn.f32x2 %0, %1, %2, %3;"
        : "=l"(*(unsigned long long*)&d)
        : "l"(*(unsigned long long*)&a), "l"(*(unsigned long long*)&b),
          "l"(*(unsigned long long*)&c));
    return d;
}
__device__ __forceinline__ float2 mul2(float2 a, float2 b) {
    float2 d;
    asm("mul.rn.f32x2 %0, %1, %2;"
        : "=l"(*(unsigned long long*)&d)
        : "l"(*(unsigned long long*)&a), "l"(*(unsigned long long*)&b));
    return d;
}
__device__ __forceinline__ float2 add2(float2 a, float2 b) {
    float2 d;
    asm("add.rn.f32x2 %0, %1, %2;"
        : "=l"(*(unsigned long long*)&d)
        : "l"(*(unsigned long long*)&a), "l"(*(unsigned long long*)&b));
    return d;
}

// ---- mma.sync bf16 helper (m16n8k16, f32 accum) ----
__device__ __forceinline__ void mma_bf16(float* d,
                                         uint32_t a0, uint32_t a1, uint32_t a2, uint32_t a3,
                                         uint32_t b0, uint32_t b1) {
    asm volatile(
        "mma.sync.aligned.m16n8k16.row.col.f32.bf16.bf16.f32 "
        "{%0,%1,%2,%3}, {%4,%5,%6,%7}, {%8,%9}, {%0,%1,%2,%3};"
        : "+f"(d[0]), "+f"(d[1]), "+f"(d[2]), "+f"(d[3])
        : "r"(a0), "r"(a1), "r"(a2), "r"(a3), "r"(b0), "r"(b1));
}

// -------------------- prep A: zero stats + weight transposes --------------------
__global__ void __launch_bounds__(256) prepA_kernel(
    const float* __restrict__ q1w, const float* __restrict__ k1w, const float* __restrict__ v1w,
    const float* __restrict__ q2w, const float* __restrict__ k2w, const float* __restrict__ v2w)
{
    int nb = blockIdx.x, tid = threadIdx.x;
    if (nb < 256) {
        int idx = nb * 256 + tid;
        g_mat[idx] = 0.f;
        if (idx < 2 * NB * 64) { g_ksum[idx] = 0.f; g_vsum[idx] = 0.f; }
        return;
    }
    int t = nb - 256;                // 0..95
    int table = t >> 4, sub = t & 15;
    int idx = sub * 256 + tid;       // 0..4095
    int o = idx >> 6, c = idx & 63;
    if (table == 0) g_wkT[c * 64 + o] = k1w[idx];
    else if (table == 1) g_wvT[c * 64 + o] = v1w[idx];
    else if (table == 2) g_wkT[4096 + c * 64 + o] = k2w[idx];
    else if (table == 3) g_wvT[4096 + c * 64 + o] = v2w[idx];
    else if (table == 4) {
        float v = q1w[idx];
        ((float2*)g_wqT2)[c * 64 + o] = make_float2(v, v);
    } else {
        float v = q2w[idx];
        ((float2*)(g_wqT2 + 8192))[c * 64 + o] = make_float2(v, v);
    }
}

// -------------------- prep B: conv weights -> mma B fragments (bf16 hi/lo) --------
// Fragment layout: u32 index = ((ky*24 + kc)*2 + half)*512 + lane*16 + nt*2 + j
// kc = kx*8 + cc8. B operand value (col-major k16 x n8):
//   reg j: k_local = (lane%4)*2 + j*8 + {0 lo16, 1 hi16};  n = nt*8 + lane/4
//   global ci = cc8*16 + k_local;  weight = cw[o=n][ci][ky][kx]
__global__ void __launch_bounds__(256) prepB_kernel(const float* __restrict__ cw)
{
    int i = blockIdx.x * 256 + threadIdx.x;
    if (i >= 73728) return;
    int ky = i / 24576;
    int rem = i % 24576;
    int kc = rem / 1024;
    int rem2 = rem % 1024;
    int half = rem2 / 512;
    int rem3 = rem2 % 512;
    int lane = rem3 / 16;
    int r4 = rem3 % 16;
    int nt = r4 >> 1, j = r4 & 1;

    int kx = kc >> 3, cc8 = kc & 7;
    int n = nt * 8 + (lane >> 2);
    int k0 = (lane & 3) * 2 + j * 8;
    int ci0 = cc8 * 16 + k0;

    float w0 = cw[((n * 128 + ci0) * 3 + ky) * 3 + kx];
    float w1 = cw[((n * 128 + ci0 + 1) * 3 + ky) * 3 + kx];
    __nv_bfloat16 v0, v1;
    if (half == 0) {
        v0 = __float2bfloat16(w0);
        v1 = __float2bfloat16(w1);
    } else {
        __nv_bfloat16 h0 = __float2bfloat16(w0);
        __nv_bfloat16 h1 = __float2bfloat16(w1);
        v0 = __float2bfloat16(w0 - __bfloat162float(h0));
        v1 = __float2bfloat16(w1 - __bfloat162float(h1));
    }
    uint32_t lo = (uint32_t)*(uint16_t*)&v0;
    uint32_t hi = (uint32_t)*(uint16_t*)&v1;
    g_Bfrag[i] = lo | (hi << 16);
}

// -------------------- pass 1: K,V proj + stats --------------------
__global__ void __launch_bounds__(256) pass1_kernel(
    const float* __restrict__ x1, const float* __restrict__ x2,
    const float* __restrict__ kb1, const float* __restrict__ vb1,
    const float* __restrict__ kb2, const float* __restrict__ vb2)
{
    __shared__ float sKt[64 * 68];
    __shared__ float sVt[64 * 68];
    __shared__ float sNp[4 * 64];
    __shared__ float sInv[64];

    const int tid = threadIdx.x;
    const int ty = tid >> 4, tx = tid & 15;
    const int b = blockIdx.y, br = blockIdx.z;
    const float* xb = (br ? x2 : x1) + (size_t)b * 64 * NPIX;
    const float* kb = br ? kb2 : kb1;
    const float* vb = br ? vb2 : vb1;
    const int pbase = blockIdx.x * 512;

    const float4* wk4 = (const float4*)(g_wkT + br * 4096);
    const float4* wv4 = (const float4*)(g_wvT + br * 4096);

    float2 kbv[2], vbv[2];
#pragma unroll
    for (int ip = 0; ip < 2; ip++) {
        kbv[ip] = __ldg(&((const float2*)kb)[ty * 2 + ip]);
        vbv[ip] = __ldg(&((const float2*)vb)[ty * 2 + ip]);
    }

    float2 macc[2][4];
    float2 ks2[2] = {{0.f, 0.f}, {0.f, 0.f}};
    float2 vs2[2] = {{0.f, 0.f}, {0.f, 0.f}};
#pragma unroll
    for (int ip = 0; ip < 2; ip++)
#pragma unroll
        for (int j = 0; j < 4; j++) macc[ip][j] = make_float2(0.f, 0.f);

    for (int t = 0; t < 8; t++) {
        const int p0 = pbase + t * 64;
#pragma unroll
        for (int r = 0; r < 16; r++) {
            int i = tid + r * 256;
            sKt[i] = xb[(size_t)(i >> 6) * NPIX + p0 + (i & 63)];
        }
        __syncthreads();

        float2 ka[2][4], va[2][4];
#pragma unroll
        for (int ip = 0; ip < 2; ip++)
#pragma unroll
            for (int j = 0; j < 4; j++) { ka[ip][j] = kbv[ip]; va[ip][j] = vbv[ip]; }

#pragma unroll 8
        for (int c = 0; c < 64; c++) {
            float4 xv = *(const float4*)&sKt[c * 64 + tx * 4];
            float2 xd[4] = {{xv.x, xv.x}, {xv.y, xv.y}, {xv.z, xv.z}, {xv.w, xv.w}};
            float4 wk = __ldg(&wk4[c * 16 + ty]);
            float4 wv = __ldg(&wv4[c * 16 + ty]);
            float2 wkp[2] = {{wk.x, wk.y}, {wk.z, wk.w}};
            float2 wvp[2] = {{wv.x, wv.y}, {wv.z, wv.w}};
#pragma unroll
            for (int ip = 0; ip < 2; ip++)
#pragma unroll
                for (int j = 0; j < 4; j++) {
                    ka[ip][j] = ffma2(wkp[ip], xd[j], ka[ip][j]);
                    va[ip][j] = ffma2(wvp[ip], xd[j], va[ip][j]);
                }
        }
        __syncthreads();

#pragma unroll
        for (int j = 0; j < 4; j++)
#pragma unroll
            for (int ip = 0; ip < 2; ip++) {
                *(float2*)&sKt[(tx * 4 + j) * 68 + ty * 4 + ip * 2] = ka[ip][j];
                *(float2*)&sVt[(tx * 4 + j) * 68 + ty * 4 + ip * 2] = va[ip][j];
            }
        __syncthreads();

        {
            int p = tid & 63, q = tid >> 6;
            const float2* row = (const float2*)(sKt + p * 68 + q * 16);
            float2 s2 = make_float2(0.f, 0.f);
#pragma unroll
            for (int mm = 0; mm < 8; mm++) s2 = ffma2(row[mm], row[mm], s2);
            sNp[q * 64 + p] = s2.x + s2.y;
        }
        __syncthreads();
        if (tid < 64)
            sInv[tid] = rsqrtf(sNp[tid] + sNp[64 + tid] + sNp[128 + tid] + sNp[192 + tid]);
        __syncthreads();

#pragma unroll 4
        for (int p = 0; p < 64; p++) {
            float inv = sInv[p];
            float2 invd = {inv, inv};
            float4 a4 = *(const float4*)&sKt[p * 68 + ty * 4];
            float2 a2[2] = {mul2(make_float2(a4.x, a4.y), invd),
                            mul2(make_float2(a4.z, a4.w), invd)};
            float4 b4 = *(const float4*)&sVt[p * 68 + tx * 4];
            float2 bd[4] = {{b4.x, b4.x}, {b4.y, b4.y}, {b4.z, b4.z}, {b4.w, b4.w}};
#pragma unroll
            for (int ip = 0; ip < 2; ip++)
#pragma unroll
                for (int j = 0; j < 4; j++) macc[ip][j] = ffma2(a2[ip], bd[j], macc[ip][j]);
            if (tx == 0) {
                ks2[0] = add2(ks2[0], a2[0]);
                ks2[1] = add2(ks2[1], a2[1]);
            }
            if (ty == 0) {
                vs2[0] = add2(vs2[0], make_float2(b4.x, b4.y));
                vs2[1] = add2(vs2[1], make_float2(b4.z, b4.w));
            }
        }
        __syncthreads();
    }

    float* mat = g_mat + ((size_t)br * NB + b) * 4096;
#pragma unroll
    for (int ip = 0; ip < 2; ip++)
#pragma unroll
        for (int j = 0; j < 4; j++) {
            atomicAdd(&mat[(ty * 4 + ip * 2) * 64 + tx * 4 + j], macc[ip][j].x);
            atomicAdd(&mat[(ty * 4 + ip * 2 + 1) * 64 + tx * 4 + j], macc[ip][j].y);
        }
    if (tx == 0) {
        float* kp = g_ksum + ((size_t)br * NB + b) * 64;
#pragma unroll
        for (int ip = 0; ip < 2; ip++) {
            atomicAdd(&kp[ty * 4 + ip * 2], ks2[ip].x);
            atomicAdd(&kp[ty * 4 + ip * 2 + 1], ks2[ip].y);
        }
    }
    if (ty == 0) {
        float* vp = g_vsum + ((size_t)br * NB + b) * 64;
        atomicAdd(&vp[tx * 4 + 0], vs2[0].x);
        atomicAdd(&vp[tx * 4 + 1], vs2[0].y);
        atomicAdd(&vp[tx * 4 + 2], vs2[1].x);
        atomicAdd(&vp[tx * 4 + 3], vs2[1].y);
    }
}

// -------------------- mid --------------------
__global__ void __launch_bounds__(256) mid_kernel(const float* __restrict__ rw1,
                                                  const float* __restrict__ rw2)
{
    __shared__ float sMat[4096];
    __shared__ float sRw[4096];
    const int tid = threadIdx.x;
    const int b = blockIdx.x, br = blockIdx.y;
    const float* rw = br ? rw2 : rw1;
    const float* mat = g_mat + ((size_t)br * NB + b) * 4096;
#pragma unroll
    for (int r = 0; r < 16; r++) {
        int i = tid + r * 256;
        sMat[i] = mat[i];
        sRw[i] = rw[i];
    }
    __syncthreads();
    const int ty = tid >> 4, tx = tid & 15;
    float acc[4][4];
#pragma unroll
    for (int i = 0; i < 4; i++)
#pragma unroll
        for (int j = 0; j < 4; j++) acc[i][j] = 0.f;
#pragma unroll 4
    for (int c = 0; c < 64; c++) {
        float a[4], w[4];
#pragma unroll
        for (int i = 0; i < 4; i++) a[i] = sMat[(ty * 4 + i) * 64 + c];
#pragma unroll
        for (int j = 0; j < 4; j++) w[j] = sRw[(tx * 4 + j) * 64 + c];
#pragma unroll
        for (int i = 0; i < 4; i++)
#pragma unroll
            for (int j = 0; j < 4; j++) acc[i][j] += a[i] * w[j];
    }
    float2* RMt = (float2*)(g_RMt2 + ((size_t)br * NB + b) * 8192);
#pragma unroll
    for (int i = 0; i < 4; i++)
#pragma unroll
        for (int j = 0; j < 4; j++)
            RMt[(ty * 4 + i) * 64 + tx * 4 + j] = make_float2(acc[i][j], acc[i][j]);
    if (tid < 64) {
        const float* vsump = g_vsum + ((size_t)br * NB + b) * 64;
        float s = 0.f;
        for (int c = 0; c < 64; c++) s += sRw[tid * 64 + c] * vsump[c];
        g_rv[((size_t)br * NB + b) * 64 + tid] = s;
        g_ksumE[((size_t)br * NB + b) * 64 + tid] =
            g_ksum[((size_t)br * NB + b) * 64 + tid] + 1e-6f;
    }
}

// -------------------- pass 2: Q proj + output -> NHWC bf16 hi/lo --------------------
__global__ void __launch_bounds__(256) pass2_kernel(
    const float* __restrict__ x1, const float* __restrict__ x2,
    const float* __restrict__ qb1, const float* __restrict__ rb1,
    const float* __restrict__ qb2, const float* __restrict__ rb2)
{
    __shared__ float sQ[64 * 64];
    __shared__ float sNp[256], sDp[256];
    __shared__ float sInv[64], sDen[64];

    const int tid = threadIdx.x;
    const int ty = tid >> 4, tx = tid & 15;
    const int b = blockIdx.y, br = blockIdx.z;
    const float* xb = (br ? x2 : x1) + (size_t)b * 64 * NPIX;
    const float* qb = br ? qb2 : qb1;
    const float* rb = br ? rb2 : rb1;
    const int pbase = blockIdx.x * 512;

    const float4* wq4 = (const float4*)(g_wqT2 + br * 8192);
    const float4* rm4 = (const float4*)(g_RMt2 + ((size_t)br * NB + b) * 8192);
    const float* ksE = g_ksumE + ((size_t)br * NB + b) * 64;
    const float* rvp = g_rv + ((size_t)br * NB + b) * 64;

    float2 qbv[4], rv2[4], rb2v[4];
#pragma unroll
    for (int i = 0; i < 4; i++) {
        float q = __ldg(&qb[ty * 4 + i]);
        float rv = __ldg(&rvp[ty * 4 + i]);
        float rbv = __ldg(&rb[ty * 4 + i]);
        qbv[i] = make_float2(q, q);
        rv2[i] = make_float2(rv, rv);
        rb2v[i] = make_float2(rbv, rbv);
    }

    for (int t = 0; t < 8; t++) {
        const int p0 = pbase + t * 64;
#pragma unroll
        for (int r = 0; r < 16; r++) {
            int i = tid + r * 256;
            sQ[i] = xb[(size_t)(i >> 6) * NPIX + p0 + (i & 63)];
        }
        __syncthreads();

        float2 qa[4][2];
#pragma unroll
        for (int i = 0; i < 4; i++) { qa[i][0] = qbv[i]; qa[i][1] = qbv[i]; }

#pragma unroll 8
        for (int c = 0; c < 64; c++) {
            float4 xv = *(const float4*)&sQ[c * 64 + tx * 4];
            float2 xp[2] = {{xv.x, xv.y}, {xv.z, xv.w}};
            float4 w0 = __ldg(&wq4[c * 32 + ty * 2]);
            float4 w1 = __ldg(&wq4[c * 32 + ty * 2 + 1]);
            float2 wd[4] = {{w0.x, w0.y}, {w0.z, w0.w}, {w1.x, w1.y}, {w1.z, w1.w}};
#pragma unroll
            for (int i = 0; i < 4; i++)
#pragma unroll
                for (int jp = 0; jp < 2; jp++) qa[i][jp] = ffma2(wd[i], xp[jp], qa[i][jp]);
        }
        __syncthreads();

#pragma unroll
        for (int i = 0; i < 4; i++)
#pragma unroll
            for (int jp = 0; jp < 2; jp++)
                *(float2*)&sQ[(ty * 4 + i) * 64 + tx * 4 + jp * 2] = qa[i][jp];
        __syncthreads();

        {
            int p = tid & 63, q = tid >> 6;
            float s = 0.f, d = 0.f;
#pragma unroll
            for (int mm = 0; mm < 16; mm++) {
                int m = q * 16 + mm;
                float v = sQ[m * 64 + p];
                s = fmaf(v, v, s);
                d = fmaf(v, __ldg(&ksE[m]), d);
            }
            sNp[q * 64 + p] = s;
            sDp[q * 64 + p] = d;
        }
        __syncthreads();
        if (tid < 64) {
            float s = sNp[tid] + sNp[64 + tid] + sNp[128 + tid] + sNp[192 + tid];
            float d = sDp[tid] + sDp[64 + tid] + sDp[128 + tid] + sDp[192 + tid];
            float inv = rsqrtf(s);
            sInv[tid] = inv;
            sDen[tid] = 1.f / (65536.f + inv * d);
        }
        __syncthreads();

        float2 acc[4][2];
#pragma unroll
        for (int i = 0; i < 4; i++) { acc[i][0] = make_float2(0.f, 0.f); acc[i][1] = make_float2(0.f, 0.f); }

#pragma unroll 8
        for (int m = 0; m < 64; m++) {
            float4 bq = *(const float4*)&sQ[m * 64 + tx * 4];
            float2 bp[2] = {{bq.x, bq.y}, {bq.z, bq.w}};
            float4 w0 = __ldg(&rm4[m * 32 + ty * 2]);
            float4 w1 = __ldg(&rm4[m * 32 + ty * 2 + 1]);
            float2 wd[4] = {{w0.x, w0.y}, {w0.z, w0.w}, {w1.x, w1.y}, {w1.z, w1.w}};
#pragma unroll
            for (int i = 0; i < 4; i++)
#pragma unroll
                for (int jp = 0; jp < 2; jp++) acc[i][jp] = ffma2(wd[i], bp[jp], acc[i][jp]);
        }

        float2 iv[2] = {*(const float2*)&sInv[tx * 4], *(const float2*)&sInv[tx * 4 + 2]};
        float2 dn[2] = {*(const float2*)&sDen[tx * 4], *(const float2*)&sDen[tx * 4 + 2]};
        float ov[4][4];
#pragma unroll
        for (int i = 0; i < 4; i++) {
            float2 t0 = ffma2(iv[0], acc[i][0], rv2[i]);
            float2 t1 = ffma2(iv[1], acc[i][1], rv2[i]);
            t0 = ffma2(dn[0], t0, rb2v[i]);
            t1 = ffma2(dn[1], t1, rb2v[i]);
            ov[i][0] = t0.x; ov[i][1] = t0.y; ov[i][2] = t1.x; ov[i][3] = t1.y;
        }
        __syncthreads();   // everyone done reading sQ

        // stage bf16 hi/lo into sQ: hi plane [px][oc] at 0, lo plane at +4096 (bf16 elems)
        __nv_bfloat16* sB = (__nv_bfloat16*)sQ;
#pragma unroll
        for (int i = 0; i < 4; i++)
#pragma unroll
            for (int j = 0; j < 4; j++) {
                float v = ov[i][j];
                __nv_bfloat16 h = __float2bfloat16(v);
                __nv_bfloat16 l = __float2bfloat16(v - __bfloat162float(h));
                sB[(tx * 4 + j) * 64 + ty * 4 + i] = h;
                sB[4096 + (tx * 4 + j) * 64 + ty * 4 + i] = l;
            }
        __syncthreads();

        // cooperative coalesced store to NHWC planes
        for (int u = tid; u < 1024; u += 256) {
            int plane = u >> 9, chunk = u & 511;
            int pxl = chunk >> 3, qq = chunk & 7;
            uint4 val = ((const uint4*)sB)[plane * 512 + chunk];
            __nv_bfloat16* dst = plane ? g_lo : g_hi;
            *(uint4*)&dst[((size_t)(b * NPIX + p0 + pxl)) * 128 + br * 64 + qq * 8] = val;
        }
        __syncthreads();
    }
}

// -------------------- conv: mma.sync bf16-split implicit GEMM --------------------
// grid (2, 256, 8), 256 thr = 8 warps. Block tile: 128 px x 64 oc, one y row.
// Warp w: px rows [x0 + w*16, +16), all 64 oc (8 n-tiles of 8).
// smem strip: [130 px rows][128 ci] bf16, row stride 272 B, hi at 0, lo at +35360.
#define STRIP_STRIDE 272
#define STRIP_BYTES (130 * STRIP_STRIDE)           // 35360
#define CONV_SMEM (2 * STRIP_BYTES)                // 70720

__global__ void __launch_bounds__(256) conv_kernel(const float* __restrict__ cbias,
                                                   float* __restrict__ out)
{
    extern __shared__ __align__(16) char dsm[];
    char* sHi = dsm;
    char* sLo = dsm + STRIP_BYTES;
    float* sOut = (float*)dsm;   // reused after compute

    const int tid = threadIdx.x;
    const int lane = tid & 31, wt = tid >> 5;
    const int x0 = blockIdx.x * 128, y = blockIdx.y, b = blockIdx.z;

    float acc[8][4];
#pragma unroll
    for (int nt = 0; nt < 8; nt++)
#pragma unroll
        for (int j = 0; j < 4; j++) acc[nt][j] = 0.f;

    const int g = lane >> 2, tg = lane & 3;   // groupID, thread-in-group
    const uint32_t aOff = (wt * 16 + g) * STRIP_STRIDE + tg * 4;

    for (int ky = 0; ky < 3; ky++) {
        int yy = y + ky - 1;
        bool yok = (yy >= 0 && yy < IMG_H);
        __syncthreads();   // strip reuse barrier
        if (yok) {
            size_t rowbase = ((size_t)b * NPIX + (size_t)yy * IMG_W) * 128;
            for (int i = tid; i < 130 * 16; i += 256) {
                int row = i >> 4, ch = i & 15;
                int px = x0 + row - 1;
                uint4 vh = make_uint4(0u, 0u, 0u, 0u);
                uint4 vl = make_uint4(0u, 0u, 0u, 0u);
                if (px >= 0 && px < IMG_W) {
                    size_t gi = rowbase + (size_t)px * 128 + ch * 8;
                    vh = *(const uint4*)&g_hi[gi];
                    vl = *(const uint4*)&g_lo[gi];
                }
                *(uint4*)(sHi + row * STRIP_STRIDE + ch * 16) = vh;
                *(uint4*)(sLo + row * STRIP_STRIDE + ch * 16) = vl;
            }
        }
        __syncthreads();
        if (!yok) continue;

#pragma unroll 1
        for (int kc = 0; kc < 24; kc++) {
            int kx = kc >> 3, cc8 = kc & 7;
            uint32_t r0 = aOff + kx * STRIP_STRIDE + cc8 * 32;
            uint32_t ah0 = *(const uint32_t*)(sHi + r0);
            uint32_t ah1 = *(const uint32_t*)(sHi + r0 + 8 * STRIP_STRIDE);
            uint32_t ah2 = *(const uint32_t*)(sHi + r0 + 16);
            uint32_t ah3 = *(const uint32_t*)(sHi + r0 + 8 * STRIP_STRIDE + 16);
            uint32_t al0 = *(const uint32_t*)(sLo + r0);
            uint32_t al1 = *(const uint32_t*)(sLo + r0 + 8 * STRIP_STRIDE);
            uint32_t al2 = *(const uint32_t*)(sLo + r0 + 16);
            uint32_t al3 = *(const uint32_t*)(sLo + r0 + 8 * STRIP_STRIDE + 16);

            const uint4* bfH = (const uint4*)(g_Bfrag + (((ky * 24 + kc) * 2 + 0) * 32 + lane) * 16);
            const uint4* bfL = (const uint4*)(g_Bfrag + (((ky * 24 + kc) * 2 + 1) * 32 + lane) * 16);
            uint4 bh[4], bl[4];
#pragma unroll
            for (int q = 0; q < 4; q++) { bh[q] = __ldg(&bfH[q]); bl[q] = __ldg(&bfL[q]); }

#pragma unroll
            for (int nt = 0; nt < 8; nt++) {
                uint32_t bh0 = (nt & 1) ? bh[nt >> 1].z : bh[nt >> 1].x;
                uint32_t bh1 = (nt & 1) ? bh[nt >> 1].w : bh[nt >> 1].y;
                uint32_t bl0 = (nt & 1) ? bl[nt >> 1].z : bl[nt >> 1].x;
                uint32_t bl1 = (nt & 1) ? bl[nt >> 1].w : bl[nt >> 1].y;
                mma_bf16(acc[nt], ah0, ah1, ah2, ah3, bh0, bh1);   // Ah*Bh
                mma_bf16(acc[nt], ah0, ah1, ah2, ah3, bl0, bl1);   // Ah*Bl
                mma_bf16(acc[nt], al0, al1, al2, al3, bh0, bh1);   // Al*Bh
            }
        }
    }

    __syncthreads();
    // transpose to [oc][px] in smem (pad 132), then coalesced NCHW store
#pragma unroll
    for (int nt = 0; nt < 8; nt++)
#pragma unroll
        for (int h = 0; h < 2; h++)
#pragma unroll
            for (int j = 0; j < 2; j++) {
                int o = nt * 8 + tg * 2 + j;
                int px = wt * 16 + g + h * 8;
                sOut[o * 132 + px] = acc[nt][h * 2 + j];
            }
    __syncthreads();
    for (int i = tid; i < 64 * 32; i += 256) {
        int o = i >> 5, ch = i & 31;
        float4 v = *(const float4*)&sOut[o * 132 + ch * 4];
        float bias = __ldg(&cbias[o]);
        v.x += bias; v.y += bias; v.z += bias; v.w += bias;
        *(float4*)&out[((size_t)(b * 64 + o)) * NPIX + (size_t)y * IMG_W + x0 + ch * 4] = v;
    }
}

// -------------------- launch --------------------
extern "C" void kernel_launch(void* const* d_in, const int* in_sizes, int n_in,
                              void* d_out, int out_size)
{
    (void)in_sizes; (void)n_in; (void)out_size;
    const float* t1  = (const float*)d_in[0];
    const float* t2  = (const float*)d_in[1];
    const float* q1w = (const float*)d_in[2];  const float* q1b = (const float*)d_in[3];
    const float* k1w = (const float*)d_in[4];  const float* k1b = (const float*)d_in[5];
    const float* v1w = (const float*)d_in[6];  const float* v1b = (const float*)d_in[7];
    const float* r1w = (const float*)d_in[8];  const float* r1b = (const float*)d_in[9];
    const float* q2w = (const float*)d_in[10]; const float* q2b = (const float*)d_in[11];
    const float* k2w = (const float*)d_in[12]; const float* k2b = (const float*)d_in[13];
    const float* v2w = (const float*)d_in[14]; const float* v2b = (const float*)d_in[15];
    const float* r2w = (const float*)d_in[16]; const float* r2b = (const float*)d_in[17];
    const float* cw  = (const float*)d_in[18]; const float* cb  = (const float*)d_in[19];

    cudaFuncSetAttribute(conv_kernel, cudaFuncAttributeMaxDynamicSharedMemorySize, CONV_SMEM);

    prepA_kernel<<<352, 256>>>(q1w, k1w, v1w, q2w, k2w, v2w);   // launch 0
    prepB_kernel<<<288, 256>>>(cw);                             // launch 1
    dim3 g1(128, 8, 2);
    pass1_kernel<<<g1, 256>>>(t1, t2, k1b, v1b, k2b, v2b);      // launch 2
    dim3 gm(8, 2);
    mid_kernel<<<gm, 256>>>(r1w, r2w);                          // launch 3
    pass2_kernel<<<g1, 256>>>(t1, t2, q1b, r1b, q2b, r2b);      // launch 4
    dim3 gc(2, 256, 8);
    conv_kernel<<<gc, 256, CONV_SMEM>>>(cb, (float*)d_out);     // launch 5 (ncu captures this)
}

// round 6
// speedup vs baseline: 1.4408x; 1.1636x over previous
#include <cuda_runtime.h>
#include <cuda_bf16.h>
#include <cstdint>

#define NPIX 65536
#define IMG_H 256
#define IMG_W 256
#define NB 8

// ---- device scratch ----
__device__ __nv_bfloat16 g_hi[NB * NPIX * 128];   // NHWC [b][y][x][ci], hi plane
__device__ __nv_bfloat16 g_lo[NB * NPIX * 128];   // lo plane
__device__ uint32_t g_Bfrag[3 * 24 * 2 * 32 * 16]; // conv weight mma frags
__device__ uint32_t g_Wqfrag[2 * 2 * 4 * 32 * 16]; // [br][half][kc][lane][ntj]
__device__ uint32_t g_RMfrag[16 * 2 * 4 * 32 * 16];// [(br*8+b)][half][kc][lane][ntj]
__device__ float g_mat[2 * NB * 64 * 64];
__device__ float g_ksum[2 * NB * 64];
__device__ float g_vsum[2 * NB * 64];
__device__ float g_rv[2 * NB * 64];
__device__ float g_ksumE[2 * NB * 64];
__device__ float g_wkT[2 * 64 * 64];
__device__ float g_wvT[2 * 64 * 64];

// ---- packed f32x2 helpers ----
__device__ __forceinline__ float2 ffma2(float2 a, float2 b, float2 c) {
    float2 d;
    asm("fma.rn.f32x2 %0, %1, %2, %3;"
        : "=l"(*(unsigned long long*)&d)
        : "l"(*(unsigned long long*)&a), "l"(*(unsigned long long*)&b),
          "l"(*(unsigned long long*)&c));
    return d;
}
__device__ __forceinline__ float2 mul2(float2 a, float2 b) {
    float2 d;
    asm("mul.rn.f32x2 %0, %1, %2;"
        : "=l"(*(unsigned long long*)&d)
        : "l"(*(unsigned long long*)&a), "l"(*(unsigned long long*)&b));
    return d;
}
__device__ __forceinline__ float2 add2(float2 a, float2 b) {
    float2 d;
    asm("add.rn.f32x2 %0, %1, %2;"
        : "=l"(*(unsigned long long*)&d)
        : "l"(*(unsigned long long*)&a), "l"(*(unsigned long long*)&b));
    return d;
}

// ---- mma.sync bf16 helper (m16n8k16, f32 accum) ----
__device__ __forceinline__ void mma_bf16(float* d,
                                         uint32_t a0, uint32_t a1, uint32_t a2, uint32_t a3,
                                         uint32_t b0, uint32_t b1) {
    asm volatile(
        "mma.sync.aligned.m16n8k16.row.col.f32.bf16.bf16.f32 "
        "{%0,%1,%2,%3}, {%4,%5,%6,%7}, {%8,%9}, {%0,%1,%2,%3};"
        : "+f"(d[0]), "+f"(d[1]), "+f"(d[2]), "+f"(d[3])
        : "r"(a0), "r"(a1), "r"(a2), "r"(a3), "r"(b0), "r"(b1));
}

// pack two floats -> bf16x2 (hi pair) and residual bf16x2 (lo pair)
__device__ __forceinline__ void splitbf(float a, float b, uint32_t& h, uint32_t& l) {
    __nv_bfloat16 ha = __float2bfloat16(a), hb = __float2bfloat16(b);
    __nv_bfloat162 hh; hh.x = ha; hh.y = hb;
    h = *(uint32_t*)&hh;
    __nv_bfloat162 ll = __floats2bfloat162_rn(a - __bfloat162float(ha),
                                              b - __bfloat162float(hb));
    l = *(uint32_t*)&ll;
}
__device__ __forceinline__ uint32_t packbf_hi_lo(float a, float b, int half) {
    if (half == 0) {
        __nv_bfloat162 hh; hh.x = __float2bfloat16(a); hh.y = __float2bfloat16(b);
        return *(uint32_t*)&hh;
    }
    __nv_bfloat16 ha = __float2bfloat16(a), hb = __float2bfloat16(b);
    __nv_bfloat162 ll = __floats2bfloat162_rn(a - __bfloat162float(ha),
                                              b - __bfloat162float(hb));
    return *(uint32_t*)&ll;
}

// -------------------- prep (single kernel) --------------------
// blocks 0..255: zero stats; 256..319: wk/wv transposes;
// 320..607: conv weight frags; 608..639: Wq frags.
__global__ void __launch_bounds__(256) prep_kernel(
    const float* __restrict__ q1w, const float* __restrict__ k1w, const float* __restrict__ v1w,
    const float* __restrict__ q2w, const float* __restrict__ k2w, const float* __restrict__ v2w,
    const float* __restrict__ cw)
{
    int nb = blockIdx.x, tid = threadIdx.x;
    if (nb < 256) {
        int idx = nb * 256 + tid;
        g_mat[idx] = 0.f;
        if (idx < 2 * NB * 64) { g_ksum[idx] = 0.f; g_vsum[idx] = 0.f; }
        return;
    }
    if (nb < 320) {
        int t = nb - 256;                // 0..63
        int table = t >> 4, sub = t & 15;
        int idx = sub * 256 + tid;       // 0..4095
        int o = idx >> 6, c = idx & 63;
        if (table == 0) g_wkT[c * 64 + o] = k1w[idx];
        else if (table == 1) g_wvT[c * 64 + o] = v1w[idx];
        else if (table == 2) g_wkT[4096 + c * 64 + o] = k2w[idx];
        else g_wvT[4096 + c * 64 + o] = v2w[idx];
        return;
    }
    if (nb < 608) {
        int i = (nb - 320) * 256 + tid;  // 0..73727
        int ky = i / 24576;
        int rem = i % 24576;
        int kc = rem / 1024;
        int rem2 = rem % 1024;
        int half = rem2 / 512;
        int rem3 = rem2 % 512;
        int lane = rem3 / 16;
        int r4 = rem3 % 16;
        int nt = r4 >> 1, j = r4 & 1;
        int kx = kc >> 3, cc8 = kc & 7;
        int n = nt * 8 + (lane >> 2);
        int ci0 = cc8 * 16 + (lane & 3) * 2 + j * 8;
        float w0 = cw[((n * 128 + ci0) * 3 + ky) * 3 + kx];
        float w1 = cw[((n * 128 + ci0 + 1) * 3 + ky) * 3 + kx];
        g_Bfrag[i] = packbf_hi_lo(w0, w1, half);
        return;
    }
    {
        int i = (nb - 608) * 256 + tid;  // 0..8191
        int br = i >> 12;
        int r = i & 4095;
        int half = r >> 11;
        int kc = (r >> 9) & 3;
        int lane = (r >> 4) & 31;
        int ntj = r & 15;
        int nt = ntj >> 1, j = ntj & 1;
        int o = nt * 8 + (lane >> 2);
        int c0 = kc * 16 + (lane & 3) * 2 + j * 8;
        const float* qw = br ? q2w : q1w;
        float w0 = qw[o * 64 + c0];
        float w1 = qw[o * 64 + c0 + 1];
        g_Wqfrag[i] = packbf_hi_lo(w0, w1, half);
    }
}

// -------------------- pass 1: K,V proj + stats (unchanged) --------------------
__global__ void __launch_bounds__(256) pass1_kernel(
    const float* __restrict__ x1, const float* __restrict__ x2,
    const float* __restrict__ kb1, const float* __restrict__ vb1,
    const float* __restrict__ kb2, const float* __restrict__ vb2)
{
    __shared__ float sKt[64 * 68];
    __shared__ float sVt[64 * 68];
    __shared__ float sNp[4 * 64];
    __shared__ float sInv[64];

    const int tid = threadIdx.x;
    const int ty = tid >> 4, tx = tid & 15;
    const int b = blockIdx.y, br = blockIdx.z;
    const float* xb = (br ? x2 : x1) + (size_t)b * 64 * NPIX;
    const float* kb = br ? kb2 : kb1;
    const float* vb = br ? vb2 : vb1;
    const int pbase = blockIdx.x * 512;

    const float4* wk4 = (const float4*)(g_wkT + br * 4096);
    const float4* wv4 = (const float4*)(g_wvT + br * 4096);

    float2 kbv[2], vbv[2];
#pragma unroll
    for (int ip = 0; ip < 2; ip++) {
        kbv[ip] = __ldg(&((const float2*)kb)[ty * 2 + ip]);
        vbv[ip] = __ldg(&((const float2*)vb)[ty * 2 + ip]);
    }

    float2 macc[2][4];
    float2 ks2[2] = {{0.f, 0.f}, {0.f, 0.f}};
    float2 vs2[2] = {{0.f, 0.f}, {0.f, 0.f}};
#pragma unroll
    for (int ip = 0; ip < 2; ip++)
#pragma unroll
        for (int j = 0; j < 4; j++) macc[ip][j] = make_float2(0.f, 0.f);

    for (int t = 0; t < 8; t++) {
        const int p0 = pbase + t * 64;
#pragma unroll
        for (int r = 0; r < 16; r++) {
            int i = tid + r * 256;
            sKt[i] = xb[(size_t)(i >> 6) * NPIX + p0 + (i & 63)];
        }
        __syncthreads();

        float2 ka[2][4], va[2][4];
#pragma unroll
        for (int ip = 0; ip < 2; ip++)
#pragma unroll
            for (int j = 0; j < 4; j++) { ka[ip][j] = kbv[ip]; va[ip][j] = vbv[ip]; }

#pragma unroll 8
        for (int c = 0; c < 64; c++) {
            float4 xv = *(const float4*)&sKt[c * 64 + tx * 4];
            float2 xd[4] = {{xv.x, xv.x}, {xv.y, xv.y}, {xv.z, xv.z}, {xv.w, xv.w}};
            float4 wk = __ldg(&wk4[c * 16 + ty]);
            float4 wv = __ldg(&wv4[c * 16 + ty]);
            float2 wkp[2] = {{wk.x, wk.y}, {wk.z, wk.w}};
            float2 wvp[2] = {{wv.x, wv.y}, {wv.z, wv.w}};
#pragma unroll
            for (int ip = 0; ip < 2; ip++)
#pragma unroll
                for (int j = 0; j < 4; j++) {
                    ka[ip][j] = ffma2(wkp[ip], xd[j], ka[ip][j]);
                    va[ip][j] = ffma2(wvp[ip], xd[j], va[ip][j]);
                }
        }
        __syncthreads();

#pragma unroll
        for (int j = 0; j < 4; j++)
#pragma unroll
            for (int ip = 0; ip < 2; ip++) {
                *(float2*)&sKt[(tx * 4 + j) * 68 + ty * 4 + ip * 2] = ka[ip][j];
                *(float2*)&sVt[(tx * 4 + j) * 68 + ty * 4 + ip * 2] = va[ip][j];
            }
        __syncthreads();

        {
            int p = tid & 63, q = tid >> 6;
            const float2* row = (const float2*)(sKt + p * 68 + q * 16);
            float2 s2 = make_float2(0.f, 0.f);
#pragma unroll
            for (int mm = 0; mm < 8; mm++) s2 = ffma2(row[mm], row[mm], s2);
            sNp[q * 64 + p] = s2.x + s2.y;
        }
        __syncthreads();
        if (tid < 64)
            sInv[tid] = rsqrtf(sNp[tid] + sNp[64 + tid] + sNp[128 + tid] + sNp[192 + tid]);
        __syncthreads();

#pragma unroll 4
        for (int p = 0; p < 64; p++) {
            float inv = sInv[p];
            float2 invd = {inv, inv};
            float4 a4 = *(const float4*)&sKt[p * 68 + ty * 4];
            float2 a2[2] = {mul2(make_float2(a4.x, a4.y), invd),
                            mul2(make_float2(a4.z, a4.w), invd)};
            float4 b4 = *(const float4*)&sVt[p * 68 + tx * 4];
            float2 bd[4] = {{b4.x, b4.x}, {b4.y, b4.y}, {b4.z, b4.z}, {b4.w, b4.w}};
#pragma unroll
            for (int ip = 0; ip < 2; ip++)
#pragma unroll
                for (int j = 0; j < 4; j++) macc[ip][j] = ffma2(a2[ip], bd[j], macc[ip][j]);
            if (tx == 0) {
                ks2[0] = add2(ks2[0], a2[0]);
                ks2[1] = add2(ks2[1], a2[1]);
            }
            if (ty == 0) {
                vs2[0] = add2(vs2[0], make_float2(b4.x, b4.y));
                vs2[1] = add2(vs2[1], make_float2(b4.z, b4.w));
            }
        }
        __syncthreads();
    }

    float* mat = g_mat + ((size_t)br * NB + b) * 4096;
#pragma unroll
    for (int ip = 0; ip < 2; ip++)
#pragma unroll
        for (int j = 0; j < 4; j++) {
            atomicAdd(&mat[(ty * 4 + ip * 2) * 64 + tx * 4 + j], macc[ip][j].x);
            atomicAdd(&mat[(ty * 4 + ip * 2 + 1) * 64 + tx * 4 + j], macc[ip][j].y);
        }
    if (tx == 0) {
        float* kp = g_ksum + ((size_t)br * NB + b) * 64;
#pragma unroll
        for (int ip = 0; ip < 2; ip++) {
            atomicAdd(&kp[ty * 4 + ip * 2], ks2[ip].x);
            atomicAdd(&kp[ty * 4 + ip * 2 + 1], ks2[ip].y);
        }
    }
    if (ty == 0) {
        float* vp = g_vsum + ((size_t)br * NB + b) * 64;
        atomicAdd(&vp[tx * 4 + 0], vs2[0].x);
        atomicAdd(&vp[tx * 4 + 1], vs2[0].y);
        atomicAdd(&vp[tx * 4 + 2], vs2[1].x);
        atomicAdd(&vp[tx * 4 + 3], vs2[1].y);
    }
}

// -------------------- mid: RM frags, rv, ksumE --------------------
__global__ void __launch_bounds__(256) mid_kernel(const float* __restrict__ rw1,
                                                  const float* __restrict__ rw2)
{
    __shared__ float sMat[4096];
    __shared__ float sRw[4096];
    const int tid = threadIdx.x;
    const int b = blockIdx.x, br = blockIdx.y;
    const float* rw = br ? rw2 : rw1;
    const float* mat = g_mat + ((size_t)br * NB + b) * 4096;
#pragma unroll
    for (int r = 0; r < 16; r++) {
        int i = tid + r * 256;
        sMat[i] = mat[i];
        sRw[i] = rw[i];
    }
    __syncthreads();
    const int ty = tid >> 4, tx = tid & 15;
    float acc[4][4];
#pragma unroll
    for (int i = 0; i < 4; i++)
#pragma unroll
        for (int j = 0; j < 4; j++) acc[i][j] = 0.f;
#pragma unroll 4
    for (int c = 0; c < 64; c++) {
        float a[4], w[4];
#pragma unroll
        for (int i = 0; i < 4; i++) a[i] = sMat[(ty * 4 + i) * 64 + c];
#pragma unroll
        for (int j = 0; j < 4; j++) w[j] = sRw[(tx * 4 + j) * 64 + c];
#pragma unroll
        for (int i = 0; i < 4; i++)
#pragma unroll
            for (int j = 0; j < 4; j++) acc[i][j] += a[i] * w[j];
    }
    // rv / ksumE (uses sRw before overwrite)
    if (tid < 64) {
        const float* vsump = g_vsum + ((size_t)br * NB + b) * 64;
        float s = 0.f;
        for (int c = 0; c < 64; c++) s += sRw[tid * 64 + c] * vsump[c];
        g_rv[((size_t)br * NB + b) * 64 + tid] = s;
        g_ksumE[((size_t)br * NB + b) * 64 + tid] =
            g_ksum[((size_t)br * NB + b) * 64 + tid] + 1e-6f;
    }
    __syncthreads();
    // store RM plain [o][m]: acc[i][j] = RM[o=tx*4+j][m=ty*4+i]
#pragma unroll
    for (int i = 0; i < 4; i++)
#pragma unroll
        for (int j = 0; j < 4; j++)
            sMat[(tx * 4 + j) * 64 + (ty * 4 + i)] = acc[i][j];
    __syncthreads();
    // build mma B fragments
    uint32_t* dst = g_RMfrag + (size_t)(br * 8 + b) * 4096;
    for (int t = tid; t < 4096; t += 256) {
        int half = t >> 11;
        int lane = (t >> 4) & 31;
        int ntj = t & 15;
        int nt = ntj >> 1, j = ntj & 1;
        int kc = (t >> 9) & 3;
        int o = nt * 8 + (lane >> 2);
        int m0 = kc * 16 + (lane & 3) * 2 + j * 8;
        float w0 = sMat[o * 64 + m0];
        float w1 = sMat[o * 64 + m0 + 1];
        dst[t] = packbf_hi_lo(w0, w1, half);
    }
}

// -------------------- pass 2: mma.sync Q proj + RM*Qn -> NHWC bf16 hi/lo ----------
// grid (256, 8, 2), 256 thr = 8 warps. Tile: 256 px x 64.
// dynamic smem 66560 B: phase A x fp32 [c:64][stride 260]; then Q fp32 [px:256][65];
// then output bf16 planes [256][64] x2.
#define P2_SMEM 66560

__global__ void __launch_bounds__(256) pass2_kernel(
    const float* __restrict__ x1, const float* __restrict__ x2,
    const float* __restrict__ qb1, const float* __restrict__ rb1,
    const float* __restrict__ qb2, const float* __restrict__ rb2)
{
    extern __shared__ __align__(16) float dsm[];
    __shared__ float sInv[256], sDen[256], sKsE[64];

    const int tid = threadIdx.x;
    const int lane = tid & 31, wt = tid >> 5;
    const int g = lane >> 2, tg = lane & 3;
    const int b = blockIdx.y, br = blockIdx.z;
    const int p0 = blockIdx.x * 256;
    const float* xb = (br ? x2 : x1) + (size_t)b * 64 * NPIX;
    const float* qb = br ? qb2 : qb1;
    const float* rb = br ? rb2 : rb1;
    const float* ksE = g_ksumE + ((size_t)br * NB + b) * 64;
    const float* rvp = g_rv + ((size_t)br * NB + b) * 64;

    if (tid < 64) sKsE[tid] = __ldg(&ksE[tid]);

    // load x tile [c][px], stride 260
    for (int i = tid; i < 4096; i += 256) {
        int c = i >> 6, q4 = i & 63;
        *(float4*)&dsm[c * 260 + q4 * 4] = *(const float4*)&xb[(size_t)c * NPIX + p0 + q4 * 4];
    }
    __syncthreads();

    float acc[2][8][4];
#pragma unroll
    for (int mt = 0; mt < 2; mt++)
#pragma unroll
        for (int nt = 0; nt < 8; nt++)
#pragma unroll
            for (int k = 0; k < 4; k++) acc[mt][nt][k] = 0.f;

    // ---- phase A: Q = Wq * x (3-term bf16 split) ----
#pragma unroll
    for (int kc = 0; kc < 4; kc++) {
        const uint4* WH = (const uint4*)&g_Wqfrag[((br * 2 + 0) * 4 + kc) * 512 + lane * 16];
        const uint4* WL = (const uint4*)&g_Wqfrag[((br * 2 + 1) * 4 + kc) * 512 + lane * 16];
        uint4 bh[4], bl[4];
#pragma unroll
        for (int q = 0; q < 4; q++) { bh[q] = __ldg(&WH[q]); bl[q] = __ldg(&WL[q]); }
        int c0 = kc * 16 + tg * 2;
#pragma unroll
        for (int mt = 0; mt < 2; mt++) {
            int r0 = wt * 32 + mt * 16 + g;
            float v00 = dsm[(c0 + 0) * 260 + r0], v01 = dsm[(c0 + 1) * 260 + r0];
            float v08 = dsm[(c0 + 8) * 260 + r0], v09 = dsm[(c0 + 9) * 260 + r0];
            float v10 = dsm[(c0 + 0) * 260 + r0 + 8], v11 = dsm[(c0 + 1) * 260 + r0 + 8];
            float v18 = dsm[(c0 + 8) * 260 + r0 + 8], v19 = dsm[(c0 + 9) * 260 + r0 + 8];
            uint32_t ah0, ah1, ah2, ah3, al0, al1, al2, al3;
            splitbf(v00, v01, ah0, al0);
            splitbf(v10, v11, ah1, al1);
            splitbf(v08, v09, ah2, al2);
            splitbf(v18, v19, ah3, al3);
#pragma unroll
            for (int nt = 0; nt < 8; nt++) {
                uint32_t b0h = (nt & 1) ? bh[nt >> 1].z : bh[nt >> 1].x;
                uint32_t b1h = (nt & 1) ? bh[nt >> 1].w : bh[nt >> 1].y;
                uint32_t b0l = (nt & 1) ? bl[nt >> 1].z : bl[nt >> 1].x;
                uint32_t b1l = (nt & 1) ? bl[nt >> 1].w : bl[nt >> 1].y;
                mma_bf16(acc[mt][nt], ah0, ah1, ah2, ah3, b0h, b1h);
                mma_bf16(acc[mt][nt], ah0, ah1, ah2, ah3, b0l, b1l);
                mma_bf16(acc[mt][nt], al0, al1, al2, al3, b0h, b1h);
            }
        }
    }
    __syncthreads();   // done reading x

    // add qb, park Q fp32 at [px][65]
    float qbv[16];
#pragma unroll
    for (int nt = 0; nt < 8; nt++) {
        qbv[nt * 2 + 0] = __ldg(&qb[nt * 8 + tg * 2 + 0]);
        qbv[nt * 2 + 1] = __ldg(&qb[nt * 8 + tg * 2 + 1]);
    }
#pragma unroll
    for (int mt = 0; mt < 2; mt++) {
        int r0 = wt * 32 + mt * 16 + g, r1 = r0 + 8;
#pragma unroll
        for (int nt = 0; nt < 8; nt++) {
            int o0 = nt * 8 + tg * 2;
            dsm[r0 * 65 + o0]     = acc[mt][nt][0] + qbv[nt * 2 + 0];
            dsm[r0 * 65 + o0 + 1] = acc[mt][nt][1] + qbv[nt * 2 + 1];
            dsm[r1 * 65 + o0]     = acc[mt][nt][2] + qbv[nt * 2 + 0];
            dsm[r1 * 65 + o0 + 1] = acc[mt][nt][3] + qbv[nt * 2 + 1];
        }
    }
    __syncthreads();

    // per-px norm + denom
    {
        float s = 0.f, d = 0.f;
        const float* qrow = &dsm[tid * 65];
#pragma unroll 8
        for (int m = 0; m < 64; m++) {
            float v = qrow[m];
            s = fmaf(v, v, s);
            d = fmaf(v, sKsE[m], d);
        }
        float inv = rsqrtf(s);
        sInv[tid] = inv;
        sDen[tid] = 1.f / (65536.f + inv * d);
    }
    __syncthreads();

    // ---- phase B: out = RM * (Q * inv) ----
#pragma unroll
    for (int mt = 0; mt < 2; mt++)
#pragma unroll
        for (int nt = 0; nt < 8; nt++)
#pragma unroll
            for (int k = 0; k < 4; k++) acc[mt][nt][k] = 0.f;

    const uint32_t* rmbase = g_RMfrag + (size_t)(br * 8 + b) * 4096;
#pragma unroll
    for (int kc = 0; kc < 4; kc++) {
        const uint4* RH = (const uint4*)&rmbase[(0 * 4 + kc) * 512 + lane * 16];
        const uint4* RL = (const uint4*)&rmbase[(1 * 4 + kc) * 512 + lane * 16];
        uint4 bh[4], bl[4];
#pragma unroll
        for (int q = 0; q < 4; q++) { bh[q] = __ldg(&RH[q]); bl[q] = __ldg(&RL[q]); }
        int m0 = kc * 16 + tg * 2;
#pragma unroll
        for (int mt = 0; mt < 2; mt++) {
            int r0 = wt * 32 + mt * 16 + g, r1 = r0 + 8;
            float ivA = sInv[r0], ivB = sInv[r1];
            float v00 = dsm[r0 * 65 + m0] * ivA,     v01 = dsm[r0 * 65 + m0 + 1] * ivA;
            float v08 = dsm[r0 * 65 + m0 + 8] * ivA, v09 = dsm[r0 * 65 + m0 + 9] * ivA;
            float v10 = dsm[r1 * 65 + m0] * ivB,     v11 = dsm[r1 * 65 + m0 + 1] * ivB;
            float v18 = dsm[r1 * 65 + m0 + 8] * ivB, v19 = dsm[r1 * 65 + m0 + 9] * ivB;
            uint32_t ah0, ah1, ah2, ah3, al0, al1, al2, al3;
            splitbf(v00, v01, ah0, al0);
            splitbf(v10, v11, ah1, al1);
            splitbf(v08, v09, ah2, al2);
            splitbf(v18, v19, ah3, al3);
#pragma unroll
            for (int nt = 0; nt < 8; nt++) {
                uint32_t b0h = (nt & 1) ? bh[nt >> 1].z : bh[nt >> 1].x;
                uint32_t b1h = (nt & 1) ? bh[nt >> 1].w : bh[nt >> 1].y;
                uint32_t b0l = (nt & 1) ? bl[nt >> 1].z : bl[nt >> 1].x;
                uint32_t b1l = (nt & 1) ? bl[nt >> 1].w : bl[nt >> 1].y;
                mma_bf16(acc[mt][nt], ah0, ah1, ah2, ah3, b0h, b1h);
                mma_bf16(acc[mt][nt], ah0, ah1, ah2, ah3, b0l, b1l);
                mma_bf16(acc[mt][nt], al0, al1, al2, al3, b0h, b1h);
            }
        }
    }
    __syncthreads();   // done reading Q

    // epilogue: out = den*(rv + acc) + rb -> bf16 hi/lo planes [px][64]
    float rvv[16], rbv[16];
#pragma unroll
    for (int nt = 0; nt < 8; nt++) {
        rvv[nt * 2 + 0] = __ldg(&rvp[nt * 8 + tg * 2 + 0]);
        rvv[nt * 2 + 1] = __ldg(&rvp[nt * 8 + tg * 2 + 1]);
        rbv[nt * 2 + 0] = __ldg(&rb[nt * 8 + tg * 2 + 0]);
        rbv[nt * 2 + 1] = __ldg(&rb[nt * 8 + tg * 2 + 1]);
    }
    __nv_bfloat16* sH = (__nv_bfloat16*)dsm;
    __nv_bfloat16* sL = sH + 16384;
#pragma unroll
    for (int mt = 0; mt < 2; mt++) {
#pragma unroll
        for (int h = 0; h < 2; h++) {
            int r = wt * 32 + mt * 16 + g + h * 8;
            float den = sDen[r];
#pragma unroll
            for (int nt = 0; nt < 8; nt++) {
#pragma unroll
                for (int j = 0; j < 2; j++) {
                    int o = nt * 8 + tg * 2 + j;
                    float v = den * (rvv[nt * 2 + j] + acc[mt][nt][h * 2 + j]) + rbv[nt * 2 + j];
                    __nv_bfloat16 hh = __float2bfloat16(v);
                    __nv_bfloat16 ll = __float2bfloat16(v - __bfloat162float(hh));
                    sH[r * 64 + o] = hh;
                    sL[r * 64 + o] = ll;
                }
            }
        }
    }
    __syncthreads();

    // cooperative NHWC store
    const char* sbase = (const char*)dsm;
    for (int u = tid; u < 4096; u += 256) {
        int plane = u >> 11;
        int rest = u & 2047;
        int px = rest >> 3, q = rest & 7;
        uint4 val = *(const uint4*)(sbase + plane * 32768 + px * 128 + q * 16);
        __nv_bfloat16* dst = plane ? g_lo : g_hi;
        *(uint4*)&dst[((size_t)(b * NPIX + p0 + px)) * 128 + br * 64 + q * 8] = val;
    }
}

// -------------------- conv: mma.sync bf16-split implicit GEMM (unchanged) ---------
#define STRIP_STRIDE 272
#define STRIP_BYTES (130 * STRIP_STRIDE)
#define CONV_SMEM (2 * STRIP_BYTES)

__global__ void __launch_bounds__(256) conv_kernel(const float* __restrict__ cbias,
                                                   float* __restrict__ out)
{
    extern __shared__ __align__(16) char dsmc[];
    char* sHi = dsmc;
    char* sLo = dsmc + STRIP_BYTES;
    float* sOut = (float*)dsmc;

    const int tid = threadIdx.x;
    const int lane = tid & 31, wt = tid >> 5;
    const int x0 = blockIdx.x * 128, y = blockIdx.y, b = blockIdx.z;

    float acc[8][4];
#pragma unroll
    for (int nt = 0; nt < 8; nt++)
#pragma unroll
        for (int j = 0; j < 4; j++) acc[nt][j] = 0.f;

    const int g = lane >> 2, tg = lane & 3;
    const uint32_t aOff = (wt * 16 + g) * STRIP_STRIDE + tg * 4;

    for (int ky = 0; ky < 3; ky++) {
        int yy = y + ky - 1;
        bool yok = (yy >= 0 && yy < IMG_H);
        __syncthreads();
        if (yok) {
            size_t rowbase = ((size_t)b * NPIX + (size_t)yy * IMG_W) * 128;
            for (int i = tid; i < 130 * 16; i += 256) {
                int row = i >> 4, ch = i & 15;
                int px = x0 + row - 1;
                uint4 vh = make_uint4(0u, 0u, 0u, 0u);
                uint4 vl = make_uint4(0u, 0u, 0u, 0u);
                if (px >= 0 && px < IMG_W) {
                    size_t gi = rowbase + (size_t)px * 128 + ch * 8;
                    vh = *(const uint4*)&g_hi[gi];
                    vl = *(const uint4*)&g_lo[gi];
                }
                *(uint4*)(sHi + row * STRIP_STRIDE + ch * 16) = vh;
                *(uint4*)(sLo + row * STRIP_STRIDE + ch * 16) = vl;
            }
        }
        __syncthreads();
        if (!yok) continue;

#pragma unroll 1
        for (int kc = 0; kc < 24; kc++) {
            int kx = kc >> 3, cc8 = kc & 7;
            uint32_t r0 = aOff + kx * STRIP_STRIDE + cc8 * 32;
            uint32_t ah0 = *(const uint32_t*)(sHi + r0);
            uint32_t ah1 = *(const uint32_t*)(sHi + r0 + 8 * STRIP_STRIDE);
            uint32_t ah2 = *(const uint32_t*)(sHi + r0 + 16);
            uint32_t ah3 = *(const uint32_t*)(sHi + r0 + 8 * STRIP_STRIDE + 16);
            uint32_t al0 = *(const uint32_t*)(sLo + r0);
            uint32_t al1 = *(const uint32_t*)(sLo + r0 + 8 * STRIP_STRIDE);
            uint32_t al2 = *(const uint32_t*)(sLo + r0 + 16);
            uint32_t al3 = *(const uint32_t*)(sLo + r0 + 8 * STRIP_STRIDE + 16);

            const uint4* bfH = (const uint4*)(g_Bfrag + (((ky * 24 + kc) * 2 + 0) * 32 + lane) * 16);
            const uint4* bfL = (const uint4*)(g_Bfrag + (((ky * 24 + kc) * 2 + 1) * 32 + lane) * 16);
            uint4 bh[4], bl[4];
#pragma unroll
            for (int q = 0; q < 4; q++) { bh[q] = __ldg(&bfH[q]); bl[q] = __ldg(&bfL[q]); }

#pragma unroll
            for (int nt = 0; nt < 8; nt++) {
                uint32_t bh0 = (nt & 1) ? bh[nt >> 1].z : bh[nt >> 1].x;
                uint32_t bh1 = (nt & 1) ? bh[nt >> 1].w : bh[nt >> 1].y;
                uint32_t bl0 = (nt & 1) ? bl[nt >> 1].z : bl[nt >> 1].x;
                uint32_t bl1 = (nt & 1) ? bl[nt >> 1].w : bl[nt >> 1].y;
                mma_bf16(acc[nt], ah0, ah1, ah2, ah3, bh0, bh1);
                mma_bf16(acc[nt], ah0, ah1, ah2, ah3, bl0, bl1);
                mma_bf16(acc[nt], al0, al1, al2, al3, bh0, bh1);
            }
        }
    }

    __syncthreads();
#pragma unroll
    for (int nt = 0; nt < 8; nt++)
#pragma unroll
        for (int h = 0; h < 2; h++)
#pragma unroll
            for (int j = 0; j < 2; j++) {
                int o = nt * 8 + tg * 2 + j;
                int px = wt * 16 + g + h * 8;
                sOut[o * 132 + px] = acc[nt][h * 2 + j];
            }
    __syncthreads();
    for (int i = tid; i < 64 * 32; i += 256) {
        int o = i >> 5, ch = i & 31;
        float4 v = *(const float4*)&sOut[o * 132 + ch * 4];
        float bias = __ldg(&cbias[o]);
        v.x += bias; v.y += bias; v.z += bias; v.w += bias;
        *(float4*)&out[((size_t)(b * 64 + o)) * NPIX + (size_t)y * IMG_W + x0 + ch * 4] = v;
    }
}

// -------------------- launch --------------------
extern "C" void kernel_launch(void* const* d_in, const int* in_sizes, int n_in,
                              void* d_out, int out_size)
{
    (void)in_sizes; (void)n_in; (void)out_size;
    const float* t1  = (const float*)d_in[0];
    const float* t2  = (const float*)d_in[1];
    const float* q1w = (const float*)d_in[2];  const float* q1b = (const float*)d_in[3];
    const float* k1w = (const float*)d_in[4];  const float* k1b = (const float*)d_in[5];
    const float* v1w = (const float*)d_in[6];  const float* v1b = (const float*)d_in[7];
    const float* r1w = (const float*)d_in[8];  const float* r1b = (const float*)d_in[9];
    const float* q2w = (const float*)d_in[10]; const float* q2b = (const float*)d_in[11];
    const float* k2w = (const float*)d_in[12]; const float* k2b = (const float*)d_in[13];
    const float* v2w = (const float*)d_in[14]; const float* v2b = (const float*)d_in[15];
    const float* r2w = (const float*)d_in[16]; const float* r2b = (const float*)d_in[17];
    const float* cw  = (const float*)d_in[18]; const float* cb  = (const float*)d_in[19];

    cudaFuncSetAttribute(conv_kernel, cudaFuncAttributeMaxDynamicSharedMemorySize, CONV_SMEM);
    cudaFuncSetAttribute(pass2_kernel, cudaFuncAttributeMaxDynamicSharedMemorySize, P2_SMEM);

    prep_kernel<<<640, 256>>>(q1w, k1w, v1w, q2w, k2w, v2w, cw);  // launch 0
    dim3 g1(128, 8, 2);
    pass1_kernel<<<g1, 256>>>(t1, t2, k1b, v1b, k2b, v2b);        // launch 1
    dim3 gm(8, 2);
    mid_kernel<<<gm, 256>>>(r1w, r2w);                            // launch 2
    dim3 g2(256, 8, 2);
    pass2_kernel<<<g2, 256, P2_SMEM>>>(t1, t2, q1b, r1b, q2b, r2b); // launch 3
    dim3 gc(2, 256, 8);
    conv_kernel<<<gc, 256, CONV_SMEM>>>(cb, (float*)d_out);       // launch 4
}

// round 7
// speedup vs baseline: 1.5388x; 1.0680x over previous
#include <cuda_runtime.h>
#include <cuda_bf16.h>
#include <cstdint>

#define NPIX 65536
#define IMG_H 256
#define IMG_W 256
#define NB 8

// ---- device scratch ----
__device__ __nv_bfloat16 g_hi[NB * NPIX * 128];   // NHWC [b][y][x][ci], hi plane
__device__ __nv_bfloat16 g_lo[NB * NPIX * 128];   // lo plane
__device__ uint32_t g_Bfrag[3 * 24 * 2 * 32 * 16];  // conv weight mma frags
__device__ uint32_t g_QKVfrag[3 * 2 * 2 * 4 * 32 * 16]; // [kind q/k/v][br][half][kc][lane][ntj]
__device__ uint32_t g_RMfrag[16 * 2 * 4 * 32 * 16]; // [(br*8+b)][half][kc][lane][ntj]
__device__ float g_mat[2 * NB * 64 * 64];
__device__ float g_ksum[2 * NB * 64];
__device__ float g_vsum[2 * NB * 64];
__device__ float g_rv[2 * NB * 64];
__device__ float g_ksumE[2 * NB * 64];

// ---- mma.sync bf16 helper (m16n8k16, f32 accum) ----
__device__ __forceinline__ void mma_bf16(float* d,
                                         uint32_t a0, uint32_t a1, uint32_t a2, uint32_t a3,
                                         uint32_t b0, uint32_t b1) {
    asm volatile(
        "mma.sync.aligned.m16n8k16.row.col.f32.bf16.bf16.f32 "
        "{%0,%1,%2,%3}, {%4,%5,%6,%7}, {%8,%9}, {%0,%1,%2,%3};"
        : "+f"(d[0]), "+f"(d[1]), "+f"(d[2]), "+f"(d[3])
        : "r"(a0), "r"(a1), "r"(a2), "r"(a3), "r"(b0), "r"(b1));
}

__device__ __forceinline__ void splitbf(float a, float b, uint32_t& h, uint32_t& l) {
    __nv_bfloat16 ha = __float2bfloat16(a), hb = __float2bfloat16(b);
    __nv_bfloat162 hh; hh.x = ha; hh.y = hb;
    h = *(uint32_t*)&hh;
    __nv_bfloat162 ll = __floats2bfloat162_rn(a - __bfloat162float(ha),
                                              b - __bfloat162float(hb));
    l = *(uint32_t*)&ll;
}
__device__ __forceinline__ uint32_t packbf_hi_lo(float a, float b, int half) {
    if (half == 0) {
        __nv_bfloat162 hh; hh.x = __float2bfloat16(a); hh.y = __float2bfloat16(b);
        return *(uint32_t*)&hh;
    }
    __nv_bfloat16 ha = __float2bfloat16(a), hb = __float2bfloat16(b);
    __nv_bfloat162 ll = __floats2bfloat162_rn(a - __bfloat162float(ha),
                                              b - __bfloat162float(hb));
    return *(uint32_t*)&ll;
}

// -------------------- prep (single kernel) --------------------
// blocks 0..255: zero stats; 256..543: conv frags; 544..639: q/k/v weight frags.
__global__ void __launch_bounds__(256) prep_kernel(
    const float* __restrict__ q1w, const float* __restrict__ k1w, const float* __restrict__ v1w,
    const float* __restrict__ q2w, const float* __restrict__ k2w, const float* __restrict__ v2w,
    const float* __restrict__ cw)
{
    int nb = blockIdx.x, tid = threadIdx.x;
    if (nb < 256) {
        int idx = nb * 256 + tid;
        g_mat[idx] = 0.f;
        if (idx < 2 * NB * 64) { g_ksum[idx] = 0.f; g_vsum[idx] = 0.f; }
        return;
    }
    if (nb < 544) {
        int i = (nb - 256) * 256 + tid;  // 0..73727
        int ky = i / 24576;
        int rem = i % 24576;
        int kc = rem / 1024;
        int rem2 = rem % 1024;
        int half = rem2 / 512;
        int rem3 = rem2 % 512;
        int lane = rem3 / 16;
        int r4 = rem3 % 16;
        int nt = r4 >> 1, j = r4 & 1;
        int kx = kc >> 3, cc8 = kc & 7;
        int n = nt * 8 + (lane >> 2);
        int ci0 = cc8 * 16 + (lane & 3) * 2 + j * 8;
        float w0 = cw[((n * 128 + ci0) * 3 + ky) * 3 + kx];
        float w1 = cw[((n * 128 + ci0 + 1) * 3 + ky) * 3 + kx];
        g_Bfrag[i] = packbf_hi_lo(w0, w1, half);
        return;
    }
    {
        int t = nb - 544;                // 0..95
        int kind = t / 32;               // 0=q, 1=k, 2=v
        int i = (t % 32) * 256 + tid;    // 0..8191
        int br = i >> 12;
        int r = i & 4095;
        int half = r >> 11;
        int kc = (r >> 9) & 3;
        int lane = (r >> 4) & 31;
        int ntj = r & 15;
        int nt = ntj >> 1, j = ntj & 1;
        int o = nt * 8 + (lane >> 2);
        int c0 = kc * 16 + (lane & 3) * 2 + j * 8;
        const float* w;
        if (kind == 0) w = br ? q2w : q1w;
        else if (kind == 1) w = br ? k2w : k1w;
        else w = br ? v2w : v1w;
        float w0 = w[o * 64 + c0];
        float w1 = w[o * 64 + c0 + 1];
        g_QKVfrag[kind * 8192 + i] = packbf_hi_lo(w0, w1, half);
    }
}

// -------------------- pass 1: mma K,V proj + mma stats --------------------
// grid (256, 8, 2), 256 thr = 8 warps. Tile: 256 px.
// dynamic smem: X fp32 [64][260] | Kp [64][260] | Vp [64][260]  = 199680 B
#define P1_SMEM (3 * 66560)

__global__ void __launch_bounds__(256) pass1_kernel(
    const float* __restrict__ x1, const float* __restrict__ x2,
    const float* __restrict__ kb1, const float* __restrict__ vb1,
    const float* __restrict__ kb2, const float* __restrict__ vb2)
{
    extern __shared__ __align__(16) float dsm1[];
    __shared__ float sInv[256];
    float* X  = dsm1;
    float* Kp = dsm1 + 16640;
    float* Vp = dsm1 + 33280;

    const int tid = threadIdx.x;
    const int lane = tid & 31, wt = tid >> 5;
    const int g = lane >> 2, tg = lane & 3;
    const int b = blockIdx.y, br = blockIdx.z;
    const int p0 = blockIdx.x * 256;
    const float* xb = (br ? x2 : x1) + (size_t)b * 64 * NPIX;
    const float* kb = br ? kb2 : kb1;
    const float* vb = br ? vb2 : vb1;

    // load x tile [c][px]
    for (int i = tid; i < 4096; i += 256) {
        int c = i >> 6, q4 = i & 63;
        *(float4*)&X[c * 260 + q4 * 4] = *(const float4*)&xb[(size_t)c * NPIX + p0 + q4 * 4];
    }
    __syncthreads();

    // ---- projections: kv=0 -> K, kv=1 -> V (3-term bf16 split mma) ----
#pragma unroll 1
    for (int kv = 0; kv < 2; kv++) {
        const uint32_t* wf = g_QKVfrag + (kv + 1) * 8192 + br * 4096;
        const float* bias = kv ? vb : kb;
        float* park = kv ? Vp : Kp;

        float acc[2][8][4];
#pragma unroll
        for (int mt = 0; mt < 2; mt++)
#pragma unroll
            for (int nt = 0; nt < 8; nt++)
#pragma unroll
                for (int k = 0; k < 4; k++) acc[mt][nt][k] = 0.f;

#pragma unroll
        for (int kc = 0; kc < 4; kc++) {
            const uint4* WH = (const uint4*)&wf[(0 * 4 + kc) * 512 + lane * 16];
            const uint4* WL = (const uint4*)&wf[(1 * 4 + kc) * 512 + lane * 16];
            uint4 bh[4], bl[4];
#pragma unroll
            for (int q = 0; q < 4; q++) { bh[q] = __ldg(&WH[q]); bl[q] = __ldg(&WL[q]); }
            int c0 = kc * 16 + tg * 2;
#pragma unroll
            for (int mt = 0; mt < 2; mt++) {
                int r0 = wt * 32 + mt * 16 + g;
                float v00 = X[(c0 + 0) * 260 + r0], v01 = X[(c0 + 1) * 260 + r0];
                float v08 = X[(c0 + 8) * 260 + r0], v09 = X[(c0 + 9) * 260 + r0];
                float v10 = X[(c0 + 0) * 260 + r0 + 8], v11 = X[(c0 + 1) * 260 + r0 + 8];
                float v18 = X[(c0 + 8) * 260 + r0 + 8], v19 = X[(c0 + 9) * 260 + r0 + 8];
                uint32_t ah0, ah1, ah2, ah3, al0, al1, al2, al3;
                splitbf(v00, v01, ah0, al0);
                splitbf(v10, v11, ah1, al1);
                splitbf(v08, v09, ah2, al2);
                splitbf(v18, v19, ah3, al3);
#pragma unroll
                for (int nt = 0; nt < 8; nt++) {
                    uint32_t b0h = (nt & 1) ? bh[nt >> 1].z : bh[nt >> 1].x;
                    uint32_t b1h = (nt & 1) ? bh[nt >> 1].w : bh[nt >> 1].y;
                    uint32_t b0l = (nt & 1) ? bl[nt >> 1].z : bl[nt >> 1].x;
                    uint32_t b1l = (nt & 1) ? bl[nt >> 1].w : bl[nt >> 1].y;
                    mma_bf16(acc[mt][nt], ah0, ah1, ah2, ah3, b0h, b1h);
                    mma_bf16(acc[mt][nt], ah0, ah1, ah2, ah3, b0l, b1l);
                    mma_bf16(acc[mt][nt], al0, al1, al2, al3, b0h, b1h);
                }
            }
        }

        // park + bias, transposed to [och][px]
        float bv[16];
#pragma unroll
        for (int nt = 0; nt < 8; nt++) {
            bv[nt * 2 + 0] = __ldg(&bias[nt * 8 + tg * 2 + 0]);
            bv[nt * 2 + 1] = __ldg(&bias[nt * 8 + tg * 2 + 1]);
        }
#pragma unroll
        for (int mt = 0; mt < 2; mt++)
#pragma unroll
            for (int h = 0; h < 2; h++) {
                int px = wt * 32 + mt * 16 + g + h * 8;
#pragma unroll
                for (int nt = 0; nt < 8; nt++) {
#pragma unroll
                    for (int j = 0; j < 2; j++) {
                        int o = nt * 8 + tg * 2 + j;
                        park[o * 260 + px] = acc[mt][nt][h * 2 + j] + bv[nt * 2 + j];
                    }
                }
            }
    }
    __syncthreads();

    // per-px 1/||K||
    {
        float s = 0.f;
#pragma unroll 8
        for (int m = 0; m < 64; m++) {
            float v = Kp[m * 260 + tid];
            s = fmaf(v, v, s);
        }
        sInv[tid] = rsqrtf(s);
    }
    __syncthreads();

    // ---- stats GEMM: matrix += Kn * V^T  (M=64 kch, N=64 vch, K=256 px) ----
    const int mt4 = wt >> 1;      // m-tile 0..3
    const int nh = wt & 1;        // n half
    float acc2[4][4];
#pragma unroll
    for (int nt = 0; nt < 4; nt++)
#pragma unroll
        for (int k = 0; k < 4; k++) acc2[nt][k] = 0.f;
    float ksg = 0.f, ksg8 = 0.f;
    float vs[4] = {0.f, 0.f, 0.f, 0.f};

#pragma unroll 2
    for (int kc = 0; kc < 16; kc++) {
        int px0 = kc * 16 + tg * 2;
        float i0 = sInv[px0], i1 = sInv[px0 + 1];
        float i8 = sInv[px0 + 8], i9 = sInv[px0 + 9];
        int m0 = mt4 * 16 + g;
        float f00 = Kp[m0 * 260 + px0] * i0;
        float f01 = Kp[m0 * 260 + px0 + 1] * i1;
        float f08 = Kp[m0 * 260 + px0 + 8] * i8;
        float f09 = Kp[m0 * 260 + px0 + 9] * i9;
        float f10 = Kp[(m0 + 8) * 260 + px0] * i0;
        float f11 = Kp[(m0 + 8) * 260 + px0 + 1] * i1;
        float f18 = Kp[(m0 + 8) * 260 + px0 + 8] * i8;
        float f19 = Kp[(m0 + 8) * 260 + px0 + 9] * i9;
        uint32_t a0h, a0l, a1h, a1l, a2h, a2l, a3h, a3l;
        splitbf(f00, f01, a0h, a0l);
        splitbf(f10, f11, a1h, a1l);
        splitbf(f08, f09, a2h, a2l);
        splitbf(f18, f19, a3h, a3l);
        if (nh == 0) {
            ksg += f00 + f01 + f08 + f09;
            ksg8 += f10 + f11 + f18 + f19;
        }
#pragma unroll
        for (int nt = 0; nt < 4; nt++) {
            int n = (nh * 4 + nt) * 8 + g;
            float2 b0 = *(const float2*)&Vp[n * 260 + px0];
            float2 b8 = *(const float2*)&Vp[n * 260 + px0 + 8];
            if (mt4 == 0) vs[nt] += b0.x + b0.y + b8.x + b8.y;
            uint32_t bh0, bl0, bh1, bl1;
            splitbf(b0.x, b0.y, bh0, bl0);
            splitbf(b8.x, b8.y, bh1, bl1);
            mma_bf16(acc2[nt], a0h, a1h, a2h, a3h, bh0, bh1);
            mma_bf16(acc2[nt], a0h, a1h, a2h, a3h, bl0, bl1);
            mma_bf16(acc2[nt], a0l, a1l, a2l, a3l, bh0, bh1);
        }
    }

    // flush: matrix atomics
    float* mat = g_mat + ((size_t)br * NB + b) * 4096;
#pragma unroll
    for (int nt = 0; nt < 4; nt++) {
#pragma unroll
        for (int k = 0; k < 4; k++) {
            int m = mt4 * 16 + g + ((k >= 2) ? 8 : 0);
            int n = (nh * 4 + nt) * 8 + tg * 2 + (k & 1);
            atomicAdd(&mat[m * 64 + n], acc2[nt][k]);
        }
    }
    // ksum (warps with nh==0 cover each channel exactly once)
    if (nh == 0) {
        ksg += __shfl_xor_sync(0xffffffffu, ksg, 1);
        ksg += __shfl_xor_sync(0xffffffffu, ksg, 2);
        ksg8 += __shfl_xor_sync(0xffffffffu, ksg8, 1);
        ksg8 += __shfl_xor_sync(0xffffffffu, ksg8, 2);
        if (tg == 0) {
            float* kp = g_ksum + ((size_t)br * NB + b) * 64;
            atomicAdd(&kp[mt4 * 16 + g], ksg);
            atomicAdd(&kp[mt4 * 16 + g + 8], ksg8);
        }
    }
    // vsum (warps with mt4==0 cover each channel exactly once)
    if (mt4 == 0) {
#pragma unroll
        for (int nt = 0; nt < 4; nt++) {
            float v = vs[nt];
            v += __shfl_xor_sync(0xffffffffu, v, 1);
            v += __shfl_xor_sync(0xffffffffu, v, 2);
            if (tg == 0)
                atomicAdd(&g_vsum[((size_t)br * NB + b) * 64 + (nh * 4 + nt) * 8 + g], v);
        }
    }
}

// -------------------- mid: RM frags, rv, ksumE --------------------
__global__ void __launch_bounds__(256) mid_kernel(const float* __restrict__ rw1,
                                                  const float* __restrict__ rw2)
{
    __shared__ float sMat[4096];
    __shared__ float sRw[4096];
    const int tid = threadIdx.x;
    const int b = blockIdx.x, br = blockIdx.y;
    const float* rw = br ? rw2 : rw1;
    const float* mat = g_mat + ((size_t)br * NB + b) * 4096;
#pragma unroll
    for (int r = 0; r < 16; r++) {
        int i = tid + r * 256;
        sMat[i] = mat[i];
        sRw[i] = rw[i];
    }
    __syncthreads();
    const int ty = tid >> 4, tx = tid & 15;
    float acc[4][4];
#pragma unroll
    for (int i = 0; i < 4; i++)
#pragma unroll
        for (int j = 0; j < 4; j++) acc[i][j] = 0.f;
#pragma unroll 4
    for (int c = 0; c < 64; c++) {
        float a[4], w[4];
#pragma unroll
        for (int i = 0; i < 4; i++) a[i] = sMat[(ty * 4 + i) * 64 + c];
#pragma unroll
        for (int j = 0; j < 4; j++) w[j] = sRw[(tx * 4 + j) * 64 + c];
#pragma unroll
        for (int i = 0; i < 4; i++)
#pragma unroll
            for (int j = 0; j < 4; j++) acc[i][j] += a[i] * w[j];
    }
    if (tid < 64) {
        const float* vsump = g_vsum + ((size_t)br * NB + b) * 64;
        float s = 0.f;
        for (int c = 0; c < 64; c++) s += sRw[tid * 64 + c] * vsump[c];
        g_rv[((size_t)br * NB + b) * 64 + tid] = s;
        g_ksumE[((size_t)br * NB + b) * 64 + tid] =
            g_ksum[((size_t)br * NB + b) * 64 + tid] + 1e-6f;
    }
    __syncthreads();
#pragma unroll
    for (int i = 0; i < 4; i++)
#pragma unroll
        for (int j = 0; j < 4; j++)
            sMat[(tx * 4 + j) * 64 + (ty * 4 + i)] = acc[i][j];
    __syncthreads();
    uint32_t* dst = g_RMfrag + (size_t)(br * 8 + b) * 4096;
    for (int t = tid; t < 4096; t += 256) {
        int half = t >> 11;
        int lane = (t >> 4) & 31;
        int ntj = t & 15;
        int nt = ntj >> 1, j = ntj & 1;
        int kc = (t >> 9) & 3;
        int o = nt * 8 + (lane >> 2);
        int m0 = kc * 16 + (lane & 3) * 2 + j * 8;
        float w0 = sMat[o * 64 + m0];
        float w1 = sMat[o * 64 + m0 + 1];
        dst[t] = packbf_hi_lo(w0, w1, half);
    }
}

// -------------------- pass 2: mma.sync Q proj + RM*Qn -> NHWC bf16 hi/lo ----------
#define P2_SMEM 66560

__global__ void __launch_bounds__(256) pass2_kernel(
    const float* __restrict__ x1, const float* __restrict__ x2,
    const float* __restrict__ qb1, const float* __restrict__ rb1,
    const float* __restrict__ qb2, const float* __restrict__ rb2)
{
    extern __shared__ __align__(16) float dsm[];
    __shared__ float sInv[256], sDen[256], sKsE[64];

    const int tid = threadIdx.x;
    const int lane = tid & 31, wt = tid >> 5;
    const int g = lane >> 2, tg = lane & 3;
    const int b = blockIdx.y, br = blockIdx.z;
    const int p0 = blockIdx.x * 256;
    const float* xb = (br ? x2 : x1) + (size_t)b * 64 * NPIX;
    const float* qb = br ? qb2 : qb1;
    const float* rb = br ? rb2 : rb1;
    const float* ksE = g_ksumE + ((size_t)br * NB + b) * 64;
    const float* rvp = g_rv + ((size_t)br * NB + b) * 64;

    if (tid < 64) sKsE[tid] = __ldg(&ksE[tid]);

    for (int i = tid; i < 4096; i += 256) {
        int c = i >> 6, q4 = i & 63;
        *(float4*)&dsm[c * 260 + q4 * 4] = *(const float4*)&xb[(size_t)c * NPIX + p0 + q4 * 4];
    }
    __syncthreads();

    float acc[2][8][4];
#pragma unroll
    for (int mt = 0; mt < 2; mt++)
#pragma unroll
        for (int nt = 0; nt < 8; nt++)
#pragma unroll
            for (int k = 0; k < 4; k++) acc[mt][nt][k] = 0.f;

#pragma unroll
    for (int kc = 0; kc < 4; kc++) {
        const uint4* WH = (const uint4*)&g_QKVfrag[((br * 2 + 0) * 4 + kc) * 512 + lane * 16];
        const uint4* WL = (const uint4*)&g_QKVfrag[((br * 2 + 1) * 4 + kc) * 512 + lane * 16];
        uint4 bh[4], bl[4];
#pragma unroll
        for (int q = 0; q < 4; q++) { bh[q] = __ldg(&WH[q]); bl[q] = __ldg(&WL[q]); }
        int c0 = kc * 16 + tg * 2;
#pragma unroll
        for (int mt = 0; mt < 2; mt++) {
            int r0 = wt * 32 + mt * 16 + g;
            float v00 = dsm[(c0 + 0) * 260 + r0], v01 = dsm[(c0 + 1) * 260 + r0];
            float v08 = dsm[(c0 + 8) * 260 + r0], v09 = dsm[(c0 + 9) * 260 + r0];
            float v10 = dsm[(c0 + 0) * 260 + r0 + 8], v11 = dsm[(c0 + 1) * 260 + r0 + 8];
            float v18 = dsm[(c0 + 8) * 260 + r0 + 8], v19 = dsm[(c0 + 9) * 260 + r0 + 8];
            uint32_t ah0, ah1, ah2, ah3, al0, al1, al2, al3;
            splitbf(v00, v01, ah0, al0);
            splitbf(v10, v11, ah1, al1);
            splitbf(v08, v09, ah2, al2);
            splitbf(v18, v19, ah3, al3);
#pragma unroll
            for (int nt = 0; nt < 8; nt++) {
                uint32_t b0h = (nt & 1) ? bh[nt >> 1].z : bh[nt >> 1].x;
                uint32_t b1h = (nt & 1) ? bh[nt >> 1].w : bh[nt >> 1].y;
                uint32_t b0l = (nt & 1) ? bl[nt >> 1].z : bl[nt >> 1].x;
                uint32_t b1l = (nt & 1) ? bl[nt >> 1].w : bl[nt >> 1].y;
                mma_bf16(acc[mt][nt], ah0, ah1, ah2, ah3, b0h, b1h);
                mma_bf16(acc[mt][nt], ah0, ah1, ah2, ah3, b0l, b1l);
                mma_bf16(acc[mt][nt], al0, al1, al2, al3, b0h, b1h);
            }
        }
    }
    __syncthreads();

    float qbv[16];
#pragma unroll
    for (int nt = 0; nt < 8; nt++) {
        qbv[nt * 2 + 0] = __ldg(&qb[nt * 8 + tg * 2 + 0]);
        qbv[nt * 2 + 1] = __ldg(&qb[nt * 8 + tg * 2 + 1]);
    }
#pragma unroll
    for (int mt = 0; mt < 2; mt++) {
        int r0 = wt * 32 + mt * 16 + g, r1 = r0 + 8;
#pragma unroll
        for (int nt = 0; nt < 8; nt++) {
            int o0 = nt * 8 + tg * 2;
            dsm[r0 * 65 + o0]     = acc[mt][nt][0] + qbv[nt * 2 + 0];
            dsm[r0 * 65 + o0 + 1] = acc[mt][nt][1] + qbv[nt * 2 + 1];
            dsm[r1 * 65 + o0]     = acc[mt][nt][2] + qbv[nt * 2 + 0];
            dsm[r1 * 65 + o0 + 1] = acc[mt][nt][3] + qbv[nt * 2 + 1];
        }
    }
    __syncthreads();

    {
        float s = 0.f, d = 0.f;
        const float* qrow = &dsm[tid * 65];
#pragma unroll 8
        for (int m = 0; m < 64; m++) {
            float v = qrow[m];
            s = fmaf(v, v, s);
            d = fmaf(v, sKsE[m], d);
        }
        float inv = rsqrtf(s);
        sInv[tid] = inv;
        sDen[tid] = 1.f / (65536.f + inv * d);
    }
    __syncthreads();

#pragma unroll
    for (int mt = 0; mt < 2; mt++)
#pragma unroll
        for (int nt = 0; nt < 8; nt++)
#pragma unroll
            for (int k = 0; k < 4; k++) acc[mt][nt][k] = 0.f;

    const uint32_t* rmbase = g_RMfrag + (size_t)(br * 8 + b) * 4096;
#pragma unroll
    for (int kc = 0; kc < 4; kc++) {
        const uint4* RH = (const uint4*)&rmbase[(0 * 4 + kc) * 512 + lane * 16];
        const uint4* RL = (const uint4*)&rmbase[(1 * 4 + kc) * 512 + lane * 16];
        uint4 bh[4], bl[4];
#pragma unroll
        for (int q = 0; q < 4; q++) { bh[q] = __ldg(&RH[q]); bl[q] = __ldg(&RL[q]); }
        int m0 = kc * 16 + tg * 2;
#pragma unroll
        for (int mt = 0; mt < 2; mt++) {
            int r0 = wt * 32 + mt * 16 + g, r1 = r0 + 8;
            float ivA = sInv[r0], ivB = sInv[r1];
            float v00 = dsm[r0 * 65 + m0] * ivA,     v01 = dsm[r0 * 65 + m0 + 1] * ivA;
            float v08 = dsm[r0 * 65 + m0 + 8] * ivA, v09 = dsm[r0 * 65 + m0 + 9] * ivA;
            float v10 = dsm[r1 * 65 + m0] * ivB,     v11 = dsm[r1 * 65 + m0 + 1] * ivB;
            float v18 = dsm[r1 * 65 + m0 + 8] * ivB, v19 = dsm[r1 * 65 + m0 + 9] * ivB;
            uint32_t ah0, ah1, ah2, ah3, al0, al1, al2, al3;
            splitbf(v00, v01, ah0, al0);
            splitbf(v10, v11, ah1, al1);
            splitbf(v08, v09, ah2, al2);
            splitbf(v18, v19, ah3, al3);
#pragma unroll
            for (int nt = 0; nt < 8; nt++) {
                uint32_t b0h = (nt & 1) ? bh[nt >> 1].z : bh[nt >> 1].x;
                uint32_t b1h = (nt & 1) ? bh[nt >> 1].w : bh[nt >> 1].y;
                uint32_t b0l = (nt & 1) ? bl[nt >> 1].z : bl[nt >> 1].x;
                uint32_t b1l = (nt & 1) ? bl[nt >> 1].w : bl[nt >> 1].y;
                mma_bf16(acc[mt][nt], ah0, ah1, ah2, ah3, b0h, b1h);
                mma_bf16(acc[mt][nt], ah0, ah1, ah2, ah3, b0l, b1l);
                mma_bf16(acc[mt][nt], al0, al1, al2, al3, b0h, b1h);
            }
        }
    }
    __syncthreads();

    float rvv[16], rbv[16];
#pragma unroll
    for (int nt = 0; nt < 8; nt++) {
        rvv[nt * 2 + 0] = __ldg(&rvp[nt * 8 + tg * 2 + 0]);
        rvv[nt * 2 + 1] = __ldg(&rvp[nt * 8 + tg * 2 + 1]);
        rbv[nt * 2 + 0] = __ldg(&rb[nt * 8 + tg * 2 + 0]);
        rbv[nt * 2 + 1] = __ldg(&rb[nt * 8 + tg * 2 + 1]);
    }
    __nv_bfloat16* sH = (__nv_bfloat16*)dsm;
    __nv_bfloat16* sL = sH + 16384;
#pragma unroll
    for (int mt = 0; mt < 2; mt++) {
#pragma unroll
        for (int h = 0; h < 2; h++) {
            int r = wt * 32 + mt * 16 + g + h * 8;
            float den = sDen[r];
#pragma unroll
            for (int nt = 0; nt < 8; nt++) {
#pragma unroll
                for (int j = 0; j < 2; j++) {
                    int o = nt * 8 + tg * 2 + j;
                    float v = den * (rvv[nt * 2 + j] + acc[mt][nt][h * 2 + j]) + rbv[nt * 2 + j];
                    __nv_bfloat16 hh = __float2bfloat16(v);
                    __nv_bfloat16 ll = __float2bfloat16(v - __bfloat162float(hh));
                    sH[r * 64 + o] = hh;
                    sL[r * 64 + o] = ll;
                }
            }
        }
    }
    __syncthreads();

    const char* sbase = (const char*)dsm;
    for (int u = tid; u < 4096; u += 256) {
        int plane = u >> 11;
        int rest = u & 2047;
        int px = rest >> 3, q = rest & 7;
        uint4 val = *(const uint4*)(sbase + plane * 32768 + px * 128 + q * 16);
        __nv_bfloat16* dst = plane ? g_lo : g_hi;
        *(uint4*)&dst[((size_t)(b * NPIX + p0 + px)) * 128 + br * 64 + q * 8] = val;
    }
}

// -------------------- conv: mma.sync bf16-split implicit GEMM (unchanged) ---------
#define STRIP_STRIDE 272
#define STRIP_BYTES (130 * STRIP_STRIDE)
#define CONV_SMEM (2 * STRIP_BYTES)

__global__ void __launch_bounds__(256) conv_kernel(const float* __restrict__ cbias,
                                                   float* __restrict__ out)
{
    extern __shared__ __align__(16) char dsmc[];
    char* sHi = dsmc;
    char* sLo = dsmc + STRIP_BYTES;
    float* sOut = (float*)dsmc;

    const int tid = threadIdx.x;
    const int lane = tid & 31, wt = tid >> 5;
    const int x0 = blockIdx.x * 128, y = blockIdx.y, b = blockIdx.z;

    float acc[8][4];
#pragma unroll
    for (int nt = 0; nt < 8; nt++)
#pragma unroll
        for (int j = 0; j < 4; j++) acc[nt][j] = 0.f;

    const int g = lane >> 2, tg = lane & 3;
    const uint32_t aOff = (wt * 16 + g) * STRIP_STRIDE + tg * 4;

    for (int ky = 0; ky < 3; ky++) {
        int yy = y + ky - 1;
        bool yok = (yy >= 0 && yy < IMG_H);
        __syncthreads();
        if (yok) {
            size_t rowbase = ((size_t)b * NPIX + (size_t)yy * IMG_W) * 128;
            for (int i = tid; i < 130 * 16; i += 256) {
                int row = i >> 4, ch = i & 15;
                int px = x0 + row - 1;
                uint4 vh = make_uint4(0u, 0u, 0u, 0u);
                uint4 vl = make_uint4(0u, 0u, 0u, 0u);
                if (px >= 0 && px < IMG_W) {
                    size_t gi = rowbase + (size_t)px * 128 + ch * 8;
                    vh = *(const uint4*)&g_hi[gi];
                    vl = *(const uint4*)&g_lo[gi];
                }
                *(uint4*)(sHi + row * STRIP_STRIDE + ch * 16) = vh;
                *(uint4*)(sLo + row * STRIP_STRIDE + ch * 16) = vl;
            }
        }
        __syncthreads();
        if (!yok) continue;

#pragma unroll 1
        for (int kc = 0; kc < 24; kc++) {
            int kx = kc >> 3, cc8 = kc & 7;
            uint32_t r0 = aOff + kx * STRIP_STRIDE + cc8 * 32;
            uint32_t ah0 = *(const uint32_t*)(sHi + r0);
            uint32_t ah1 = *(const uint32_t*)(sHi + r0 + 8 * STRIP_STRIDE);
            uint32_t ah2 = *(const uint32_t*)(sHi + r0 + 16);
            uint32_t ah3 = *(const uint32_t*)(sHi + r0 + 8 * STRIP_STRIDE + 16);
            uint32_t al0 = *(const uint32_t*)(sLo + r0);
            uint32_t al1 = *(const uint32_t*)(sLo + r0 + 8 * STRIP_STRIDE);
            uint32_t al2 = *(const uint32_t*)(sLo + r0 + 16);
            uint32_t al3 = *(const uint32_t*)(sLo + r0 + 8 * STRIP_STRIDE + 16);

            const uint4* bfH = (const uint4*)(g_Bfrag + (((ky * 24 + kc) * 2 + 0) * 32 + lane) * 16);
            const uint4* bfL = (const uint4*)(g_Bfrag + (((ky * 24 + kc) * 2 + 1) * 32 + lane) * 16);
            uint4 bh[4], bl[4];
#pragma unroll
            for (int q = 0; q < 4; q++) { bh[q] = __ldg(&bfH[q]); bl[q] = __ldg(&bfL[q]); }

#pragma unroll
            for (int nt = 0; nt < 8; nt++) {
                uint32_t bh0 = (nt & 1) ? bh[nt >> 1].z : bh[nt >> 1].x;
                uint32_t bh1 = (nt & 1) ? bh[nt >> 1].w : bh[nt >> 1].y;
                uint32_t bl0 = (nt & 1) ? bl[nt >> 1].z : bl[nt >> 1].x;
                uint32_t bl1 = (nt & 1) ? bl[nt >> 1].w : bl[nt >> 1].y;
                mma_bf16(acc[nt], ah0, ah1, ah2, ah3, bh0, bh1);
                mma_bf16(acc[nt], ah0, ah1, ah2, ah3, bl0, bl1);
                mma_bf16(acc[nt], al0, al1, al2, al3, bh0, bh1);
            }
        }
    }

    __syncthreads();
#pragma unroll
    for (int nt = 0; nt < 8; nt++)
#pragma unroll
        for (int h = 0; h < 2; h++)
#pragma unroll
            for (int j = 0; j < 2; j++) {
                int o = nt * 8 + tg * 2 + j;
                int px = wt * 16 + g + h * 8;
                sOut[o * 132 + px] = acc[nt][h * 2 + j];
            }
    __syncthreads();
    for (int i = tid; i < 64 * 32; i += 256) {
        int o = i >> 5, ch = i & 31;
        float4 v = *(const float4*)&sOut[o * 132 + ch * 4];
        float bias = __ldg(&cbias[o]);
        v.x += bias; v.y += bias; v.z += bias; v.w += bias;
        *(float4*)&out[((size_t)(b * 64 + o)) * NPIX + (size_t)y * IMG_W + x0 + ch * 4] = v;
    }
}

// -------------------- launch --------------------
extern "C" void kernel_launch(void* const* d_in, const int* in_sizes, int n_in,
                              void* d_out, int out_size)
{
    (void)in_sizes; (void)n_in; (void)out_size;
    const float* t1  = (const float*)d_in[0];
    const float* t2  = (const float*)d_in[1];
    const float* q1w = (const float*)d_in[2];  const float* q1b = (const float*)d_in[3];
    const float* k1w = (const float*)d_in[4];  const float* k1b = (const float*)d_in[5];
    const float* v1w = (const float*)d_in[6];  const float* v1b = (const float*)d_in[7];
    const float* r1w = (const float*)d_in[8];  const float* r1b = (const float*)d_in[9];
    const float* q2w = (const float*)d_in[10]; const float* q2b = (const float*)d_in[11];
    const float* k2w = (const float*)d_in[12]; const float* k2b = (const float*)d_in[13];
    const float* v2w = (const float*)d_in[14]; const float* v2b = (const float*)d_in[15];
    const float* r2w = (const float*)d_in[16]; const float* r2b = (const float*)d_in[17];
    const float* cw  = (const float*)d_in[18]; const float* cb  = (const float*)d_in[19];

    cudaFuncSetAttribute(pass1_kernel, cudaFuncAttributeMaxDynamicSharedMemorySize, P1_SMEM);
    cudaFuncSetAttribute(pass2_kernel, cudaFuncAttributeMaxDynamicSharedMemorySize, P2_SMEM);
    cudaFuncSetAttribute(conv_kernel, cudaFuncAttributeMaxDynamicSharedMemorySize, CONV_SMEM);

    prep_kernel<<<640, 256>>>(q1w, k1w, v1w, q2w, k2w, v2w, cw);      // launch 0
    dim3 g1(256, 8, 2);
    pass1_kernel<<<g1, 256, P1_SMEM>>>(t1, t2, k1b, v1b, k2b, v2b);   // launch 1
    dim3 gm(8, 2);
    mid_kernel<<<gm, 256>>>(r1w, r2w);                                // launch 2
    pass2_kernel<<<g1, 256, P2_SMEM>>>(t1, t2, q1b, r1b, q2b, r2b);   // launch 3
    dim3 gc(2, 256, 8);
    conv_kernel<<<gc, 256, CONV_SMEM>>>(cb, (float*)d_out);           // launch 4
}

// round 8
// speedup vs baseline: 1.5905x; 1.0336x over previous
#include <cuda_runtime.h>
#include <cuda_bf16.h>
#include <cstdint>

#define NPIX 65536
#define IMG_H 256
#define IMG_W 256
#define NB 8

// ---- device scratch ----
__device__ __nv_bfloat16 g_hi[NB * NPIX * 128];   // NHWC [b][y][x][ci], hi plane
__device__ __nv_bfloat16 g_lo[NB * NPIX * 128];   // lo plane
__device__ uint32_t g_Bfrag[3 * 24 * 2 * 32 * 16];  // conv weight mma frags
__device__ uint32_t g_QKVfrag[3 * 2 * 2 * 4 * 32 * 16]; // [kind q/k/v][br][half][kc][lane][ntj]
__device__ uint32_t g_RMfrag[16 * 2 * 4 * 32 * 16]; // [(br*8+b)][half][kc][lane][ntj]
__device__ float g_mat[2 * NB * 64 * 64];
__device__ float g_ksum[2 * NB * 64];
__device__ float g_vsum[2 * NB * 64];
__device__ float g_rv[2 * NB * 64];
__device__ float g_ksumE[2 * NB * 64];

// ---- mma.sync bf16 helper (m16n8k16, f32 accum) ----
__device__ __forceinline__ void mma_bf16(float* d,
                                         uint32_t a0, uint32_t a1, uint32_t a2, uint32_t a3,
                                         uint32_t b0, uint32_t b1) {
    asm volatile(
        "mma.sync.aligned.m16n8k16.row.col.f32.bf16.bf16.f32 "
        "{%0,%1,%2,%3}, {%4,%5,%6,%7}, {%8,%9}, {%0,%1,%2,%3};"
        : "+f"(d[0]), "+f"(d[1]), "+f"(d[2]), "+f"(d[3])
        : "r"(a0), "r"(a1), "r"(a2), "r"(a3), "r"(b0), "r"(b1));
}

__device__ __forceinline__ void splitbf(float a, float b, uint32_t& h, uint32_t& l) {
    __nv_bfloat16 ha = __float2bfloat16(a), hb = __float2bfloat16(b);
    __nv_bfloat162 hh; hh.x = ha; hh.y = hb;
    h = *(uint32_t*)&hh;
    __nv_bfloat162 ll = __floats2bfloat162_rn(a - __bfloat162float(ha),
                                              b - __bfloat162float(hb));
    l = *(uint32_t*)&ll;
}
__device__ __forceinline__ uint32_t packbf_hi_lo(float a, float b, int half) {
    if (half == 0) {
        __nv_bfloat162 hh; hh.x = __float2bfloat16(a); hh.y = __float2bfloat16(b);
        return *(uint32_t*)&hh;
    }
    __nv_bfloat16 ha = __float2bfloat16(a), hb = __float2bfloat16(b);
    __nv_bfloat162 ll = __floats2bfloat162_rn(a - __bfloat162float(ha),
                                              b - __bfloat162float(hb));
    return *(uint32_t*)&ll;
}

// -------------------- prep (single kernel) --------------------
__global__ void __launch_bounds__(256) prep_kernel(
    const float* __restrict__ q1w, const float* __restrict__ k1w, const float* __restrict__ v1w,
    const float* __restrict__ q2w, const float* __restrict__ k2w, const float* __restrict__ v2w,
    const float* __restrict__ cw)
{
    int nb = blockIdx.x, tid = threadIdx.x;
    if (nb < 256) {
        int idx = nb * 256 + tid;
        g_mat[idx] = 0.f;
        if (idx < 2 * NB * 64) { g_ksum[idx] = 0.f; g_vsum[idx] = 0.f; }
        return;
    }
    if (nb < 544) {
        int i = (nb - 256) * 256 + tid;  // 0..73727
        int ky = i / 24576;
        int rem = i % 24576;
        int kc = rem / 1024;
        int rem2 = rem % 1024;
        int half = rem2 / 512;
        int rem3 = rem2 % 512;
        int lane = rem3 / 16;
        int r4 = rem3 % 16;
        int nt = r4 >> 1, j = r4 & 1;
        int kx = kc >> 3, cc8 = kc & 7;
        int n = nt * 8 + (lane >> 2);
        int ci0 = cc8 * 16 + (lane & 3) * 2 + j * 8;
        float w0 = cw[((n * 128 + ci0) * 3 + ky) * 3 + kx];
        float w1 = cw[((n * 128 + ci0 + 1) * 3 + ky) * 3 + kx];
        g_Bfrag[i] = packbf_hi_lo(w0, w1, half);
        return;
    }
    {
        int t = nb - 544;                // 0..95
        int kind = t / 32;               // 0=q, 1=k, 2=v
        int i = (t % 32) * 256 + tid;    // 0..8191
        int br = i >> 12;
        int r = i & 4095;
        int half = r >> 11;
        int kc = (r >> 9) & 3;
        int lane = (r >> 4) & 31;
        int ntj = r & 15;
        int nt = ntj >> 1, j = ntj & 1;
        int o = nt * 8 + (lane >> 2);
        int c0 = kc * 16 + (lane & 3) * 2 + j * 8;
        const float* w;
        if (kind == 0) w = br ? q2w : q1w;
        else if (kind == 1) w = br ? k2w : k1w;
        else w = br ? v2w : v1w;
        float w0 = w[o * 64 + c0];
        float w1 = w[o * 64 + c0 + 1];
        g_QKVfrag[kind * 8192 + i] = packbf_hi_lo(w0, w1, half);
    }
}

// -------------------- pass 1: mma K,V proj + mma stats --------------------
// grid (256, 8, 2), 256 thr = 8 warps. Tile: 256 px.
// smem: X fp32 [64][260] | Kn fp32 [64][260] | V fp32 [64][260]
#define P1_SMEM (3 * 66560)

__global__ void __launch_bounds__(256) pass1_kernel(
    const float* __restrict__ x1, const float* __restrict__ x2,
    const float* __restrict__ kb1, const float* __restrict__ vb1,
    const float* __restrict__ kb2, const float* __restrict__ vb2)
{
    extern __shared__ __align__(16) float dsm1[];
    float* X  = dsm1;
    float* Kp = dsm1 + 16640;
    float* Vp = dsm1 + 33280;

    const int tid = threadIdx.x;
    const int lane = tid & 31, wt = tid >> 5;
    const int g = lane >> 2, tg = lane & 3;
    const int b = blockIdx.y, br = blockIdx.z;
    const int p0 = blockIdx.x * 256;
    const float* xb = (br ? x2 : x1) + (size_t)b * 64 * NPIX;
    const float* kb = br ? kb2 : kb1;
    const float* vb = br ? vb2 : vb1;

    for (int i = tid; i < 4096; i += 256) {
        int c = i >> 6, q4 = i & 63;
        *(float4*)&X[c * 260 + q4 * 4] = *(const float4*)&xb[(size_t)c * NPIX + p0 + q4 * 4];
    }
    __syncthreads();

    // ---- projections: kv=0 -> K (normalized at park), kv=1 -> V ----
#pragma unroll 1
    for (int kv = 0; kv < 2; kv++) {
        const uint32_t* wf = g_QKVfrag + (kv + 1) * 8192 + br * 4096;
        const float* bias = kv ? vb : kb;
        float* park = kv ? Vp : Kp;

        float acc[2][8][4];
#pragma unroll
        for (int mt = 0; mt < 2; mt++)
#pragma unroll
            for (int nt = 0; nt < 8; nt++)
#pragma unroll
                for (int k = 0; k < 4; k++) acc[mt][nt][k] = 0.f;

#pragma unroll
        for (int kc = 0; kc < 4; kc++) {
            const uint4* WH = (const uint4*)&wf[(0 * 4 + kc) * 512 + lane * 16];
            const uint4* WL = (const uint4*)&wf[(1 * 4 + kc) * 512 + lane * 16];
            uint4 bh[4], bl[4];
#pragma unroll
            for (int q = 0; q < 4; q++) { bh[q] = __ldg(&WH[q]); bl[q] = __ldg(&WL[q]); }
            int c0 = kc * 16 + tg * 2;
#pragma unroll
            for (int mt = 0; mt < 2; mt++) {
                int r0 = wt * 32 + mt * 16 + g;
                float v00 = X[(c0 + 0) * 260 + r0], v01 = X[(c0 + 1) * 260 + r0];
                float v08 = X[(c0 + 8) * 260 + r0], v09 = X[(c0 + 9) * 260 + r0];
                float v10 = X[(c0 + 0) * 260 + r0 + 8], v11 = X[(c0 + 1) * 260 + r0 + 8];
                float v18 = X[(c0 + 8) * 260 + r0 + 8], v19 = X[(c0 + 9) * 260 + r0 + 8];
                uint32_t ah0, ah1, ah2, ah3, al0, al1, al2, al3;
                splitbf(v00, v01, ah0, al0);
                splitbf(v10, v11, ah1, al1);
                splitbf(v08, v09, ah2, al2);
                splitbf(v18, v19, ah3, al3);
#pragma unroll
                for (int nt = 0; nt < 8; nt++) {
                    uint32_t b0h = (nt & 1) ? bh[nt >> 1].z : bh[nt >> 1].x;
                    uint32_t b1h = (nt & 1) ? bh[nt >> 1].w : bh[nt >> 1].y;
                    uint32_t b0l = (nt & 1) ? bl[nt >> 1].z : bl[nt >> 1].x;
                    uint32_t b1l = (nt & 1) ? bl[nt >> 1].w : bl[nt >> 1].y;
                    mma_bf16(acc[mt][nt], ah0, ah1, ah2, ah3, b0h, b1h);
                    mma_bf16(acc[mt][nt], ah0, ah1, ah2, ah3, b0l, b1l);
                    mma_bf16(acc[mt][nt], al0, al1, al2, al3, b0h, b1h);
                }
            }
        }

        // add bias
        float bv[16];
#pragma unroll
        for (int nt = 0; nt < 8; nt++) {
            bv[nt * 2 + 0] = __ldg(&bias[nt * 8 + tg * 2 + 0]);
            bv[nt * 2 + 1] = __ldg(&bias[nt * 8 + tg * 2 + 1]);
        }
#pragma unroll
        for (int mt = 0; mt < 2; mt++)
#pragma unroll
            for (int nt = 0; nt < 8; nt++) {
#pragma unroll
                for (int k = 0; k < 4; k++) acc[mt][nt][k] += bv[nt * 2 + (k & 1)];
            }

        if (kv == 0) {
            // per-px 1/||K|| via quad shfl; park normalized
#pragma unroll
            for (int mt = 0; mt < 2; mt++)
#pragma unroll
                for (int h = 0; h < 2; h++) {
                    float s = 0.f;
#pragma unroll
                    for (int nt = 0; nt < 8; nt++) {
                        float a = acc[mt][nt][h * 2], c = acc[mt][nt][h * 2 + 1];
                        s = fmaf(a, a, s); s = fmaf(c, c, s);
                    }
                    s += __shfl_xor_sync(0xffffffffu, s, 1);
                    s += __shfl_xor_sync(0xffffffffu, s, 2);
                    float inv = rsqrtf(s);
                    int px = wt * 32 + mt * 16 + g + h * 8;
#pragma unroll
                    for (int nt = 0; nt < 8; nt++) {
#pragma unroll
                        for (int j = 0; j < 2; j++) {
                            int o = nt * 8 + tg * 2 + j;
                            park[o * 260 + px] = acc[mt][nt][h * 2 + j] * inv;
                        }
                    }
                }
        } else {
#pragma unroll
            for (int mt = 0; mt < 2; mt++)
#pragma unroll
                for (int h = 0; h < 2; h++) {
                    int px = wt * 32 + mt * 16 + g + h * 8;
#pragma unroll
                    for (int nt = 0; nt < 8; nt++) {
#pragma unroll
                        for (int j = 0; j < 2; j++) {
                            int o = nt * 8 + tg * 2 + j;
                            park[o * 260 + px] = acc[mt][nt][h * 2 + j];
                        }
                    }
                }
        }
    }
    __syncthreads();

    // ---- stats GEMM: matrix += Kn * V^T  (M=64 kch, N=64 vch, K=256 px) ----
    const int mt4 = wt >> 1;
    const int nh = wt & 1;
    float acc2[4][4];
#pragma unroll
    for (int nt = 0; nt < 4; nt++)
#pragma unroll
        for (int k = 0; k < 4; k++) acc2[nt][k] = 0.f;
    float ksg = 0.f, ksg8 = 0.f;
    float vs[4] = {0.f, 0.f, 0.f, 0.f};

#pragma unroll 2
    for (int kc = 0; kc < 16; kc++) {
        int px0 = kc * 16 + tg * 2;
        int m0 = mt4 * 16 + g;
        float2 k0 = *(const float2*)&Kp[m0 * 260 + px0];
        float2 k8 = *(const float2*)&Kp[m0 * 260 + px0 + 8];
        float2 k10 = *(const float2*)&Kp[(m0 + 8) * 260 + px0];
        float2 k18 = *(const float2*)&Kp[(m0 + 8) * 260 + px0 + 8];
        uint32_t a0h, a0l, a1h, a1l, a2h, a2l, a3h, a3l;
        splitbf(k0.x, k0.y, a0h, a0l);
        splitbf(k10.x, k10.y, a1h, a1l);
        splitbf(k8.x, k8.y, a2h, a2l);
        splitbf(k18.x, k18.y, a3h, a3l);
        if (nh == 0) {
            ksg += k0.x + k0.y + k8.x + k8.y;
            ksg8 += k10.x + k10.y + k18.x + k18.y;
        }
#pragma unroll
        for (int nt = 0; nt < 4; nt++) {
            int n = (nh * 4 + nt) * 8 + g;
            float2 b0 = *(const float2*)&Vp[n * 260 + px0];
            float2 b8 = *(const float2*)&Vp[n * 260 + px0 + 8];
            if (mt4 == 0) vs[nt] += b0.x + b0.y + b8.x + b8.y;
            uint32_t bh0, bl0, bh1, bl1;
            splitbf(b0.x, b0.y, bh0, bl0);
            splitbf(b8.x, b8.y, bh1, bl1);
            mma_bf16(acc2[nt], a0h, a1h, a2h, a3h, bh0, bh1);
            mma_bf16(acc2[nt], a0h, a1h, a2h, a3h, bl0, bl1);
            mma_bf16(acc2[nt], a0l, a1l, a2l, a3l, bh0, bh1);
        }
    }

    float* mat = g_mat + ((size_t)br * NB + b) * 4096;
#pragma unroll
    for (int nt = 0; nt < 4; nt++) {
#pragma unroll
        for (int k = 0; k < 4; k++) {
            int m = mt4 * 16 + g + ((k >= 2) ? 8 : 0);
            int n = (nh * 4 + nt) * 8 + tg * 2 + (k & 1);
            atomicAdd(&mat[m * 64 + n], acc2[nt][k]);
        }
    }
    if (nh == 0) {
        ksg += __shfl_xor_sync(0xffffffffu, ksg, 1);
        ksg += __shfl_xor_sync(0xffffffffu, ksg, 2);
        ksg8 += __shfl_xor_sync(0xffffffffu, ksg8, 1);
        ksg8 += __shfl_xor_sync(0xffffffffu, ksg8, 2);
        if (tg == 0) {
            float* kp = g_ksum + ((size_t)br * NB + b) * 64;
            atomicAdd(&kp[mt4 * 16 + g], ksg);
            atomicAdd(&kp[mt4 * 16 + g + 8], ksg8);
        }
    }
    if (mt4 == 0) {
#pragma unroll
        for (int nt = 0; nt < 4; nt++) {
            float v = vs[nt];
            v += __shfl_xor_sync(0xffffffffu, v, 1);
            v += __shfl_xor_sync(0xffffffffu, v, 2);
            if (tg == 0)
                atomicAdd(&g_vsum[((size_t)br * NB + b) * 64 + (nh * 4 + nt) * 8 + g], v);
        }
    }
}

// -------------------- mid: RM frags, rv, ksumE --------------------
__global__ void __launch_bounds__(256) mid_kernel(const float* __restrict__ rw1,
                                                  const float* __restrict__ rw2)
{
    __shared__ float sMat[4096];
    __shared__ float sRw[4096];
    const int tid = threadIdx.x;
    const int b = blockIdx.x, br = blockIdx.y;
    const float* rw = br ? rw2 : rw1;
    const float* mat = g_mat + ((size_t)br * NB + b) * 4096;
#pragma unroll
    for (int r = 0; r < 16; r++) {
        int i = tid + r * 256;
        sMat[i] = mat[i];
        sRw[i] = rw[i];
    }
    __syncthreads();
    const int ty = tid >> 4, tx = tid & 15;
    float acc[4][4];
#pragma unroll
    for (int i = 0; i < 4; i++)
#pragma unroll
        for (int j = 0; j < 4; j++) acc[i][j] = 0.f;
#pragma unroll 4
    for (int c = 0; c < 64; c++) {
        float a[4], w[4];
#pragma unroll
        for (int i = 0; i < 4; i++) a[i] = sMat[(ty * 4 + i) * 64 + c];
#pragma unroll
        for (int j = 0; j < 4; j++) w[j] = sRw[(tx * 4 + j) * 64 + c];
#pragma unroll
        for (int i = 0; i < 4; i++)
#pragma unroll
            for (int j = 0; j < 4; j++) acc[i][j] += a[i] * w[j];
    }
    if (tid < 64) {
        const float* vsump = g_vsum + ((size_t)br * NB + b) * 64;
        float s = 0.f;
        for (int c = 0; c < 64; c++) s += sRw[tid * 64 + c] * vsump[c];
        g_rv[((size_t)br * NB + b) * 64 + tid] = s;
        g_ksumE[((size_t)br * NB + b) * 64 + tid] =
            g_ksum[((size_t)br * NB + b) * 64 + tid] + 1e-6f;
    }
    __syncthreads();
#pragma unroll
    for (int i = 0; i < 4; i++)
#pragma unroll
        for (int j = 0; j < 4; j++)
            sMat[(tx * 4 + j) * 64 + (ty * 4 + i)] = acc[i][j];
    __syncthreads();
    uint32_t* dst = g_RMfrag + (size_t)(br * 8 + b) * 4096;
    for (int t = tid; t < 4096; t += 256) {
        int half = t >> 11;
        int lane = (t >> 4) & 31;
        int ntj = t & 15;
        int nt = ntj >> 1, j = ntj & 1;
        int kc = (t >> 9) & 3;
        int o = nt * 8 + (lane >> 2);
        int m0 = kc * 16 + (lane & 3) * 2 + j * 8;
        float w0 = sMat[o * 64 + m0];
        float w1 = sMat[o * 64 + m0 + 1];
        dst[t] = packbf_hi_lo(w0, w1, half);
    }
}

// -------------------- pass 2: register-resident double GEMM --------------------
// grid (256, 8, 2), 256 thr = 8 warps. Tile: 256 px.
// smem: X fp32 [64][260] (66560 B), reused for output staging.
#define P2_SMEM 66560

__global__ void __launch_bounds__(256) pass2_kernel(
    const float* __restrict__ x1, const float* __restrict__ x2,
    const float* __restrict__ qb1, const float* __restrict__ rb1,
    const float* __restrict__ qb2, const float* __restrict__ rb2)
{
    extern __shared__ __align__(16) float dsm[];

    const int tid = threadIdx.x;
    const int lane = tid & 31, wt = tid >> 5;
    const int g = lane >> 2, tg = lane & 3;
    const int b = blockIdx.y, br = blockIdx.z;
    const int p0 = blockIdx.x * 256;
    const float* xb = (br ? x2 : x1) + (size_t)b * 64 * NPIX;
    const float* qb = br ? qb2 : qb1;
    const float* rb = br ? rb2 : rb1;
    const float* ksE = g_ksumE + ((size_t)br * NB + b) * 64;
    const float* rvp = g_rv + ((size_t)br * NB + b) * 64;

    for (int i = tid; i < 4096; i += 256) {
        int c = i >> 6, q4 = i & 63;
        *(float4*)&dsm[c * 260 + q4 * 4] = *(const float4*)&xb[(size_t)c * NPIX + p0 + q4 * 4];
    }
    __syncthreads();

    // ---- phase A: Q = Wq*x + qb ----
    float acc[2][8][4];
#pragma unroll
    for (int mt = 0; mt < 2; mt++)
#pragma unroll
        for (int nt = 0; nt < 8; nt++)
#pragma unroll
            for (int k = 0; k < 4; k++) acc[mt][nt][k] = 0.f;

#pragma unroll
    for (int kc = 0; kc < 4; kc++) {
        const uint4* WH = (const uint4*)&g_QKVfrag[((br * 2 + 0) * 4 + kc) * 512 + lane * 16];
        const uint4* WL = (const uint4*)&g_QKVfrag[((br * 2 + 1) * 4 + kc) * 512 + lane * 16];
        uint4 bh[4], bl[4];
#pragma unroll
        for (int q = 0; q < 4; q++) { bh[q] = __ldg(&WH[q]); bl[q] = __ldg(&WL[q]); }
        int c0 = kc * 16 + tg * 2;
#pragma unroll
        for (int mt = 0; mt < 2; mt++) {
            int r0 = wt * 32 + mt * 16 + g;
            float v00 = dsm[(c0 + 0) * 260 + r0], v01 = dsm[(c0 + 1) * 260 + r0];
            float v08 = dsm[(c0 + 8) * 260 + r0], v09 = dsm[(c0 + 9) * 260 + r0];
            float v10 = dsm[(c0 + 0) * 260 + r0 + 8], v11 = dsm[(c0 + 1) * 260 + r0 + 8];
            float v18 = dsm[(c0 + 8) * 260 + r0 + 8], v19 = dsm[(c0 + 9) * 260 + r0 + 8];
            uint32_t ah0, ah1, ah2, ah3, al0, al1, al2, al3;
            splitbf(v00, v01, ah0, al0);
            splitbf(v10, v11, ah1, al1);
            splitbf(v08, v09, ah2, al2);
            splitbf(v18, v19, ah3, al3);
#pragma unroll
            for (int nt = 0; nt < 8; nt++) {
                uint32_t b0h = (nt & 1) ? bh[nt >> 1].z : bh[nt >> 1].x;
                uint32_t b1h = (nt & 1) ? bh[nt >> 1].w : bh[nt >> 1].y;
                uint32_t b0l = (nt & 1) ? bl[nt >> 1].z : bl[nt >> 1].x;
                uint32_t b1l = (nt & 1) ? bl[nt >> 1].w : bl[nt >> 1].y;
                mma_bf16(acc[mt][nt], ah0, ah1, ah2, ah3, b0h, b1h);
                mma_bf16(acc[mt][nt], ah0, ah1, ah2, ah3, b0l, b1l);
                mma_bf16(acc[mt][nt], al0, al1, al2, al3, b0h, b1h);
            }
        }
    }
    __syncthreads();   // X dead; smem free for staging

    // add qb; load ksE for this thread's channels
    float kse[16];
#pragma unroll
    for (int nt = 0; nt < 8; nt++) {
        float q0 = __ldg(&qb[nt * 8 + tg * 2 + 0]);
        float q1 = __ldg(&qb[nt * 8 + tg * 2 + 1]);
        kse[nt * 2 + 0] = __ldg(&ksE[nt * 8 + tg * 2 + 0]);
        kse[nt * 2 + 1] = __ldg(&ksE[nt * 8 + tg * 2 + 1]);
#pragma unroll
        for (int mt = 0; mt < 2; mt++) {
            acc[mt][nt][0] += q0; acc[mt][nt][1] += q1;
            acc[mt][nt][2] += q0; acc[mt][nt][3] += q1;
        }
    }

    // per-px inv + den via quad shfl
    float invv[2][2], denn[2][2];
#pragma unroll
    for (int mt = 0; mt < 2; mt++)
#pragma unroll
        for (int h = 0; h < 2; h++) {
            float s = 0.f, d = 0.f;
#pragma unroll
            for (int nt = 0; nt < 8; nt++) {
                float a = acc[mt][nt][h * 2], c = acc[mt][nt][h * 2 + 1];
                s = fmaf(a, a, s); s = fmaf(c, c, s);
                d = fmaf(a, kse[nt * 2], d); d = fmaf(c, kse[nt * 2 + 1], d);
            }
            s += __shfl_xor_sync(0xffffffffu, s, 1);
            s += __shfl_xor_sync(0xffffffffu, s, 2);
            d += __shfl_xor_sync(0xffffffffu, d, 1);
            d += __shfl_xor_sync(0xffffffffu, d, 2);
            float inv = rsqrtf(s);
            invv[mt][h] = inv;
            denn[mt][h] = 1.f / (65536.f + inv * d);
        }

    // ---- phase B from registers: out = RM * (Q * inv) ----
    float acc2[2][8][4];
#pragma unroll
    for (int mt = 0; mt < 2; mt++)
#pragma unroll
        for (int nt = 0; nt < 8; nt++)
#pragma unroll
            for (int k = 0; k < 4; k++) acc2[mt][nt][k] = 0.f;

    const uint32_t* rmbase = g_RMfrag + (size_t)(br * 8 + b) * 4096;
#pragma unroll
    for (int kc = 0; kc < 4; kc++) {
        const uint4* RH = (const uint4*)&rmbase[(0 * 4 + kc) * 512 + lane * 16];
        const uint4* RL = (const uint4*)&rmbase[(1 * 4 + kc) * 512 + lane * 16];
        uint4 bh[4], bl[4];
#pragma unroll
        for (int q = 0; q < 4; q++) { bh[q] = __ldg(&RH[q]); bl[q] = __ldg(&RL[q]); }
#pragma unroll
        for (int mt = 0; mt < 2; mt++) {
            float i0 = invv[mt][0], i1 = invv[mt][1];
            uint32_t ah0, ah1, ah2, ah3, al0, al1, al2, al3;
            splitbf(acc[mt][2 * kc][0] * i0, acc[mt][2 * kc][1] * i0, ah0, al0);
            splitbf(acc[mt][2 * kc][2] * i1, acc[mt][2 * kc][3] * i1, ah1, al1);
            splitbf(acc[mt][2 * kc + 1][0] * i0, acc[mt][2 * kc + 1][1] * i0, ah2, al2);
            splitbf(acc[mt][2 * kc + 1][2] * i1, acc[mt][2 * kc + 1][3] * i1, ah3, al3);
#pragma unroll
            for (int nt = 0; nt < 8; nt++) {
                uint32_t b0h = (nt & 1) ? bh[nt >> 1].z : bh[nt >> 1].x;
                uint32_t b1h = (nt & 1) ? bh[nt >> 1].w : bh[nt >> 1].y;
                uint32_t b0l = (nt & 1) ? bl[nt >> 1].z : bl[nt >> 1].x;
                uint32_t b1l = (nt & 1) ? bl[nt >> 1].w : bl[nt >> 1].y;
                mma_bf16(acc2[mt][nt], ah0, ah1, ah2, ah3, b0h, b1h);
                mma_bf16(acc2[mt][nt], ah0, ah1, ah2, ah3, b0l, b1l);
                mma_bf16(acc2[mt][nt], al0, al1, al2, al3, b0h, b1h);
            }
        }
    }

    // epilogue: out = den*(rv + acc2) + rb -> bf16 hi/lo planes [px][64] in smem
    float rvv[16], rbv[16];
#pragma unroll
    for (int nt = 0; nt < 8; nt++) {
        rvv[nt * 2 + 0] = __ldg(&rvp[nt * 8 + tg * 2 + 0]);
        rvv[nt * 2 + 1] = __ldg(&rvp[nt * 8 + tg * 2 + 1]);
        rbv[nt * 2 + 0] = __ldg(&rb[nt * 8 + tg * 2 + 0]);
        rbv[nt * 2 + 1] = __ldg(&rb[nt * 8 + tg * 2 + 1]);
    }
    __nv_bfloat16* sH = (__nv_bfloat16*)dsm;
    __nv_bfloat16* sL = sH + 16384;
#pragma unroll
    for (int mt = 0; mt < 2; mt++) {
#pragma unroll
        for (int h = 0; h < 2; h++) {
            int r = wt * 32 + mt * 16 + g + h * 8;
            float den = denn[mt][h];
#pragma unroll
            for (int nt = 0; nt < 8; nt++) {
#pragma unroll
                for (int j = 0; j < 2; j++) {
                    int o = nt * 8 + tg * 2 + j;
                    float v = den * (rvv[nt * 2 + j] + acc2[mt][nt][h * 2 + j]) + rbv[nt * 2 + j];
                    __nv_bfloat16 hh = __float2bfloat16(v);
                    __nv_bfloat16 ll = __float2bfloat16(v - __bfloat162float(hh));
                    sH[r * 64 + o] = hh;
                    sL[r * 64 + o] = ll;
                }
            }
        }
    }
    __syncthreads();

    const char* sbase = (const char*)dsm;
    for (int u = tid; u < 4096; u += 256) {
        int plane = u >> 11;
        int rest = u & 2047;
        int px = rest >> 3, q = rest & 7;
        uint4 val = *(const uint4*)(sbase + plane * 32768 + px * 128 + q * 16);
        __nv_bfloat16* dst = plane ? g_lo : g_hi;
        *(uint4*)&dst[((size_t)(b * NPIX + p0 + px)) * 128 + br * 64 + q * 8] = val;
    }
}

// -------------------- conv: mma.sync bf16-split implicit GEMM (unchanged) ---------
#define STRIP_STRIDE 272
#define STRIP_BYTES (130 * STRIP_STRIDE)
#define CONV_SMEM (2 * STRIP_BYTES)

__global__ void __launch_bounds__(256) conv_kernel(const float* __restrict__ cbias,
                                                   float* __restrict__ out)
{
    extern __shared__ __align__(16) char dsmc[];
    char* sHi = dsmc;
    char* sLo = dsmc + STRIP_BYTES;
    float* sOut = (float*)dsmc;

    const int tid = threadIdx.x;
    const int lane = tid & 31, wt = tid >> 5;
    const int x0 = blockIdx.x * 128, y = blockIdx.y, b = blockIdx.z;

    float acc[8][4];
#pragma unroll
    for (int nt = 0; nt < 8; nt++)
#pragma unroll
        for (int j = 0; j < 4; j++) acc[nt][j] = 0.f;

    const int g = lane >> 2, tg = lane & 3;
    const uint32_t aOff = (wt * 16 + g) * STRIP_STRIDE + tg * 4;

    for (int ky = 0; ky < 3; ky++) {
        int yy = y + ky - 1;
        bool yok = (yy >= 0 && yy < IMG_H);
        __syncthreads();
        if (yok) {
            size_t rowbase = ((size_t)b * NPIX + (size_t)yy * IMG_W) * 128;
            for (int i = tid; i < 130 * 16; i += 256) {
                int row = i >> 4, ch = i & 15;
                int px = x0 + row - 1;
                uint4 vh = make_uint4(0u, 0u, 0u, 0u);
                uint4 vl = make_uint4(0u, 0u, 0u, 0u);
                if (px >= 0 && px < IMG_W) {
                    size_t gi = rowbase + (size_t)px * 128 + ch * 8;
                    vh = *(const uint4*)&g_hi[gi];
                    vl = *(const uint4*)&g_lo[gi];
                }
                *(uint4*)(sHi + row * STRIP_STRIDE + ch * 16) = vh;
                *(uint4*)(sLo + row * STRIP_STRIDE + ch * 16) = vl;
            }
        }
        __syncthreads();
        if (!yok) continue;

#pragma unroll 1
        for (int kc = 0; kc < 24; kc++) {
            int kx = kc >> 3, cc8 = kc & 7;
            uint32_t r0 = aOff + kx * STRIP_STRIDE + cc8 * 32;
            uint32_t ah0 = *(const uint32_t*)(sHi + r0);
            uint32_t ah1 = *(const uint32_t*)(sHi + r0 + 8 * STRIP_STRIDE);
            uint32_t ah2 = *(const uint32_t*)(sHi + r0 + 16);
            uint32_t ah3 = *(const uint32_t*)(sHi + r0 + 8 * STRIP_STRIDE + 16);
            uint32_t al0 = *(const uint32_t*)(sLo + r0);
            uint32_t al1 = *(const uint32_t*)(sLo + r0 + 8 * STRIP_STRIDE);
            uint32_t al2 = *(const uint32_t*)(sLo + r0 + 16);
            uint32_t al3 = *(const uint32_t*)(sLo + r0 + 8 * STRIP_STRIDE + 16);

            const uint4* bfH = (const uint4*)(g_Bfrag + (((ky * 24 + kc) * 2 + 0) * 32 + lane) * 16);
            const uint4* bfL = (const uint4*)(g_Bfrag + (((ky * 24 + kc) * 2 + 1) * 32 + lane) * 16);
            uint4 bh[4], bl[4];
#pragma unroll
            for (int q = 0; q < 4; q++) { bh[q] = __ldg(&bfH[q]); bl[q] = __ldg(&bfL[q]); }

#pragma unroll
            for (int nt = 0; nt < 8; nt++) {
                uint32_t bh0 = (nt & 1) ? bh[nt >> 1].z : bh[nt >> 1].x;
                uint32_t bh1 = (nt & 1) ? bh[nt >> 1].w : bh[nt >> 1].y;
                uint32_t bl0 = (nt & 1) ? bl[nt >> 1].z : bl[nt >> 1].x;
                uint32_t bl1 = (nt & 1) ? bl[nt >> 1].w : bl[nt >> 1].y;
                mma_bf16(acc[nt], ah0, ah1, ah2, ah3, bh0, bh1);
                mma_bf16(acc[nt], ah0, ah1, ah2, ah3, bl0, bl1);
                mma_bf16(acc[nt], al0, al1, al2, al3, bh0, bh1);
            }
        }
    }

    __syncthreads();
#pragma unroll
    for (int nt = 0; nt < 8; nt++)
#pragma unroll
        for (int h = 0; h < 2; h++)
#pragma unroll
            for (int j = 0; j < 2; j++) {
                int o = nt * 8 + tg * 2 + j;
                int px = wt * 16 + g + h * 8;
                sOut[o * 132 + px] = acc[nt][h * 2 + j];
            }
    __syncthreads();
    for (int i = tid; i < 64 * 32; i += 256) {
        int o = i >> 5, ch = i & 31;
        float4 v = *(const float4*)&sOut[o * 132 + ch * 4];
        float bias = __ldg(&cbias[o]);
        v.x += bias; v.y += bias; v.z += bias; v.w += bias;
        *(float4*)&out[((size_t)(b * 64 + o)) * NPIX + (size_t)y * IMG_W + x0 + ch * 4] = v;
    }
}

// -------------------- launch --------------------
extern "C" void kernel_launch(void* const* d_in, const int* in_sizes, int n_in,
                              void* d_out, int out_size)
{
    (void)in_sizes; (void)n_in; (void)out_size;
    const float* t1  = (const float*)d_in[0];
    const float* t2  = (const float*)d_in[1];
    const float* q1w = (const float*)d_in[2];  const float* q1b = (const float*)d_in[3];
    const float* k1w = (const float*)d_in[4];  const float* k1b = (const float*)d_in[5];
    const float* v1w = (const float*)d_in[6];  const float* v1b = (const float*)d_in[7];
    const float* r1w = (const float*)d_in[8];  const float* r1b = (const float*)d_in[9];
    const float* q2w = (const float*)d_in[10]; const float* q2b = (const float*)d_in[11];
    const float* k2w = (const float*)d_in[12]; const float* k2b = (const float*)d_in[13];
    const float* v2w = (const float*)d_in[14]; const float* v2b = (const float*)d_in[15];
    const float* r2w = (const float*)d_in[16]; const float* r2b = (const float*)d_in[17];
    const float* cw  = (const float*)d_in[18]; const float* cb  = (const float*)d_in[19];

    cudaFuncSetAttribute(pass1_kernel, cudaFuncAttributeMaxDynamicSharedMemorySize, P1_SMEM);
    cudaFuncSetAttribute(pass2_kernel, cudaFuncAttributeMaxDynamicSharedMemorySize, P2_SMEM);
    cudaFuncSetAttribute(conv_kernel, cudaFuncAttributeMaxDynamicSharedMemorySize, CONV_SMEM);

    prep_kernel<<<640, 256>>>(q1w, k1w, v1w, q2w, k2w, v2w, cw);      // launch 0
    dim3 g1(256, 8, 2);
    pass1_kernel<<<g1, 256, P1_SMEM>>>(t1, t2, k1b, v1b, k2b, v2b);   // launch 1
    dim3 gm(8, 2);
    mid_kernel<<<gm, 256>>>(r1w, r2w);                                // launch 2
    pass2_kernel<<<g1, 256, P2_SMEM>>>(t1, t2, q1b, r1b, q2b, r2b);   // launch 3
    dim3 gc(2, 256, 8);
    conv_kernel<<<gc, 256, CONV_SMEM>>>(cb, (float*)d_out);           // launch 4
}

// round 9
// speedup vs baseline: 1.6605x; 1.0440x over previous
#include <cuda_runtime.h>
#include <cuda_bf16.h>
#include <cstdint>

#define NPIX 65536
#define IMG_H 256
#define IMG_W 256
#define NB 8

// ---- device scratch ----
__device__ __nv_bfloat16 g_hi[NB * NPIX * 128];   // NHWC [b][y][x][ci], hi plane
__device__ __nv_bfloat16 g_lo[NB * NPIX * 128];   // lo plane
__device__ uint32_t g_Bfrag[3 * 24 * 2 * 32 * 16];  // conv weight mma frags
__device__ uint32_t g_QKVfrag[3 * 2 * 2 * 4 * 32 * 16]; // [kind q/k/v][br][half][kc][lane][ntj]
__device__ uint32_t g_RMfrag[16 * 2 * 4 * 32 * 16]; // [(br*8+b)][half][kc][lane][ntj]
__device__ float g_mat[2 * NB * 64 * 64];
__device__ float g_ksum[2 * NB * 64];
__device__ float g_vsum[2 * NB * 64];
__device__ float g_rv[2 * NB * 64];
__device__ float g_ksumE[2 * NB * 64];

// ---- mma.sync bf16 helper (m16n8k16, f32 accum) ----
__device__ __forceinline__ void mma_bf16(float* d,
                                         uint32_t a0, uint32_t a1, uint32_t a2, uint32_t a3,
                                         uint32_t b0, uint32_t b1) {
    asm volatile(
        "mma.sync.aligned.m16n8k16.row.col.f32.bf16.bf16.f32 "
        "{%0,%1,%2,%3}, {%4,%5,%6,%7}, {%8,%9}, {%0,%1,%2,%3};"
        : "+f"(d[0]), "+f"(d[1]), "+f"(d[2]), "+f"(d[3])
        : "r"(a0), "r"(a1), "r"(a2), "r"(a3), "r"(b0), "r"(b1));
}

__device__ __forceinline__ void splitbf(float a, float b, uint32_t& h, uint32_t& l) {
    __nv_bfloat16 ha = __float2bfloat16(a), hb = __float2bfloat16(b);
    __nv_bfloat162 hh; hh.x = ha; hh.y = hb;
    h = *(uint32_t*)&hh;
    __nv_bfloat162 ll = __floats2bfloat162_rn(a - __bfloat162float(ha),
                                              b - __bfloat162float(hb));
    l = *(uint32_t*)&ll;
}
__device__ __forceinline__ uint32_t packbf_hi_lo(float a, float b, int half) {
    if (half == 0) {
        __nv_bfloat162 hh; hh.x = __float2bfloat16(a); hh.y = __float2bfloat16(b);
        return *(uint32_t*)&hh;
    }
    __nv_bfloat16 ha = __float2bfloat16(a), hb = __float2bfloat16(b);
    __nv_bfloat162 ll = __floats2bfloat162_rn(a - __bfloat162float(ha),
                                              b - __bfloat162float(hb));
    return *(uint32_t*)&ll;
}

// -------------------- prep (single kernel) --------------------
__global__ void __launch_bounds__(256) prep_kernel(
    const float* __restrict__ q1w, const float* __restrict__ k1w, const float* __restrict__ v1w,
    const float* __restrict__ q2w, const float* __restrict__ k2w, const float* __restrict__ v2w,
    const float* __restrict__ cw)
{
    int nb = blockIdx.x, tid = threadIdx.x;
    if (nb < 256) {
        int idx = nb * 256 + tid;
        g_mat[idx] = 0.f;
        if (idx < 2 * NB * 64) { g_ksum[idx] = 0.f; g_vsum[idx] = 0.f; }
        return;
    }
    if (nb < 544) {
        int i = (nb - 256) * 256 + tid;  // 0..73727
        int ky = i / 24576;
        int rem = i % 24576;
        int kc = rem / 1024;
        int rem2 = rem % 1024;
        int half = rem2 / 512;
        int rem3 = rem2 % 512;
        int lane = rem3 / 16;
        int r4 = rem3 % 16;
        int nt = r4 >> 1, j = r4 & 1;
        int kx = kc >> 3, cc8 = kc & 7;
        int n = nt * 8 + (lane >> 2);
        int ci0 = cc8 * 16 + (lane & 3) * 2 + j * 8;
        float w0 = cw[((n * 128 + ci0) * 3 + ky) * 3 + kx];
        float w1 = cw[((n * 128 + ci0 + 1) * 3 + ky) * 3 + kx];
        g_Bfrag[i] = packbf_hi_lo(w0, w1, half);
        return;
    }
    {
        int t = nb - 544;                // 0..95
        int kind = t / 32;               // 0=q, 1=k, 2=v
        int i = (t % 32) * 256 + tid;    // 0..8191
        int br = i >> 12;
        int r = i & 4095;
        int half = r >> 11;
        int kc = (r >> 9) & 3;
        int lane = (r >> 4) & 31;
        int ntj = r & 15;
        int nt = ntj >> 1, j = ntj & 1;
        int o = nt * 8 + (lane >> 2);
        int c0 = kc * 16 + (lane & 3) * 2 + j * 8;
        const float* w;
        if (kind == 0) w = br ? q2w : q1w;
        else if (kind == 1) w = br ? k2w : k1w;
        else w = br ? v2w : v1w;
        float w0 = w[o * 64 + c0];
        float w1 = w[o * 64 + c0 + 1];
        g_QKVfrag[kind * 8192 + i] = packbf_hi_lo(w0, w1, half);
    }
}

// -------------------- pass 1: mma K,V proj + mma stats --------------------
// grid (512, 8, 2), 256 thr = 8 warps, 2 CTAs/SM. Tile: 128 px.
// smem: X fp32 [64][132] | Kn [64][132] | V [64][132] = 101376 B
#define P1_SMEM (3 * 33792)

__global__ void __launch_bounds__(256, 2) pass1_kernel(
    const float* __restrict__ x1, const float* __restrict__ x2,
    const float* __restrict__ kb1, const float* __restrict__ vb1,
    const float* __restrict__ kb2, const float* __restrict__ vb2)
{
    extern __shared__ __align__(16) float dsm1[];
    float* X  = dsm1;
    float* Kp = dsm1 + 8448;
    float* Vp = dsm1 + 16896;

    const int tid = threadIdx.x;
    const int lane = tid & 31, wt = tid >> 5;
    const int g = lane >> 2, tg = lane & 3;
    const int b = blockIdx.y, br = blockIdx.z;
    const int p0 = blockIdx.x * 128;
    const float* xb = (br ? x2 : x1) + (size_t)b * 64 * NPIX;
    const float* kb = br ? kb2 : kb1;
    const float* vb = br ? vb2 : vb1;

    for (int i = tid; i < 2048; i += 256) {
        int c = i >> 5, q4 = i & 31;
        *(float4*)&X[c * 132 + q4 * 4] = *(const float4*)&xb[(size_t)c * NPIX + p0 + q4 * 4];
    }
    __syncthreads();

    // ---- projections: kv=0 -> K (normalized at park), kv=1 -> V ----
#pragma unroll 1
    for (int kv = 0; kv < 2; kv++) {
        const uint32_t* wf = g_QKVfrag + (kv + 1) * 8192 + br * 4096;
        const float* bias = kv ? vb : kb;
        float* park = kv ? Vp : Kp;

        float acc[8][4];
#pragma unroll
        for (int nt = 0; nt < 8; nt++)
#pragma unroll
            for (int k = 0; k < 4; k++) acc[nt][k] = 0.f;

#pragma unroll
        for (int kc = 0; kc < 4; kc++) {
            const uint4* WH = (const uint4*)&wf[(0 * 4 + kc) * 512 + lane * 16];
            const uint4* WL = (const uint4*)&wf[(1 * 4 + kc) * 512 + lane * 16];
            uint4 bh[4], bl[4];
#pragma unroll
            for (int q = 0; q < 4; q++) { bh[q] = __ldg(&WH[q]); bl[q] = __ldg(&WL[q]); }
            int c0 = kc * 16 + tg * 2;
            int r0 = wt * 16 + g;
            float v00 = X[(c0 + 0) * 132 + r0], v01 = X[(c0 + 1) * 132 + r0];
            float v08 = X[(c0 + 8) * 132 + r0], v09 = X[(c0 + 9) * 132 + r0];
            float v10 = X[(c0 + 0) * 132 + r0 + 8], v11 = X[(c0 + 1) * 132 + r0 + 8];
            float v18 = X[(c0 + 8) * 132 + r0 + 8], v19 = X[(c0 + 9) * 132 + r0 + 8];
            uint32_t ah0, ah1, ah2, ah3, al0, al1, al2, al3;
            splitbf(v00, v01, ah0, al0);
            splitbf(v10, v11, ah1, al1);
            splitbf(v08, v09, ah2, al2);
            splitbf(v18, v19, ah3, al3);
#pragma unroll
            for (int nt = 0; nt < 8; nt++) {
                uint32_t b0h = (nt & 1) ? bh[nt >> 1].z : bh[nt >> 1].x;
                uint32_t b1h = (nt & 1) ? bh[nt >> 1].w : bh[nt >> 1].y;
                uint32_t b0l = (nt & 1) ? bl[nt >> 1].z : bl[nt >> 1].x;
                uint32_t b1l = (nt & 1) ? bl[nt >> 1].w : bl[nt >> 1].y;
                mma_bf16(acc[nt], ah0, ah1, ah2, ah3, b0h, b1h);
                mma_bf16(acc[nt], ah0, ah1, ah2, ah3, b0l, b1l);
                mma_bf16(acc[nt], al0, al1, al2, al3, b0h, b1h);
            }
        }

        // add bias
#pragma unroll
        for (int nt = 0; nt < 8; nt++) {
            float b0 = __ldg(&bias[nt * 8 + tg * 2 + 0]);
            float b1 = __ldg(&bias[nt * 8 + tg * 2 + 1]);
            acc[nt][0] += b0; acc[nt][1] += b1;
            acc[nt][2] += b0; acc[nt][3] += b1;
        }

        if (kv == 0) {
#pragma unroll
            for (int h = 0; h < 2; h++) {
                float s = 0.f;
#pragma unroll
                for (int nt = 0; nt < 8; nt++) {
                    float a = acc[nt][h * 2], c = acc[nt][h * 2 + 1];
                    s = fmaf(a, a, s); s = fmaf(c, c, s);
                }
                s += __shfl_xor_sync(0xffffffffu, s, 1);
                s += __shfl_xor_sync(0xffffffffu, s, 2);
                float inv = rsqrtf(s);
                int px = wt * 16 + g + h * 8;
#pragma unroll
                for (int nt = 0; nt < 8; nt++)
#pragma unroll
                    for (int j = 0; j < 2; j++)
                        park[(nt * 8 + tg * 2 + j) * 132 + px] = acc[nt][h * 2 + j] * inv;
            }
        } else {
#pragma unroll
            for (int h = 0; h < 2; h++) {
                int px = wt * 16 + g + h * 8;
#pragma unroll
                for (int nt = 0; nt < 8; nt++)
#pragma unroll
                    for (int j = 0; j < 2; j++)
                        park[(nt * 8 + tg * 2 + j) * 132 + px] = acc[nt][h * 2 + j];
            }
        }
    }
    __syncthreads();

    // ---- stats GEMM: matrix += Kn * V^T  (M=64 kch, N=64 vch, K=128 px) ----
    const int mt4 = wt >> 1;
    const int nh = wt & 1;
    float acc2[4][4];
#pragma unroll
    for (int nt = 0; nt < 4; nt++)
#pragma unroll
        for (int k = 0; k < 4; k++) acc2[nt][k] = 0.f;
    float ksg = 0.f, ksg8 = 0.f;
    float vs[4] = {0.f, 0.f, 0.f, 0.f};

#pragma unroll 2
    for (int kc = 0; kc < 8; kc++) {
        int px0 = kc * 16 + tg * 2;
        int m0 = mt4 * 16 + g;
        float2 k0 = *(const float2*)&Kp[m0 * 132 + px0];
        float2 k8 = *(const float2*)&Kp[m0 * 132 + px0 + 8];
        float2 k10 = *(const float2*)&Kp[(m0 + 8) * 132 + px0];
        float2 k18 = *(const float2*)&Kp[(m0 + 8) * 132 + px0 + 8];
        uint32_t a0h, a0l, a1h, a1l, a2h, a2l, a3h, a3l;
        splitbf(k0.x, k0.y, a0h, a0l);
        splitbf(k10.x, k10.y, a1h, a1l);
        splitbf(k8.x, k8.y, a2h, a2l);
        splitbf(k18.x, k18.y, a3h, a3l);
        if (nh == 0) {
            ksg += k0.x + k0.y + k8.x + k8.y;
            ksg8 += k10.x + k10.y + k18.x + k18.y;
        }
#pragma unroll
        for (int nt = 0; nt < 4; nt++) {
            int n = (nh * 4 + nt) * 8 + g;
            float2 b0 = *(const float2*)&Vp[n * 132 + px0];
            float2 b8 = *(const float2*)&Vp[n * 132 + px0 + 8];
            if (mt4 == 0) vs[nt] += b0.x + b0.y + b8.x + b8.y;
            uint32_t bh0, bl0, bh1, bl1;
            splitbf(b0.x, b0.y, bh0, bl0);
            splitbf(b8.x, b8.y, bh1, bl1);
            mma_bf16(acc2[nt], a0h, a1h, a2h, a3h, bh0, bh1);
            mma_bf16(acc2[nt], a0h, a1h, a2h, a3h, bl0, bl1);
            mma_bf16(acc2[nt], a0l, a1l, a2l, a3l, bh0, bh1);
        }
    }

    float* mat = g_mat + ((size_t)br * NB + b) * 4096;
#pragma unroll
    for (int nt = 0; nt < 4; nt++) {
#pragma unroll
        for (int k = 0; k < 4; k++) {
            int m = mt4 * 16 + g + ((k >= 2) ? 8 : 0);
            int n = (nh * 4 + nt) * 8 + tg * 2 + (k & 1);
            atomicAdd(&mat[m * 64 + n], acc2[nt][k]);
        }
    }
    if (nh == 0) {
        ksg += __shfl_xor_sync(0xffffffffu, ksg, 1);
        ksg += __shfl_xor_sync(0xffffffffu, ksg, 2);
        ksg8 += __shfl_xor_sync(0xffffffffu, ksg8, 1);
        ksg8 += __shfl_xor_sync(0xffffffffu, ksg8, 2);
        if (tg == 0) {
            float* kp = g_ksum + ((size_t)br * NB + b) * 64;
            atomicAdd(&kp[mt4 * 16 + g], ksg);
            atomicAdd(&kp[mt4 * 16 + g + 8], ksg8);
        }
    }
    if (mt4 == 0) {
#pragma unroll
        for (int nt = 0; nt < 4; nt++) {
            float v = vs[nt];
            v += __shfl_xor_sync(0xffffffffu, v, 1);
            v += __shfl_xor_sync(0xffffffffu, v, 2);
            if (tg == 0)
                atomicAdd(&g_vsum[((size_t)br * NB + b) * 64 + (nh * 4 + nt) * 8 + g], v);
        }
    }
}

// -------------------- mid: RM frags, rv, ksumE --------------------
__global__ void __launch_bounds__(256) mid_kernel(const float* __restrict__ rw1,
                                                  const float* __restrict__ rw2)
{
    __shared__ float sMat[4096];
    __shared__ float sRw[4096];
    const int tid = threadIdx.x;
    const int b = blockIdx.x, br = blockIdx.y;
    const float* rw = br ? rw2 : rw1;
    const float* mat = g_mat + ((size_t)br * NB + b) * 4096;
#pragma unroll
    for (int r = 0; r < 16; r++) {
        int i = tid + r * 256;
        sMat[i] = mat[i];
        sRw[i] = rw[i];
    }
    __syncthreads();
    const int ty = tid >> 4, tx = tid & 15;
    float acc[4][4];
#pragma unroll
    for (int i = 0; i < 4; i++)
#pragma unroll
        for (int j = 0; j < 4; j++) acc[i][j] = 0.f;
#pragma unroll 4
    for (int c = 0; c < 64; c++) {
        float a[4], w[4];
#pragma unroll
        for (int i = 0; i < 4; i++) a[i] = sMat[(ty * 4 + i) * 64 + c];
#pragma unroll
        for (int j = 0; j < 4; j++) w[j] = sRw[(tx * 4 + j) * 64 + c];
#pragma unroll
        for (int i = 0; i < 4; i++)
#pragma unroll
            for (int j = 0; j < 4; j++) acc[i][j] += a[i] * w[j];
    }
    if (tid < 64) {
        const float* vsump = g_vsum + ((size_t)br * NB + b) * 64;
        float s = 0.f;
        for (int c = 0; c < 64; c++) s += sRw[tid * 64 + c] * vsump[c];
        g_rv[((size_t)br * NB + b) * 64 + tid] = s;
        g_ksumE[((size_t)br * NB + b) * 64 + tid] =
            g_ksum[((size_t)br * NB + b) * 64 + tid] + 1e-6f;
    }
    __syncthreads();
#pragma unroll
    for (int i = 0; i < 4; i++)
#pragma unroll
        for (int j = 0; j < 4; j++)
            sMat[(tx * 4 + j) * 64 + (ty * 4 + i)] = acc[i][j];
    __syncthreads();
    uint32_t* dst = g_RMfrag + (size_t)(br * 8 + b) * 4096;
    for (int t = tid; t < 4096; t += 256) {
        int half = t >> 11;
        int lane = (t >> 4) & 31;
        int ntj = t & 15;
        int nt = ntj >> 1, j = ntj & 1;
        int kc = (t >> 9) & 3;
        int o = nt * 8 + (lane >> 2);
        int m0 = kc * 16 + (lane & 3) * 2 + j * 8;
        float w0 = sMat[o * 64 + m0];
        float w1 = sMat[o * 64 + m0 + 1];
        dst[t] = packbf_hi_lo(w0, w1, half);
    }
}

// -------------------- pass 2: register-resident double GEMM --------------------
// grid (512, 8, 2), 256 thr = 8 warps, 2 CTAs/SM. Tile: 128 px.
// smem: X fp32 [64][132] = 33792 B, reused for output staging.
#define P2_SMEM 33792

__global__ void __launch_bounds__(256, 2) pass2_kernel(
    const float* __restrict__ x1, const float* __restrict__ x2,
    const float* __restrict__ qb1, const float* __restrict__ rb1,
    const float* __restrict__ qb2, const float* __restrict__ rb2)
{
    extern __shared__ __align__(16) float dsm[];

    const int tid = threadIdx.x;
    const int lane = tid & 31, wt = tid >> 5;
    const int g = lane >> 2, tg = lane & 3;
    const int b = blockIdx.y, br = blockIdx.z;
    const int p0 = blockIdx.x * 128;
    const float* xb = (br ? x2 : x1) + (size_t)b * 64 * NPIX;
    const float* qb = br ? qb2 : qb1;
    const float* rb = br ? rb2 : rb1;
    const float* ksE = g_ksumE + ((size_t)br * NB + b) * 64;
    const float* rvp = g_rv + ((size_t)br * NB + b) * 64;

    for (int i = tid; i < 2048; i += 256) {
        int c = i >> 5, q4 = i & 31;
        *(float4*)&dsm[c * 132 + q4 * 4] = *(const float4*)&xb[(size_t)c * NPIX + p0 + q4 * 4];
    }
    __syncthreads();

    // ---- phase A: Q = Wq*x + qb ----
    float acc[8][4];
#pragma unroll
    for (int nt = 0; nt < 8; nt++)
#pragma unroll
        for (int k = 0; k < 4; k++) acc[nt][k] = 0.f;

#pragma unroll
    for (int kc = 0; kc < 4; kc++) {
        const uint4* WH = (const uint4*)&g_QKVfrag[((br * 2 + 0) * 4 + kc) * 512 + lane * 16];
        const uint4* WL = (const uint4*)&g_QKVfrag[((br * 2 + 1) * 4 + kc) * 512 + lane * 16];
        uint4 bh[4], bl[4];
#pragma unroll
        for (int q = 0; q < 4; q++) { bh[q] = __ldg(&WH[q]); bl[q] = __ldg(&WL[q]); }
        int c0 = kc * 16 + tg * 2;
        int r0 = wt * 16 + g;
        float v00 = dsm[(c0 + 0) * 132 + r0], v01 = dsm[(c0 + 1) * 132 + r0];
        float v08 = dsm[(c0 + 8) * 132 + r0], v09 = dsm[(c0 + 9) * 132 + r0];
        float v10 = dsm[(c0 + 0) * 132 + r0 + 8], v11 = dsm[(c0 + 1) * 132 + r0 + 8];
        float v18 = dsm[(c0 + 8) * 132 + r0 + 8], v19 = dsm[(c0 + 9) * 132 + r0 + 8];
        uint32_t ah0, ah1, ah2, ah3, al0, al1, al2, al3;
        splitbf(v00, v01, ah0, al0);
        splitbf(v10, v11, ah1, al1);
        splitbf(v08, v09, ah2, al2);
        splitbf(v18, v19, ah3, al3);
#pragma unroll
        for (int nt = 0; nt < 8; nt++) {
            uint32_t b0h = (nt & 1) ? bh[nt >> 1].z : bh[nt >> 1].x;
            uint32_t b1h = (nt & 1) ? bh[nt >> 1].w : bh[nt >> 1].y;
            uint32_t b0l = (nt & 1) ? bl[nt >> 1].z : bl[nt >> 1].x;
            uint32_t b1l = (nt & 1) ? bl[nt >> 1].w : bl[nt >> 1].y;
            mma_bf16(acc[nt], ah0, ah1, ah2, ah3, b0h, b1h);
            mma_bf16(acc[nt], ah0, ah1, ah2, ah3, b0l, b1l);
            mma_bf16(acc[nt], al0, al1, al2, al3, b0h, b1h);
        }
    }
    __syncthreads();   // X dead; smem free for staging

    // add qb
    float kse[16];
#pragma unroll
    for (int nt = 0; nt < 8; nt++) {
        float q0 = __ldg(&qb[nt * 8 + tg * 2 + 0]);
        float q1 = __ldg(&qb[nt * 8 + tg * 2 + 1]);
        kse[nt * 2 + 0] = __ldg(&ksE[nt * 8 + tg * 2 + 0]);
        kse[nt * 2 + 1] = __ldg(&ksE[nt * 8 + tg * 2 + 1]);
        acc[nt][0] += q0; acc[nt][1] += q1;
        acc[nt][2] += q0; acc[nt][3] += q1;
    }

    // per-px inv + den via quad shfl
    float invv[2], denn[2];
#pragma unroll
    for (int h = 0; h < 2; h++) {
        float s = 0.f, d = 0.f;
#pragma unroll
        for (int nt = 0; nt < 8; nt++) {
            float a = acc[nt][h * 2], c = acc[nt][h * 2 + 1];
            s = fmaf(a, a, s); s = fmaf(c, c, s);
            d = fmaf(a, kse[nt * 2], d); d = fmaf(c, kse[nt * 2 + 1], d);
        }
        s += __shfl_xor_sync(0xffffffffu, s, 1);
        s += __shfl_xor_sync(0xffffffffu, s, 2);
        d += __shfl_xor_sync(0xffffffffu, d, 1);
        d += __shfl_xor_sync(0xffffffffu, d, 2);
        float inv = rsqrtf(s);
        invv[h] = inv;
        denn[h] = 1.f / (65536.f + inv * d);
    }

    // ---- phase B from registers: out = RM * (Q * inv) ----
    float acc2[8][4];
#pragma unroll
    for (int nt = 0; nt < 8; nt++)
#pragma unroll
        for (int k = 0; k < 4; k++) acc2[nt][k] = 0.f;

    const uint32_t* rmbase = g_RMfrag + (size_t)(br * 8 + b) * 4096;
#pragma unroll
    for (int kc = 0; kc < 4; kc++) {
        const uint4* RH = (const uint4*)&rmbase[(0 * 4 + kc) * 512 + lane * 16];
        const uint4* RL = (const uint4*)&rmbase[(1 * 4 + kc) * 512 + lane * 16];
        uint4 bh[4], bl[4];
#pragma unroll
        for (int q = 0; q < 4; q++) { bh[q] = __ldg(&RH[q]); bl[q] = __ldg(&RL[q]); }
        float i0 = invv[0], i1 = invv[1];
        uint32_t ah0, ah1, ah2, ah3, al0, al1, al2, al3;
        splitbf(acc[2 * kc][0] * i0, acc[2 * kc][1] * i0, ah0, al0);
        splitbf(acc[2 * kc][2] * i1, acc[2 * kc][3] * i1, ah1, al1);
        splitbf(acc[2 * kc + 1][0] * i0, acc[2 * kc + 1][1] * i0, ah2, al2);
        splitbf(acc[2 * kc + 1][2] * i1, acc[2 * kc + 1][3] * i1, ah3, al3);
#pragma unroll
        for (int nt = 0; nt < 8; nt++) {
            uint32_t b0h = (nt & 1) ? bh[nt >> 1].z : bh[nt >> 1].x;
            uint32_t b1h = (nt & 1) ? bh[nt >> 1].w : bh[nt >> 1].y;
            uint32_t b0l = (nt & 1) ? bl[nt >> 1].z : bl[nt >> 1].x;
            uint32_t b1l = (nt & 1) ? bl[nt >> 1].w : bl[nt >> 1].y;
            mma_bf16(acc2[nt], ah0, ah1, ah2, ah3, b0h, b1h);
            mma_bf16(acc2[nt], ah0, ah1, ah2, ah3, b0l, b1l);
            mma_bf16(acc2[nt], al0, al1, al2, al3, b0h, b1h);
        }
    }

    // epilogue -> bf16 hi/lo planes [px][64] in smem
    __nv_bfloat16* sH = (__nv_bfloat16*)dsm;
    __nv_bfloat16* sL = sH + 8192;
#pragma unroll
    for (int h = 0; h < 2; h++) {
        int r = wt * 16 + g + h * 8;
        float den = denn[h];
#pragma unroll
        for (int nt = 0; nt < 8; nt++) {
#pragma unroll
            for (int j = 0; j < 2; j++) {
                int o = nt * 8 + tg * 2 + j;
                float rv = __ldg(&rvp[o]);
                float rbb = __ldg(&rb[o]);
                float v = den * (rv + acc2[nt][h * 2 + j]) + rbb;
                __nv_bfloat16 hh = __float2bfloat16(v);
                __nv_bfloat16 ll = __float2bfloat16(v - __bfloat162float(hh));
                sH[r * 64 + o] = hh;
                sL[r * 64 + o] = ll;
            }
        }
    }
    __syncthreads();

    const char* sbase = (const char*)dsm;
    for (int u = tid; u < 2048; u += 256) {
        int plane = u >> 10;
        int rest = u & 1023;
        int px = rest >> 3, q = rest & 7;
        uint4 val = *(const uint4*)(sbase + plane * 16384 + px * 128 + q * 16);
        __nv_bfloat16* dst = plane ? g_lo : g_hi;
        *(uint4*)&dst[((size_t)(b * NPIX + p0 + px)) * 128 + br * 64 + q * 8] = val;
    }
}

// -------------------- conv: mma.sync bf16-split implicit GEMM --------------------
#define STRIP_STRIDE 272
#define STRIP_BYTES (130 * STRIP_STRIDE)
#define CONV_SMEM (2 * STRIP_BYTES)

__global__ void __launch_bounds__(256, 2) conv_kernel(const float* __restrict__ cbias,
                                                      float* __restrict__ out)
{
    extern __shared__ __align__(16) char dsmc[];
    char* sHi = dsmc;
    char* sLo = dsmc + STRIP_BYTES;
    float* sOut = (float*)dsmc;

    const int tid = threadIdx.x;
    const int lane = tid & 31, wt = tid >> 5;
    const int x0 = blockIdx.x * 128, y = blockIdx.y, b = blockIdx.z;

    float acc[8][4];
#pragma unroll
    for (int nt = 0; nt < 8; nt++)
#pragma unroll
        for (int j = 0; j < 4; j++) acc[nt][j] = 0.f;

    const int g = lane >> 2, tg = lane & 3;
    const uint32_t aOff = (wt * 16 + g) * STRIP_STRIDE + tg * 4;

    for (int ky = 0; ky < 3; ky++) {
        int yy = y + ky - 1;
        bool yok = (yy >= 0 && yy < IMG_H);
        __syncthreads();
        if (yok) {
            size_t rowbase = ((size_t)b * NPIX + (size_t)yy * IMG_W) * 128;
            for (int i = tid; i < 130 * 16; i += 256) {
                int row = i >> 4, ch = i & 15;
                int px = x0 + row - 1;
                uint4 vh = make_uint4(0u, 0u, 0u, 0u);
                uint4 vl = make_uint4(0u, 0u, 0u, 0u);
                if (px >= 0 && px < IMG_W) {
                    size_t gi = rowbase + (size_t)px * 128 + ch * 8;
                    vh = *(const uint4*)&g_hi[gi];
                    vl = *(const uint4*)&g_lo[gi];
                }
                *(uint4*)(sHi + row * STRIP_STRIDE + ch * 16) = vh;
                *(uint4*)(sLo + row * STRIP_STRIDE + ch * 16) = vl;
            }
        }
        __syncthreads();
        if (!yok) continue;

#pragma unroll 1
        for (int kc = 0; kc < 24; kc++) {
            int kx = kc >> 3, cc8 = kc & 7;
            uint32_t r0 = aOff + kx * STRIP_STRIDE + cc8 * 32;
            uint32_t ah0 = *(const uint32_t*)(sHi + r0);
            uint32_t ah1 = *(const uint32_t*)(sHi + r0 + 8 * STRIP_STRIDE);
            uint32_t ah2 = *(const uint32_t*)(sHi + r0 + 16);
            uint32_t ah3 = *(const uint32_t*)(sHi + r0 + 8 * STRIP_STRIDE + 16);
            uint32_t al0 = *(const uint32_t*)(sLo + r0);
            uint32_t al1 = *(const uint32_t*)(sLo + r0 + 8 * STRIP_STRIDE);
            uint32_t al2 = *(const uint32_t*)(sLo + r0 + 16);
            uint32_t al3 = *(const uint32_t*)(sLo + r0 + 8 * STRIP_STRIDE + 16);

            const uint4* bfH = (const uint4*)(g_Bfrag + (((ky * 24 + kc) * 2 + 0) * 32 + lane) * 16);
            const uint4* bfL = (const uint4*)(g_Bfrag + (((ky * 24 + kc) * 2 + 1) * 32 + lane) * 16);
            uint4 bh[4], bl[4];
#pragma unroll
            for (int q = 0; q < 4; q++) { bh[q] = __ldg(&bfH[q]); bl[q] = __ldg(&bfL[q]); }

#pragma unroll
            for (int nt = 0; nt < 8; nt++) {
                uint32_t bh0 = (nt & 1) ? bh[nt >> 1].z : bh[nt >> 1].x;
                uint32_t bh1 = (nt & 1) ? bh[nt >> 1].w : bh[nt >> 1].y;
                uint32_t bl0 = (nt & 1) ? bl[nt >> 1].z : bl[nt >> 1].x;
                uint32_t bl1 = (nt & 1) ? bl[nt >> 1].w : bl[nt >> 1].y;
                mma_bf16(acc[nt], ah0, ah1, ah2, ah3, bh0, bh1);
                mma_bf16(acc[nt], ah0, ah1, ah2, ah3, bl0, bl1);
                mma_bf16(acc[nt], al0, al1, al2, al3, bh0, bh1);
            }
        }
    }

    __syncthreads();
#pragma unroll
    for (int nt = 0; nt < 8; nt++)
#pragma unroll
        for (int h = 0; h < 2; h++)
#pragma unroll
            for (int j = 0; j < 2; j++) {
                int o = nt * 8 + tg * 2 + j;
                int px = wt * 16 + g + h * 8;
                sOut[o * 132 + px] = acc[nt][h * 2 + j];
            }
    __syncthreads();
    for (int i = tid; i < 64 * 32; i += 256) {
        int o = i >> 5, ch = i & 31;
        float4 v = *(const float4*)&sOut[o * 132 + ch * 4];
        float bias = __ldg(&cbias[o]);
        v.x += bias; v.y += bias; v.z += bias; v.w += bias;
        *(float4*)&out[((size_t)(b * 64 + o)) * NPIX + (size_t)y * IMG_W + x0 + ch * 4] = v;
    }
}

// -------------------- launch --------------------
extern "C" void kernel_launch(void* const* d_in, const int* in_sizes, int n_in,
                              void* d_out, int out_size)
{
    (void)in_sizes; (void)n_in; (void)out_size;
    const float* t1  = (const float*)d_in[0];
    const float* t2  = (const float*)d_in[1];
    const float* q1w = (const float*)d_in[2];  const float* q1b = (const float*)d_in[3];
    const float* k1w = (const float*)d_in[4];  const float* k1b = (const float*)d_in[5];
    const float* v1w = (const float*)d_in[6];  const float* v1b = (const float*)d_in[7];
    const float* r1w = (const float*)d_in[8];  const float* r1b = (const float*)d_in[9];
    const float* q2w = (const float*)d_in[10]; const float* q2b = (const float*)d_in[11];
    const float* k2w = (const float*)d_in[12]; const float* k2b = (const float*)d_in[13];
    const float* v2w = (const float*)d_in[14]; const float* v2b = (const float*)d_in[15];
    const float* r2w = (const float*)d_in[16]; const float* r2b = (const float*)d_in[17];
    const float* cw  = (const float*)d_in[18]; const float* cb  = (const float*)d_in[19];

    cudaFuncSetAttribute(pass1_kernel, cudaFuncAttributeMaxDynamicSharedMemorySize, P1_SMEM);
    cudaFuncSetAttribute(pass2_kernel, cudaFuncAttributeMaxDynamicSharedMemorySize, P2_SMEM);
    cudaFuncSetAttribute(conv_kernel, cudaFuncAttributeMaxDynamicSharedMemorySize, CONV_SMEM);

    prep_kernel<<<640, 256>>>(q1w, k1w, v1w, q2w, k2w, v2w, cw);      // launch 0
    dim3 g1(512, 8, 2);
    pass1_kernel<<<g1, 256, P1_SMEM>>>(t1, t2, k1b, v1b, k2b, v2b);   // launch 1
    dim3 gm(8, 2);
    mid_kernel<<<gm, 256>>>(r1w, r2w);                                // launch 2
    pass2_kernel<<<g1, 256, P2_SMEM>>>(t1, t2, q1b, r1b, q2b, r2b);   // launch 3
    dim3 gc(2, 256, 8);
    conv_kernel<<<gc, 256, CONV_SMEM>>>(cb, (float*)d_out);           // launch 4
}